// round 10
// baseline (speedup 1.0000x reference)
#include <cuda_runtime.h>
#include <cuda_bf16.h>
#include <cuda_fp16.h>
#include <cstdint>

#define NB       2
#define SDIM     256
#define FDIM     512
#define NNODES   20000
#define NE_      320000
#define NLAYERS  3
#define BSJ      512

// ---------------- scratch (device globals) ---------------------------------
__device__ __nv_bfloat16 g_nsum_hi[(size_t)NNODES * FDIM];
__device__ __nv_bfloat16 g_nsum_lo[(size_t)NNODES * FDIM];
__device__ __nv_bfloat16 g_x_hi  [(size_t)BSJ * FDIM];
__device__ __nv_bfloat16 g_x_lo  [(size_t)BSJ * FDIM];
__device__ __nv_bfloat16 g_WpT_hi[(size_t)FDIM * FDIM];
__device__ __nv_bfloat16 g_WpT_lo[(size_t)FDIM * FDIM];
__device__ __nv_bfloat16 g_CT_hi [(size_t)BSJ * FDIM];
__device__ __nv_bfloat16 g_CT_lo [(size_t)BSJ * FDIM];
__device__ __nv_bfloat16 g_WT_hi [(size_t)NLAYERS * SDIM * SDIM];
__device__ __nv_bfloat16 g_WT_lo [(size_t)NLAYERS * SDIM * SDIM];
__device__ __nv_bfloat16 g_Ahi   [(size_t)NB * NNODES * SDIM];
__device__ __nv_bfloat16 g_Alo   [(size_t)NB * NNODES * SDIM];
__device__ __half        g_hw_h  [(size_t)NB * NNODES * SDIM];   // hw fp16 hi
__device__ __half        g_hw_l  [(size_t)NB * NNODES * SDIM];   // hw fp16 lo
__device__ float g_dvec[BSJ];
__device__ int   g_deg [NNODES];
__device__ int   g_off [NNODES + 1];
__device__ int   g_cur [NNODES];
__device__ int   g_srcs[NE_];
__device__ float g_wnorm[NE_];
__device__ float g_dinv[NNODES];

__device__ __forceinline__ void bsplit(float v, __nv_bfloat16& h, __nv_bfloat16& l) {
    h = __float2bfloat16(v);
    l = __float2bfloat16(v - __bfloat162float(h));
}
__device__ __forceinline__ void hsplit(float v, __half& h, __half& l) {
    h = __float2half(v);
    l = __float2half(v - __half2float(h));
}
__device__ __forceinline__ float4 h2f4(uint2 u) {
    __half2 a = *(__half2*)&u.x, b = *(__half2*)&u.y;
    float2 fa = __half22float2(a), fb = __half22float2(b);
    return make_float4(fa.x, fa.y, fb.x, fb.y);
}

// ---------------- CSR build ------------------------------------------------
__global__ void k_init_deg() {
    int i = blockIdx.x * blockDim.x + threadIdx.x;
    if (i < NNODES) g_deg[i] = 1;
}
__global__ void k_hist(const int* __restrict__ ei) {
    int e = blockIdx.x * blockDim.x + threadIdx.x;
    if (e < NE_) atomicAdd(&g_deg[ei[NE_ + e]], 1);
}
__global__ void k_scan() {
    __shared__ int ssum[512];
    int tid = threadIdx.x;
    const int CH = (NNODES + 511) / 512;
    int base = tid * CH;
    int s = 0;
    for (int i = 0; i < CH; ++i) {
        int idx = base + i;
        if (idx < NNODES) s += g_deg[idx] - 1;
    }
    ssum[tid] = s;
    __syncthreads();
    for (int off = 1; off < 512; off <<= 1) {
        int v = ssum[tid];
        int u = (tid >= off) ? ssum[tid - off] : 0;
        __syncthreads();
        ssum[tid] = v + u;
        __syncthreads();
    }
    int run = (tid == 0) ? 0 : ssum[tid - 1];
    for (int i = 0; i < CH; ++i) {
        int idx = base + i;
        if (idx < NNODES) {
            g_off[idx] = run;
            g_cur[idx] = run;
            g_dinv[idx] = rsqrtf((float)g_deg[idx]);
            run += g_deg[idx] - 1;
        }
    }
    if (tid == 511) g_off[NNODES] = run;
}
// scatter with precomputed edge norm (dinv ready after k_scan)
__global__ void k_scatter(const int* __restrict__ ei) {
    int e = blockIdx.x * blockDim.x + threadIdx.x;
    if (e < NE_) {
        int s = ei[e];
        int d = ei[NE_ + e];
        int p = atomicAdd(&g_cur[d], 1);
        g_srcs[p] = s;
        g_wnorm[p] = g_dinv[s] * g_dinv[d];
    }
}

// ---------------- nsum -> bf16 hi/lo ---------------------------------------
__global__ void k_nsum(const float* __restrict__ nodes) {
    long i = (long)blockIdx.x * blockDim.x + threadIdx.x;
    const long total = (long)NNODES * FDIM / 4;
    if (i >= total) return;
    const float4* nd = (const float4*)nodes;
    long n = i / (FDIM / 4);
    long f = i % (FDIM / 4);
    float4 a = nd[n * (2 * FDIM / 4) + f];
    float4 b = nd[n * (2 * FDIM / 4) + FDIM / 4 + f];
    float v[4] = {a.x + b.x, a.y + b.y, a.z + b.z, a.w + b.w};
    __nv_bfloat16 h[4], l[4];
#pragma unroll
    for (int q = 0; q < 4; ++q) bsplit(v[q], h[q], l[q]);
    __nv_bfloat162* ph = (__nv_bfloat162*)g_nsum_hi + i * 2;
    __nv_bfloat162* pl = (__nv_bfloat162*)g_nsum_lo + i * 2;
    ph[0] = __nv_bfloat162{h[0], h[1]}; ph[1] = __nv_bfloat162{h[2], h[3]};
    pl[0] = __nv_bfloat162{l[0], l[1]}; pl[1] = __nv_bfloat162{l[2], l[3]};
}

// ---------------- prep: x cvt, WpT, WT transposes, dvec --------------------
#define PREP_S0 1024
#define PREP_S1 1024
#define PREP_S2 768
__global__ void k_prep(const float* __restrict__ x, const float* __restrict__ Wp,
                       const float* __restrict__ gW, const float* __restrict__ bp) {
    int blk = blockIdx.x;
    if (blk < PREP_S0) {
        int idx = blk * 256 + threadIdx.x;
        bsplit(x[idx], g_x_hi[idx], g_x_lo[idx]);
    } else if (blk < PREP_S0 + PREP_S1) {
        int idx = (blk - PREP_S0) * 256 + threadIdx.x;
        int k = idx >> 9, f2 = idx & 511;
        bsplit(Wp[idx], g_WpT_hi[(long)f2 * FDIM + k], g_WpT_lo[(long)f2 * FDIM + k]);
    } else if (blk < PREP_S0 + PREP_S1 + PREP_S2) {
        int idx = (blk - PREP_S0 - PREP_S1) * 256 + threadIdx.x;
        int l = idx / (SDIM * SDIM), r2 = idx % (SDIM * SDIM);
        int i = r2 >> 8, o = r2 & 255;
        long dst = (long)l * SDIM * SDIM + (long)o * SDIM + i;
        bsplit(gW[idx], g_WT_hi[dst], g_WT_lo[dst]);
    } else {
        __shared__ float sh[256];
        int j = blk - (PREP_S0 + PREP_S1 + PREP_S2);
        float s = 0.f;
        for (int k = threadIdx.x; k < FDIM; k += 256)
            s += bp[k] * x[(long)j * FDIM + k];
        sh[threadIdx.x] = s;
        __syncthreads();
        for (int o = 128; o > 0; o >>= 1) {
            if (threadIdx.x < o) sh[threadIdx.x] += sh[threadIdx.x + o];
            __syncthreads();
        }
        if (threadIdx.x == 0) g_dvec[j] = 2.f * sh[0];
    }
}

// ---------------- bf16-split NT GEMM via mma.sync.m16n8k16 -----------------
#define KST   32
#define RSTR  40
#define TILEB (128 * RSTR * 2)
#define MMA_SMEM (8 * TILEB)

__device__ __forceinline__ void cpa16g(void* dst, const void* src, int nbytes) {
    unsigned d = (unsigned)__cvta_generic_to_shared(dst);
    asm volatile("cp.async.cg.shared.global [%0], [%1], 16, %2;\n"
                 :: "r"(d), "l"(src), "r"(nbytes));
}
__device__ __forceinline__ void mma16(float c[4], const unsigned a[4], const unsigned b[2]) {
    asm volatile(
        "mma.sync.aligned.m16n8k16.row.col.f32.bf16.bf16.f32 "
        "{%0,%1,%2,%3}, {%4,%5,%6,%7}, {%8,%9}, {%0,%1,%2,%3};"
        : "+f"(c[0]), "+f"(c[1]), "+f"(c[2]), "+f"(c[3])
        : "r"(a[0]), "r"(a[1]), "r"(a[2]), "r"(a[3]), "r"(b[0]), "r"(b[1]));
}
__device__ __forceinline__ void store_split(__nv_bfloat16* Ohi, __nv_bfloat16* Olo,
                                            long idx, float v0, float v1) {
    __nv_bfloat16 h0, l0, h1, l1;
    bsplit(v0, h0, l0);
    bsplit(v1, h1, l1);
    *(__nv_bfloat162*)(Ohi + idx) = __nv_bfloat162{h0, h1};
    *(__nv_bfloat162*)(Olo + idx) = __nv_bfloat162{l0, l1};
}
__device__ __forceinline__ void store_hsplit(__half* Hh, __half* Hl,
                                             long idx, float v0, float v1) {
    __half h0, l0, h1, l1;
    hsplit(v0, h0, l0);
    hsplit(v1, h1, l1);
    *(__half2*)(Hh + idx) = __half2{h0, h1};
    *(__half2*)(Hl + idx) = __half2{l0, l1};
}

// modes: 0 = fp16 hi/lo hw store; 1 = H0 (dvec add + bf16 split [b,n,s]); 2 = bf16 split row-major
__global__ __launch_bounds__(256) void mma_bf(
    const __nv_bfloat16* __restrict__ Ahi, const __nv_bfloat16* __restrict__ Alo,
    const __nv_bfloat16* __restrict__ Bhi, const __nv_bfloat16* __restrict__ Blo,
    __half* __restrict__ Chh, __half* __restrict__ Chl,
    __nv_bfloat16* __restrict__ Ohi, __nv_bfloat16* __restrict__ Olo,
    const float* __restrict__ dvec,
    int M, int K, int ldc, long aSlab, long cSlab, int mode)
{
    extern __shared__ char smem[];
    int t = threadIdx.x;
    int brow = blockIdx.x * 128, bcol = blockIdx.y * 128;
    long zA = (long)blockIdx.z * aSlab;
    int lane = t & 31, wid = t >> 5;
    int g = lane >> 2, tig = lane & 3;
    int wm = (wid & 1) * 64, wn = (wid >> 1) * 32;

    float acc[4][4][4] = {};
    int nK = K / KST;

    auto load_stage = [&](int st, int k0) {
        char* base = smem + st * 4 * TILEB;
#pragma unroll
        for (int half = 0; half < 2; ++half) {
            int c = t + half * 256;
            int row = c >> 2, q = c & 3;
            long ao = zA + (long)(brow + row) * K + k0 + q * 8;
            long bo = (long)(bcol + row) * K + k0 + q * 8;
            int av = ((brow + row) < M) ? 16 : 0;
            unsigned off = row * (RSTR * 2) + q * 16;
            cpa16g(base + 0 * TILEB + off, Ahi + ao, av);
            cpa16g(base + 1 * TILEB + off, Alo + ao, av);
            cpa16g(base + 2 * TILEB + off, Bhi + bo, 16);
            cpa16g(base + 3 * TILEB + off, Blo + bo, 16);
        }
        asm volatile("cp.async.commit_group;\n");
    };

    load_stage(0, 0);

    for (int it = 0; it < nK; ++it) {
        asm volatile("cp.async.wait_group 0;\n");
        __syncthreads();
        if (it + 1 < nK) load_stage((it + 1) & 1, (it + 1) * KST);
        char* base = smem + (it & 1) * 4 * TILEB;
        const __nv_bfloat16* ah_s = (const __nv_bfloat16*)(base + 0 * TILEB);
        const __nv_bfloat16* al_s = (const __nv_bfloat16*)(base + 1 * TILEB);
        const __nv_bfloat16* bh_s = (const __nv_bfloat16*)(base + 2 * TILEB);
        const __nv_bfloat16* bl_s = (const __nv_bfloat16*)(base + 3 * TILEB);

#pragma unroll
        for (int ks = 0; ks < KST; ks += 16) {
            unsigned ah[4][4], al[4][4], bh[4][2], bl[4][2];
#pragma unroll
            for (int mi = 0; mi < 4; ++mi) {
                int m = wm + mi * 16 + g;
                ah[mi][0] = *(const unsigned*)(ah_s + m * RSTR + ks + 2 * tig);
                ah[mi][1] = *(const unsigned*)(ah_s + (m + 8) * RSTR + ks + 2 * tig);
                ah[mi][2] = *(const unsigned*)(ah_s + m * RSTR + ks + 8 + 2 * tig);
                ah[mi][3] = *(const unsigned*)(ah_s + (m + 8) * RSTR + ks + 8 + 2 * tig);
                al[mi][0] = *(const unsigned*)(al_s + m * RSTR + ks + 2 * tig);
                al[mi][1] = *(const unsigned*)(al_s + (m + 8) * RSTR + ks + 2 * tig);
                al[mi][2] = *(const unsigned*)(al_s + m * RSTR + ks + 8 + 2 * tig);
                al[mi][3] = *(const unsigned*)(al_s + (m + 8) * RSTR + ks + 8 + 2 * tig);
            }
#pragma unroll
            for (int ni = 0; ni < 4; ++ni) {
                int n = wn + ni * 8 + g;
                bh[ni][0] = *(const unsigned*)(bh_s + n * RSTR + ks + 2 * tig);
                bh[ni][1] = *(const unsigned*)(bh_s + n * RSTR + ks + 8 + 2 * tig);
                bl[ni][0] = *(const unsigned*)(bl_s + n * RSTR + ks + 2 * tig);
                bl[ni][1] = *(const unsigned*)(bl_s + n * RSTR + ks + 8 + 2 * tig);
            }
#pragma unroll
            for (int mi = 0; mi < 4; ++mi)
#pragma unroll
                for (int ni = 0; ni < 4; ++ni)
                    mma16(acc[mi][ni], ah[mi], bh[ni]);
#pragma unroll
            for (int mi = 0; mi < 4; ++mi)
#pragma unroll
                for (int ni = 0; ni < 4; ++ni)
                    mma16(acc[mi][ni], ah[mi], bl[ni]);
#pragma unroll
            for (int mi = 0; mi < 4; ++mi)
#pragma unroll
                for (int ni = 0; ni < 4; ++ni)
                    mma16(acc[mi][ni], al[mi], bh[ni]);
        }
        __syncthreads();
    }

    // epilogue
#pragma unroll
    for (int mi = 0; mi < 4; ++mi) {
        int r0 = brow + wm + mi * 16 + g;
#pragma unroll
        for (int ni = 0; ni < 4; ++ni) {
            int c0 = bcol + wn + ni * 8 + 2 * tig;
            if (mode == 0) {
                long zc = (long)blockIdx.z * cSlab;
                if (r0 < M)
                    store_hsplit(Chh, Chl, zc + (long)r0 * ldc + c0,
                                 acc[mi][ni][0], acc[mi][ni][1]);
                if (r0 + 8 < M)
                    store_hsplit(Chh, Chl, zc + (long)(r0 + 8) * ldc + c0,
                                 acc[mi][ni][2], acc[mi][ni][3]);
            } else if (mode == 1) {
                int b = c0 >> 8, s0 = c0 & 255;
                float d0 = dvec[c0], d1 = dvec[c0 + 1];
                long baseO = (long)b * NNODES * SDIM;
                if (r0 < M)
                    store_split(Ohi, Olo, baseO + (long)r0 * SDIM + s0,
                                acc[mi][ni][0] + d0, acc[mi][ni][1] + d1);
                if (r0 + 8 < M)
                    store_split(Ohi, Olo, baseO + (long)(r0 + 8) * SDIM + s0,
                                acc[mi][ni][2] + d0, acc[mi][ni][3] + d1);
            } else {
                if (r0 < M)
                    store_split(Ohi, Olo, (long)r0 * ldc + c0,
                                acc[mi][ni][0], acc[mi][ni][1]);
                if (r0 + 8 < M)
                    store_split(Ohi, Olo, (long)(r0 + 8) * ldc + c0,
                                acc[mi][ni][2], acc[mi][ni][3]);
            }
        }
    }
}

// ---------------- CSR aggregation (pipelined fp16 gather) -------------------
__global__ __launch_bounds__(256) void k_agg(const float* __restrict__ bias,
                                             const float* __restrict__ wbp,
                                             const float* __restrict__ bbp,
                                             float* __restrict__ out, int final_) {
    __shared__ float red[4][2][2];
    int sub = threadIdx.x >> 6;
    int t64 = threadIdx.x & 63;
    int node = blockIdx.x * 4 + sub;
    float dt = g_dinv[node];
    const uint2* Hh = (const uint2*)g_hw_h;
    const uint2* Hl = (const uint2*)g_hw_l;
    const long slab8 = (long)NNODES * 64;
    long n8 = (long)node * 64 + t64;

    // self: hi + lo
    float4 s0h = h2f4(Hh[n8]),         s0l = h2f4(Hl[n8]);
    float4 s1h = h2f4(Hh[slab8 + n8]), s1l = h2f4(Hl[slab8 + n8]);
    float sw = dt * dt;
    float4 acc0 = make_float4((s0h.x + s0l.x) * sw, (s0h.y + s0l.y) * sw,
                              (s0h.z + s0l.z) * sw, (s0h.w + s0l.w) * sw);
    float4 acc1 = make_float4((s1h.x + s1l.x) * sw, (s1h.y + s1l.y) * sw,
                              (s1h.z + s1l.z) * sw, (s1h.w + s1l.w) * sw);

    int e0 = g_off[node], e1 = g_off[node + 1];
    // software-pipelined, 2 edges per step; next pair's (src,w) prefetched
    int sA = 0, sB = 0;
    float wA = 0.f, wB = 0.f;
    if (e0 < e1)     { sA = g_srcs[e0];     wA = g_wnorm[e0]; }
    if (e0 + 1 < e1) { sB = g_srcs[e0 + 1]; wB = g_wnorm[e0 + 1]; }
    for (int e = e0; e < e1; e += 2) {
        int tA = 0, tB = 0;
        float vA = 0.f, vB = 0.f;
        if (e + 2 < e1) { tA = g_srcs[e + 2]; vA = g_wnorm[e + 2]; }
        if (e + 3 < e1) { tB = g_srcs[e + 3]; vB = g_wnorm[e + 3]; }

        {
            long s8 = (long)sA * 64 + t64;
            float4 u0 = h2f4(Hh[s8]);
            float4 u1 = h2f4(Hh[slab8 + s8]);
            acc0.x = fmaf(u0.x, wA, acc0.x); acc0.y = fmaf(u0.y, wA, acc0.y);
            acc0.z = fmaf(u0.z, wA, acc0.z); acc0.w = fmaf(u0.w, wA, acc0.w);
            acc1.x = fmaf(u1.x, wA, acc1.x); acc1.y = fmaf(u1.y, wA, acc1.y);
            acc1.z = fmaf(u1.z, wA, acc1.z); acc1.w = fmaf(u1.w, wA, acc1.w);
        }
        if (e + 1 < e1) {
            long s8 = (long)sB * 64 + t64;
            float4 u0 = h2f4(Hh[s8]);
            float4 u1 = h2f4(Hh[slab8 + s8]);
            acc0.x = fmaf(u0.x, wB, acc0.x); acc0.y = fmaf(u0.y, wB, acc0.y);
            acc0.z = fmaf(u0.z, wB, acc0.z); acc0.w = fmaf(u0.w, wB, acc0.w);
            acc1.x = fmaf(u1.x, wB, acc1.x); acc1.y = fmaf(u1.y, wB, acc1.y);
            acc1.z = fmaf(u1.z, wB, acc1.z); acc1.w = fmaf(u1.w, wB, acc1.w);
        }
        sA = tA; wA = vA; sB = tB; wB = vB;
    }

    float4 bb = ((const float4*)bias)[t64];
    acc0.x += bb.x; acc0.y += bb.y; acc0.z += bb.z; acc0.w += bb.w;
    acc1.x += bb.x; acc1.y += bb.y; acc1.z += bb.z; acc1.w += bb.w;
    acc0.x = acc0.x > 0.f ? acc0.x : 0.01f * acc0.x;
    acc0.y = acc0.y > 0.f ? acc0.y : 0.01f * acc0.y;
    acc0.z = acc0.z > 0.f ? acc0.z : 0.01f * acc0.z;
    acc0.w = acc0.w > 0.f ? acc0.w : 0.01f * acc0.w;
    acc1.x = acc1.x > 0.f ? acc1.x : 0.01f * acc1.x;
    acc1.y = acc1.y > 0.f ? acc1.y : 0.01f * acc1.y;
    acc1.z = acc1.z > 0.f ? acc1.z : 0.01f * acc1.z;
    acc1.w = acc1.w > 0.f ? acc1.w : 0.01f * acc1.w;

    if (!final_) {
        long bE = (long)node * SDIM + t64 * 4;
        __nv_bfloat16 h0, l0, h1, l1, h2, l2, h3, l3;
        bsplit(acc0.x, h0, l0); bsplit(acc0.y, h1, l1);
        bsplit(acc0.z, h2, l2); bsplit(acc0.w, h3, l3);
        ((__nv_bfloat162*)(g_Ahi + bE))[0] = __nv_bfloat162{h0, h1};
        ((__nv_bfloat162*)(g_Ahi + bE))[1] = __nv_bfloat162{h2, h3};
        ((__nv_bfloat162*)(g_Alo + bE))[0] = __nv_bfloat162{l0, l1};
        ((__nv_bfloat162*)(g_Alo + bE))[1] = __nv_bfloat162{l2, l3};
        long bE1 = bE + (long)NNODES * SDIM;
        bsplit(acc1.x, h0, l0); bsplit(acc1.y, h1, l1);
        bsplit(acc1.z, h2, l2); bsplit(acc1.w, h3, l3);
        ((__nv_bfloat162*)(g_Ahi + bE1))[0] = __nv_bfloat162{h0, h1};
        ((__nv_bfloat162*)(g_Ahi + bE1))[1] = __nv_bfloat162{h2, h3};
        ((__nv_bfloat162*)(g_Alo + bE1))[0] = __nv_bfloat162{l0, l1};
        ((__nv_bfloat162*)(g_Alo + bE1))[1] = __nv_bfloat162{l2, l3};
    } else {
        float4 w4 = ((const float4*)wbp)[t64];
        float p0 = acc0.x * w4.x + acc0.y * w4.y + acc0.z * w4.z + acc0.w * w4.w;
        float p1 = acc1.x * w4.x + acc1.y * w4.y + acc1.z * w4.z + acc1.w * w4.w;
#pragma unroll
        for (int o = 16; o; o >>= 1) {
            p0 += __shfl_xor_sync(0xffffffffu, p0, o);
            p1 += __shfl_xor_sync(0xffffffffu, p1, o);
        }
        int w = t64 >> 5;
        if ((t64 & 31) == 0) { red[sub][w][0] = p0; red[sub][w][1] = p1; }
        __syncthreads();
        if (t64 == 0) {
            float b0 = bbp[0];
            out[node] = red[sub][0][0] + red[sub][1][0] + b0;
            out[NNODES + node] = red[sub][0][1] + red[sub][1][1] + b0;
        }
    }
}

// ---------------- launcher -------------------------------------------------
extern "C" void kernel_launch(void* const* d_in, const int* in_sizes, int n_in,
                              void* d_out, int out_size) {
    const float* x     = (const float*)d_in[0];
    const float* nodes = (const float*)d_in[1];
    const int*   ei    = (const int*)  d_in[2];
    const float* Wp    = (const float*)d_in[3];
    const float* bp    = (const float*)d_in[4];
    const float* gW    = (const float*)d_in[5];
    const float* gb    = (const float*)d_in[6];
    const float* wbp   = (const float*)d_in[7];
    const float* bbp   = (const float*)d_in[8];
    float* out = (float*)d_out;

    cudaFuncSetAttribute(mma_bf, cudaFuncAttributeMaxDynamicSharedMemorySize, MMA_SMEM);

    void *pNh, *pNl, *pXh, *pXl, *pWh, *pWl, *pCh, *pCl, *pTh, *pTl, *pAh, *pAl,
         *pHh, *pHl, *pDV;
    cudaGetSymbolAddress(&pNh, g_nsum_hi); cudaGetSymbolAddress(&pNl, g_nsum_lo);
    cudaGetSymbolAddress(&pXh, g_x_hi);    cudaGetSymbolAddress(&pXl, g_x_lo);
    cudaGetSymbolAddress(&pWh, g_WpT_hi);  cudaGetSymbolAddress(&pWl, g_WpT_lo);
    cudaGetSymbolAddress(&pCh, g_CT_hi);   cudaGetSymbolAddress(&pCl, g_CT_lo);
    cudaGetSymbolAddress(&pTh, g_WT_hi);   cudaGetSymbolAddress(&pTl, g_WT_lo);
    cudaGetSymbolAddress(&pAh, g_Ahi);     cudaGetSymbolAddress(&pAl, g_Alo);
    cudaGetSymbolAddress(&pHh, g_hw_h);    cudaGetSymbolAddress(&pHl, g_hw_l);
    cudaGetSymbolAddress(&pDV, g_dvec);

    const int MB = (NNODES + 127) / 128;   // 157
    const long slab = (long)NNODES * SDIM;

    // 0: nsum -> hi/lo
    k_nsum<<<(int)(((long)NNODES * FDIM / 4 + 255) / 256), 256>>>(nodes);
    // 1: x cvt + WpT + WT + dvec
    k_prep<<<PREP_S0 + PREP_S1 + PREP_S2 + BSJ, 256>>>(x, Wp, gW, bp);
    // 2: CT = x @ Wp (mode 2)
    mma_bf<<<dim3(BSJ / 128, FDIM / 128, 1), 256, MMA_SMEM>>>(
        (__nv_bfloat16*)pXh, (__nv_bfloat16*)pXl,
        (__nv_bfloat16*)pWh, (__nv_bfloat16*)pWl,
        nullptr, nullptr, (__nv_bfloat16*)pCh, (__nv_bfloat16*)pCl, nullptr,
        BSJ, FDIM, FDIM, 0, 0, 2);
    // 3: H0 = nsum @ CT^T + dvec (mode 1)
    mma_bf<<<dim3(MB, BSJ / 128, 1), 256, MMA_SMEM>>>(
        (__nv_bfloat16*)pNh, (__nv_bfloat16*)pNl,
        (__nv_bfloat16*)pCh, (__nv_bfloat16*)pCl,
        nullptr, nullptr, (__nv_bfloat16*)pAh, (__nv_bfloat16*)pAl, (float*)pDV,
        NNODES, FDIM, 0, 0, 0, 1);

    // CSR build
    k_init_deg<<<(NNODES + 255) / 256, 256>>>();
    k_hist<<<(NE_ + 255) / 256, 256>>>(ei);
    k_scan<<<1, 512>>>();
    k_scatter<<<(NE_ + 255) / 256, 256>>>(ei);

    // GCN layers (final layer fuses belief projection)
    for (int l = 0; l < NLAYERS; ++l) {
        mma_bf<<<dim3(MB, SDIM / 128, NB), 256, MMA_SMEM>>>(
            (__nv_bfloat16*)pAh, (__nv_bfloat16*)pAl,
            (__nv_bfloat16*)pTh + (long)l * SDIM * SDIM,
            (__nv_bfloat16*)pTl + (long)l * SDIM * SDIM,
            (__half*)pHh, (__half*)pHl, nullptr, nullptr, nullptr,
            NNODES, SDIM, SDIM, slab, slab, 0);
        k_agg<<<NNODES / 4, 256>>>(gb + (long)l * SDIM, wbp, bbp, out,
                                   (l == NLAYERS - 1) ? 1 : 0);
    }
}

// round 11
// speedup vs baseline: 1.5830x; 1.5830x over previous
#include <cuda_runtime.h>
#include <cuda_bf16.h>
#include <cuda_fp16.h>
#include <cstdint>

#define NB       2
#define SDIM     256
#define FDIM     512
#define NNODES   20000
#define NE_      320000
#define NLAYERS  3
#define BSJ      512

// ---------------- scratch (device globals) ---------------------------------
__device__ __nv_bfloat16 g_nsum_hi[(size_t)NNODES * FDIM];
__device__ __nv_bfloat16 g_nsum_lo[(size_t)NNODES * FDIM];
__device__ __nv_bfloat16 g_x_hi  [(size_t)BSJ * FDIM];
__device__ __nv_bfloat16 g_x_lo  [(size_t)BSJ * FDIM];
__device__ __nv_bfloat16 g_WpT_hi[(size_t)FDIM * FDIM];
__device__ __nv_bfloat16 g_WpT_lo[(size_t)FDIM * FDIM];
__device__ __nv_bfloat16 g_CT_hi [(size_t)BSJ * FDIM];
__device__ __nv_bfloat16 g_CT_lo [(size_t)BSJ * FDIM];
__device__ __nv_bfloat16 g_WT_hi [(size_t)NLAYERS * SDIM * SDIM];
__device__ __nv_bfloat16 g_WT_lo [(size_t)NLAYERS * SDIM * SDIM];
__device__ __nv_bfloat16 g_Ahi   [(size_t)NB * NNODES * SDIM];
__device__ __nv_bfloat16 g_Alo   [(size_t)NB * NNODES * SDIM];
__device__ __half        g_hw_h  [(size_t)NB * NNODES * SDIM];   // hw fp16 hi
__device__ __half        g_hw_l  [(size_t)NB * NNODES * SDIM];   // hw fp16 lo
__device__ float g_dvec[BSJ];
__device__ int   g_deg [NNODES];
__device__ int   g_off [NNODES + 1];
__device__ int   g_cur [NNODES];
__device__ int   g_srcs[NE_];
__device__ float g_wnorm[NE_];
__device__ float g_dinv[NNODES];

__device__ __forceinline__ void bsplit(float v, __nv_bfloat16& h, __nv_bfloat16& l) {
    h = __float2bfloat16(v);
    l = __float2bfloat16(v - __bfloat162float(h));
}
__device__ __forceinline__ void hsplit(float v, __half& h, __half& l) {
    h = __float2half(v);
    l = __float2half(v - __half2float(h));
}
__device__ __forceinline__ float4 h2f4(uint2 u) {
    __half2 a = *(__half2*)&u.x, b = *(__half2*)&u.y;
    float2 fa = __half22float2(a), fb = __half22float2(b);
    return make_float4(fa.x, fa.y, fb.x, fb.y);
}

// ---------------- CSR build ------------------------------------------------
__global__ void k_init_deg() {
    int i = blockIdx.x * blockDim.x + threadIdx.x;
    if (i < NNODES) g_deg[i] = 1;
}
__global__ void k_hist(const int* __restrict__ ei) {
    int e = blockIdx.x * blockDim.x + threadIdx.x;
    if (e < NE_) atomicAdd(&g_deg[ei[NE_ + e]], 1);
}
__global__ void k_scan() {
    __shared__ int ssum[512];
    int tid = threadIdx.x;
    const int CH = (NNODES + 511) / 512;
    int base = tid * CH;
    int s = 0;
    for (int i = 0; i < CH; ++i) {
        int idx = base + i;
        if (idx < NNODES) s += g_deg[idx] - 1;
    }
    ssum[tid] = s;
    __syncthreads();
    for (int off = 1; off < 512; off <<= 1) {
        int v = ssum[tid];
        int u = (tid >= off) ? ssum[tid - off] : 0;
        __syncthreads();
        ssum[tid] = v + u;
        __syncthreads();
    }
    int run = (tid == 0) ? 0 : ssum[tid - 1];
    for (int i = 0; i < CH; ++i) {
        int idx = base + i;
        if (idx < NNODES) {
            g_off[idx] = run;
            g_cur[idx] = run;
            g_dinv[idx] = rsqrtf((float)g_deg[idx]);
            run += g_deg[idx] - 1;
        }
    }
    if (tid == 511) g_off[NNODES] = run;
}
// scatter with precomputed edge norm (dinv ready after k_scan)
__global__ void k_scatter(const int* __restrict__ ei) {
    int e = blockIdx.x * blockDim.x + threadIdx.x;
    if (e < NE_) {
        int s = ei[e];
        int d = ei[NE_ + e];
        int p = atomicAdd(&g_cur[d], 1);
        g_srcs[p] = s;
        g_wnorm[p] = g_dinv[s] * g_dinv[d];
    }
}

// ---------------- nsum -> bf16 hi/lo ---------------------------------------
__global__ void k_nsum(const float* __restrict__ nodes) {
    long i = (long)blockIdx.x * blockDim.x + threadIdx.x;
    const long total = (long)NNODES * FDIM / 4;
    if (i >= total) return;
    const float4* nd = (const float4*)nodes;
    long n = i / (FDIM / 4);
    long f = i % (FDIM / 4);
    float4 a = nd[n * (2 * FDIM / 4) + f];
    float4 b = nd[n * (2 * FDIM / 4) + FDIM / 4 + f];
    float v[4] = {a.x + b.x, a.y + b.y, a.z + b.z, a.w + b.w};
    __nv_bfloat16 h[4], l[4];
#pragma unroll
    for (int q = 0; q < 4; ++q) bsplit(v[q], h[q], l[q]);
    __nv_bfloat162* ph = (__nv_bfloat162*)g_nsum_hi + i * 2;
    __nv_bfloat162* pl = (__nv_bfloat162*)g_nsum_lo + i * 2;
    ph[0] = __nv_bfloat162{h[0], h[1]}; ph[1] = __nv_bfloat162{h[2], h[3]};
    pl[0] = __nv_bfloat162{l[0], l[1]}; pl[1] = __nv_bfloat162{l[2], l[3]};
}

// ---------------- prep: x cvt, WpT, WT transposes, dvec --------------------
#define PREP_S0 1024
#define PREP_S1 1024
#define PREP_S2 768
__global__ void k_prep(const float* __restrict__ x, const float* __restrict__ Wp,
                       const float* __restrict__ gW, const float* __restrict__ bp) {
    int blk = blockIdx.x;
    if (blk < PREP_S0) {
        int idx = blk * 256 + threadIdx.x;
        bsplit(x[idx], g_x_hi[idx], g_x_lo[idx]);
    } else if (blk < PREP_S0 + PREP_S1) {
        int idx = (blk - PREP_S0) * 256 + threadIdx.x;
        int k = idx >> 9, f2 = idx & 511;
        bsplit(Wp[idx], g_WpT_hi[(long)f2 * FDIM + k], g_WpT_lo[(long)f2 * FDIM + k]);
    } else if (blk < PREP_S0 + PREP_S1 + PREP_S2) {
        int idx = (blk - PREP_S0 - PREP_S1) * 256 + threadIdx.x;
        int l = idx / (SDIM * SDIM), r2 = idx % (SDIM * SDIM);
        int i = r2 >> 8, o = r2 & 255;
        long dst = (long)l * SDIM * SDIM + (long)o * SDIM + i;
        bsplit(gW[idx], g_WT_hi[dst], g_WT_lo[dst]);
    } else {
        __shared__ float sh[256];
        int j = blk - (PREP_S0 + PREP_S1 + PREP_S2);
        float s = 0.f;
        for (int k = threadIdx.x; k < FDIM; k += 256)
            s += bp[k] * x[(long)j * FDIM + k];
        sh[threadIdx.x] = s;
        __syncthreads();
        for (int o = 128; o > 0; o >>= 1) {
            if (threadIdx.x < o) sh[threadIdx.x] += sh[threadIdx.x + o];
            __syncthreads();
        }
        if (threadIdx.x == 0) g_dvec[j] = 2.f * sh[0];
    }
}

// ---------------- bf16-split NT GEMM via mma.sync.m16n8k16 -----------------
#define KST   32
#define RSTR  40
#define TILEB (128 * RSTR * 2)
#define MMA_SMEM (8 * TILEB)

__device__ __forceinline__ void cpa16g(void* dst, const void* src, int nbytes) {
    unsigned d = (unsigned)__cvta_generic_to_shared(dst);
    asm volatile("cp.async.cg.shared.global [%0], [%1], 16, %2;\n"
                 :: "r"(d), "l"(src), "r"(nbytes));
}
__device__ __forceinline__ void mma16(float c[4], const unsigned a[4], const unsigned b[2]) {
    asm volatile(
        "mma.sync.aligned.m16n8k16.row.col.f32.bf16.bf16.f32 "
        "{%0,%1,%2,%3}, {%4,%5,%6,%7}, {%8,%9}, {%0,%1,%2,%3};"
        : "+f"(c[0]), "+f"(c[1]), "+f"(c[2]), "+f"(c[3])
        : "r"(a[0]), "r"(a[1]), "r"(a[2]), "r"(a[3]), "r"(b[0]), "r"(b[1]));
}
__device__ __forceinline__ void store_split(__nv_bfloat16* Ohi, __nv_bfloat16* Olo,
                                            long idx, float v0, float v1) {
    __nv_bfloat16 h0, l0, h1, l1;
    bsplit(v0, h0, l0);
    bsplit(v1, h1, l1);
    *(__nv_bfloat162*)(Ohi + idx) = __nv_bfloat162{h0, h1};
    *(__nv_bfloat162*)(Olo + idx) = __nv_bfloat162{l0, l1};
}
__device__ __forceinline__ void store_hsplit(__half* Hh, __half* Hl,
                                             long idx, float v0, float v1) {
    __half h0, l0, h1, l1;
    hsplit(v0, h0, l0);
    hsplit(v1, h1, l1);
    *(__half2*)(Hh + idx) = __half2{h0, h1};
    *(__half2*)(Hl + idx) = __half2{l0, l1};
}

// modes: 0 = fp16 hi/lo hw store; 1 = H0 (dvec add + bf16 split [b,n,s]); 2 = bf16 split row-major
__global__ __launch_bounds__(256) void mma_bf(
    const __nv_bfloat16* __restrict__ Ahi, const __nv_bfloat16* __restrict__ Alo,
    const __nv_bfloat16* __restrict__ Bhi, const __nv_bfloat16* __restrict__ Blo,
    __half* __restrict__ Chh, __half* __restrict__ Chl,
    __nv_bfloat16* __restrict__ Ohi, __nv_bfloat16* __restrict__ Olo,
    const float* __restrict__ dvec,
    int M, int K, int ldc, long aSlab, long cSlab, int mode)
{
    extern __shared__ char smem[];
    int t = threadIdx.x;
    int brow = blockIdx.x * 128, bcol = blockIdx.y * 128;
    long zA = (long)blockIdx.z * aSlab;
    int lane = t & 31, wid = t >> 5;
    int g = lane >> 2, tig = lane & 3;
    int wm = (wid & 1) * 64, wn = (wid >> 1) * 32;

    float acc[4][4][4] = {};
    int nK = K / KST;

    auto load_stage = [&](int st, int k0) {
        char* base = smem + st * 4 * TILEB;
#pragma unroll
        for (int half = 0; half < 2; ++half) {
            int c = t + half * 256;
            int row = c >> 2, q = c & 3;
            long ao = zA + (long)(brow + row) * K + k0 + q * 8;
            long bo = (long)(bcol + row) * K + k0 + q * 8;
            int av = ((brow + row) < M) ? 16 : 0;
            unsigned off = row * (RSTR * 2) + q * 16;
            cpa16g(base + 0 * TILEB + off, Ahi + ao, av);
            cpa16g(base + 1 * TILEB + off, Alo + ao, av);
            cpa16g(base + 2 * TILEB + off, Bhi + bo, 16);
            cpa16g(base + 3 * TILEB + off, Blo + bo, 16);
        }
        asm volatile("cp.async.commit_group;\n");
    };

    load_stage(0, 0);

    for (int it = 0; it < nK; ++it) {
        asm volatile("cp.async.wait_group 0;\n");
        __syncthreads();
        if (it + 1 < nK) load_stage((it + 1) & 1, (it + 1) * KST);
        char* base = smem + (it & 1) * 4 * TILEB;
        const __nv_bfloat16* ah_s = (const __nv_bfloat16*)(base + 0 * TILEB);
        const __nv_bfloat16* al_s = (const __nv_bfloat16*)(base + 1 * TILEB);
        const __nv_bfloat16* bh_s = (const __nv_bfloat16*)(base + 2 * TILEB);
        const __nv_bfloat16* bl_s = (const __nv_bfloat16*)(base + 3 * TILEB);

#pragma unroll
        for (int ks = 0; ks < KST; ks += 16) {
            unsigned ah[4][4], al[4][4], bh[4][2], bl[4][2];
#pragma unroll
            for (int mi = 0; mi < 4; ++mi) {
                int m = wm + mi * 16 + g;
                ah[mi][0] = *(const unsigned*)(ah_s + m * RSTR + ks + 2 * tig);
                ah[mi][1] = *(const unsigned*)(ah_s + (m + 8) * RSTR + ks + 2 * tig);
                ah[mi][2] = *(const unsigned*)(ah_s + m * RSTR + ks + 8 + 2 * tig);
                ah[mi][3] = *(const unsigned*)(ah_s + (m + 8) * RSTR + ks + 8 + 2 * tig);
                al[mi][0] = *(const unsigned*)(al_s + m * RSTR + ks + 2 * tig);
                al[mi][1] = *(const unsigned*)(al_s + (m + 8) * RSTR + ks + 2 * tig);
                al[mi][2] = *(const unsigned*)(al_s + m * RSTR + ks + 8 + 2 * tig);
                al[mi][3] = *(const unsigned*)(al_s + (m + 8) * RSTR + ks + 8 + 2 * tig);
            }
#pragma unroll
            for (int ni = 0; ni < 4; ++ni) {
                int n = wn + ni * 8 + g;
                bh[ni][0] = *(const unsigned*)(bh_s + n * RSTR + ks + 2 * tig);
                bh[ni][1] = *(const unsigned*)(bh_s + n * RSTR + ks + 8 + 2 * tig);
                bl[ni][0] = *(const unsigned*)(bl_s + n * RSTR + ks + 2 * tig);
                bl[ni][1] = *(const unsigned*)(bl_s + n * RSTR + ks + 8 + 2 * tig);
            }
#pragma unroll
            for (int mi = 0; mi < 4; ++mi)
#pragma unroll
                for (int ni = 0; ni < 4; ++ni)
                    mma16(acc[mi][ni], ah[mi], bh[ni]);
#pragma unroll
            for (int mi = 0; mi < 4; ++mi)
#pragma unroll
                for (int ni = 0; ni < 4; ++ni)
                    mma16(acc[mi][ni], ah[mi], bl[ni]);
#pragma unroll
            for (int mi = 0; mi < 4; ++mi)
#pragma unroll
                for (int ni = 0; ni < 4; ++ni)
                    mma16(acc[mi][ni], al[mi], bh[ni]);
        }
        __syncthreads();
    }

    // epilogue
#pragma unroll
    for (int mi = 0; mi < 4; ++mi) {
        int r0 = brow + wm + mi * 16 + g;
#pragma unroll
        for (int ni = 0; ni < 4; ++ni) {
            int c0 = bcol + wn + ni * 8 + 2 * tig;
            if (mode == 0) {
                long zc = (long)blockIdx.z * cSlab;
                if (r0 < M)
                    store_hsplit(Chh, Chl, zc + (long)r0 * ldc + c0,
                                 acc[mi][ni][0], acc[mi][ni][1]);
                if (r0 + 8 < M)
                    store_hsplit(Chh, Chl, zc + (long)(r0 + 8) * ldc + c0,
                                 acc[mi][ni][2], acc[mi][ni][3]);
            } else if (mode == 1) {
                int b = c0 >> 8, s0 = c0 & 255;
                float d0 = dvec[c0], d1 = dvec[c0 + 1];
                long baseO = (long)b * NNODES * SDIM;
                if (r0 < M)
                    store_split(Ohi, Olo, baseO + (long)r0 * SDIM + s0,
                                acc[mi][ni][0] + d0, acc[mi][ni][1] + d1);
                if (r0 + 8 < M)
                    store_split(Ohi, Olo, baseO + (long)(r0 + 8) * SDIM + s0,
                                acc[mi][ni][2] + d0, acc[mi][ni][3] + d1);
            } else {
                if (r0 < M)
                    store_split(Ohi, Olo, (long)r0 * ldc + c0,
                                acc[mi][ni][0], acc[mi][ni][1]);
                if (r0 + 8 < M)
                    store_split(Ohi, Olo, (long)(r0 + 8) * ldc + c0,
                                acc[mi][ni][2], acc[mi][ni][3]);
            }
        }
    }
}

// ---------------- CSR aggregation (fp16 gather, simple loop) ----------------
__global__ __launch_bounds__(256) void k_agg(const float* __restrict__ bias,
                                             const float* __restrict__ wbp,
                                             const float* __restrict__ bbp,
                                             float* __restrict__ out, int final_) {
    __shared__ float red[4][2][2];
    int sub = threadIdx.x >> 6;
    int t64 = threadIdx.x & 63;
    int node = blockIdx.x * 4 + sub;
    float dt = g_dinv[node];
    const uint2* Hh = (const uint2*)g_hw_h;
    const uint2* Hl = (const uint2*)g_hw_l;
    const long slab8 = (long)NNODES * 64;
    long n8 = (long)node * 64 + t64;

    // self: hi + lo (full precision)
    float4 s0h = h2f4(Hh[n8]),         s0l = h2f4(Hl[n8]);
    float4 s1h = h2f4(Hh[slab8 + n8]), s1l = h2f4(Hl[slab8 + n8]);
    float sw = dt * dt;
    float4 acc0 = make_float4((s0h.x + s0l.x) * sw, (s0h.y + s0l.y) * sw,
                              (s0h.z + s0l.z) * sw, (s0h.w + s0l.w) * sw);
    float4 acc1 = make_float4((s1h.x + s1l.x) * sw, (s1h.y + s1l.y) * sw,
                              (s1h.z + s1l.z) * sw, (s1h.w + s1l.w) * sw);
    int e0 = g_off[node], e1 = g_off[node + 1];
    for (int e = e0; e < e1; ++e) {
        int src = g_srcs[e];
        float w = g_wnorm[e];
        long s8 = (long)src * 64 + t64;
        float4 u0 = h2f4(Hh[s8]);
        float4 u1 = h2f4(Hh[slab8 + s8]);
        acc0.x = fmaf(u0.x, w, acc0.x); acc0.y = fmaf(u0.y, w, acc0.y);
        acc0.z = fmaf(u0.z, w, acc0.z); acc0.w = fmaf(u0.w, w, acc0.w);
        acc1.x = fmaf(u1.x, w, acc1.x); acc1.y = fmaf(u1.y, w, acc1.y);
        acc1.z = fmaf(u1.z, w, acc1.z); acc1.w = fmaf(u1.w, w, acc1.w);
    }
    float4 bb = ((const float4*)bias)[t64];
    acc0.x += bb.x; acc0.y += bb.y; acc0.z += bb.z; acc0.w += bb.w;
    acc1.x += bb.x; acc1.y += bb.y; acc1.z += bb.z; acc1.w += bb.w;
    acc0.x = acc0.x > 0.f ? acc0.x : 0.01f * acc0.x;
    acc0.y = acc0.y > 0.f ? acc0.y : 0.01f * acc0.y;
    acc0.z = acc0.z > 0.f ? acc0.z : 0.01f * acc0.z;
    acc0.w = acc0.w > 0.f ? acc0.w : 0.01f * acc0.w;
    acc1.x = acc1.x > 0.f ? acc1.x : 0.01f * acc1.x;
    acc1.y = acc1.y > 0.f ? acc1.y : 0.01f * acc1.y;
    acc1.z = acc1.z > 0.f ? acc1.z : 0.01f * acc1.z;
    acc1.w = acc1.w > 0.f ? acc1.w : 0.01f * acc1.w;

    if (!final_) {
        long bE = (long)node * SDIM + t64 * 4;
        __nv_bfloat16 h0, l0, h1, l1, h2, l2, h3, l3;
        bsplit(acc0.x, h0, l0); bsplit(acc0.y, h1, l1);
        bsplit(acc0.z, h2, l2); bsplit(acc0.w, h3, l3);
        ((__nv_bfloat162*)(g_Ahi + bE))[0] = __nv_bfloat162{h0, h1};
        ((__nv_bfloat162*)(g_Ahi + bE))[1] = __nv_bfloat162{h2, h3};
        ((__nv_bfloat162*)(g_Alo + bE))[0] = __nv_bfloat162{l0, l1};
        ((__nv_bfloat162*)(g_Alo + bE))[1] = __nv_bfloat162{l2, l3};
        long bE1 = bE + (long)NNODES * SDIM;
        bsplit(acc1.x, h0, l0); bsplit(acc1.y, h1, l1);
        bsplit(acc1.z, h2, l2); bsplit(acc1.w, h3, l3);
        ((__nv_bfloat162*)(g_Ahi + bE1))[0] = __nv_bfloat162{h0, h1};
        ((__nv_bfloat162*)(g_Ahi + bE1))[1] = __nv_bfloat162{h2, h3};
        ((__nv_bfloat162*)(g_Alo + bE1))[0] = __nv_bfloat162{l0, l1};
        ((__nv_bfloat162*)(g_Alo + bE1))[1] = __nv_bfloat162{l2, l3};
    } else {
        float4 w4 = ((const float4*)wbp)[t64];
        float p0 = acc0.x * w4.x + acc0.y * w4.y + acc0.z * w4.z + acc0.w * w4.w;
        float p1 = acc1.x * w4.x + acc1.y * w4.y + acc1.z * w4.z + acc1.w * w4.w;
#pragma unroll
        for (int o = 16; o; o >>= 1) {
            p0 += __shfl_xor_sync(0xffffffffu, p0, o);
            p1 += __shfl_xor_sync(0xffffffffu, p1, o);
        }
        int w = t64 >> 5;
        if ((t64 & 31) == 0) { red[sub][w][0] = p0; red[sub][w][1] = p1; }
        __syncthreads();
        if (t64 == 0) {
            float b0 = bbp[0];
            out[node] = red[sub][0][0] + red[sub][1][0] + b0;
            out[NNODES + node] = red[sub][0][1] + red[sub][1][1] + b0;
        }
    }
}

// ---------------- launcher -------------------------------------------------
extern "C" void kernel_launch(void* const* d_in, const int* in_sizes, int n_in,
                              void* d_out, int out_size) {
    const float* x     = (const float*)d_in[0];
    const float* nodes = (const float*)d_in[1];
    const int*   ei    = (const int*)  d_in[2];
    const float* Wp    = (const float*)d_in[3];
    const float* bp    = (const float*)d_in[4];
    const float* gW    = (const float*)d_in[5];
    const float* gb    = (const float*)d_in[6];
    const float* wbp   = (const float*)d_in[7];
    const float* bbp   = (const float*)d_in[8];
    float* out = (float*)d_out;

    cudaFuncSetAttribute(mma_bf, cudaFuncAttributeMaxDynamicSharedMemorySize, MMA_SMEM);

    void *pNh, *pNl, *pXh, *pXl, *pWh, *pWl, *pCh, *pCl, *pTh, *pTl, *pAh, *pAl,
         *pHh, *pHl, *pDV;
    cudaGetSymbolAddress(&pNh, g_nsum_hi); cudaGetSymbolAddress(&pNl, g_nsum_lo);
    cudaGetSymbolAddress(&pXh, g_x_hi);    cudaGetSymbolAddress(&pXl, g_x_lo);
    cudaGetSymbolAddress(&pWh, g_WpT_hi);  cudaGetSymbolAddress(&pWl, g_WpT_lo);
    cudaGetSymbolAddress(&pCh, g_CT_hi);   cudaGetSymbolAddress(&pCl, g_CT_lo);
    cudaGetSymbolAddress(&pTh, g_WT_hi);   cudaGetSymbolAddress(&pTl, g_WT_lo);
    cudaGetSymbolAddress(&pAh, g_Ahi);     cudaGetSymbolAddress(&pAl, g_Alo);
    cudaGetSymbolAddress(&pHh, g_hw_h);    cudaGetSymbolAddress(&pHl, g_hw_l);
    cudaGetSymbolAddress(&pDV, g_dvec);

    const int MB = (NNODES + 127) / 128;   // 157
    const long slab = (long)NNODES * SDIM;

    // 0: nsum -> hi/lo
    k_nsum<<<(int)(((long)NNODES * FDIM / 4 + 255) / 256), 256>>>(nodes);
    // 1: x cvt + WpT + WT + dvec
    k_prep<<<PREP_S0 + PREP_S1 + PREP_S2 + BSJ, 256>>>(x, Wp, gW, bp);
    // 2: CT = x @ Wp (mode 2)
    mma_bf<<<dim3(BSJ / 128, FDIM / 128, 1), 256, MMA_SMEM>>>(
        (__nv_bfloat16*)pXh, (__nv_bfloat16*)pXl,
        (__nv_bfloat16*)pWh, (__nv_bfloat16*)pWl,
        nullptr, nullptr, (__nv_bfloat16*)pCh, (__nv_bfloat16*)pCl, nullptr,
        BSJ, FDIM, FDIM, 0, 0, 2);
    // 3: H0 = nsum @ CT^T + dvec (mode 1)
    mma_bf<<<dim3(MB, BSJ / 128, 1), 256, MMA_SMEM>>>(
        (__nv_bfloat16*)pNh, (__nv_bfloat16*)pNl,
        (__nv_bfloat16*)pCh, (__nv_bfloat16*)pCl,
        nullptr, nullptr, (__nv_bfloat16*)pAh, (__nv_bfloat16*)pAl, (float*)pDV,
        NNODES, FDIM, 0, 0, 0, 1);

    // CSR build
    k_init_deg<<<(NNODES + 255) / 256, 256>>>();
    k_hist<<<(NE_ + 255) / 256, 256>>>(ei);
    k_scan<<<1, 512>>>();
    k_scatter<<<(NE_ + 255) / 256, 256>>>(ei);

    // GCN layers (final layer fuses belief projection)
    for (int l = 0; l < NLAYERS; ++l) {
        mma_bf<<<dim3(MB, SDIM / 128, NB), 256, MMA_SMEM>>>(
            (__nv_bfloat16*)pAh, (__nv_bfloat16*)pAl,
            (__nv_bfloat16*)pTh + (long)l * SDIM * SDIM,
            (__nv_bfloat16*)pTl + (long)l * SDIM * SDIM,
            (__half*)pHh, (__half*)pHl, nullptr, nullptr, nullptr,
            NNODES, SDIM, SDIM, slab, slab, 0);
        k_agg<<<NNODES / 4, 256>>>(gb + (long)l * SDIM, wbp, bbp, out,
                                   (l == NLAYERS - 1) ? 1 : 0);
    }
}

// round 12
// speedup vs baseline: 1.6032x; 1.0128x over previous
#include <cuda_runtime.h>
#include <cuda_bf16.h>
#include <cuda_fp16.h>
#include <cstdint>

#define NB       2
#define SDIM     256
#define FDIM     512
#define NNODES   20000
#define NE_      320000
#define NLAYERS  3
#define BSJ      512

// ---------------- scratch (device globals) ---------------------------------
__device__ __nv_bfloat16 g_nsum_hi[(size_t)NNODES * FDIM];
__device__ __nv_bfloat16 g_nsum_lo[(size_t)NNODES * FDIM];
__device__ __nv_bfloat16 g_x_hi  [(size_t)BSJ * FDIM];
__device__ __nv_bfloat16 g_x_lo  [(size_t)BSJ * FDIM];
__device__ __nv_bfloat16 g_WpT_hi[(size_t)FDIM * FDIM];
__device__ __nv_bfloat16 g_WpT_lo[(size_t)FDIM * FDIM];
__device__ __nv_bfloat16 g_CT_hi [(size_t)BSJ * FDIM];
__device__ __nv_bfloat16 g_CT_lo [(size_t)BSJ * FDIM];
__device__ __nv_bfloat16 g_WT_hi [(size_t)NLAYERS * SDIM * SDIM];
__device__ __nv_bfloat16 g_WT_lo [(size_t)NLAYERS * SDIM * SDIM];
__device__ __nv_bfloat16 g_Ahi   [(size_t)NB * NNODES * SDIM];
__device__ __nv_bfloat16 g_Alo   [(size_t)NB * NNODES * SDIM];
__device__ __half        g_hw_h  [(size_t)NB * NNODES * SDIM];   // hw fp16 hi
__device__ __half        g_hw_l  [(size_t)NB * NNODES * SDIM];   // hw fp16 lo
__device__ float g_dvec[BSJ];
__device__ int   g_deg [NNODES];
__device__ int   g_off [NNODES + 1];
__device__ int   g_cur [NNODES];
__device__ int   g_srcs[NE_];
__device__ float g_wnorm[NE_];
__device__ float g_dinv[NNODES];

__device__ __forceinline__ void bsplit(float v, __nv_bfloat16& h, __nv_bfloat16& l) {
    h = __float2bfloat16(v);
    l = __float2bfloat16(v - __bfloat162float(h));
}
__device__ __forceinline__ void hsplit(float v, __half& h, __half& l) {
    h = __float2half(v);
    l = __float2half(v - __half2float(h));
}
__device__ __forceinline__ float4 h2f4(uint2 u) {
    __half2 a = *(__half2*)&u.x, b = *(__half2*)&u.y;
    float2 fa = __half22float2(a), fb = __half22float2(b);
    return make_float4(fa.x, fa.y, fb.x, fb.y);
}

// ---------------- CSR build ------------------------------------------------
__global__ void k_init_deg() {
    int i = blockIdx.x * blockDim.x + threadIdx.x;
    if (i < NNODES) g_deg[i] = 1;
}
__global__ void k_hist(const int* __restrict__ ei) {
    int e = blockIdx.x * blockDim.x + threadIdx.x;
    if (e < NE_) atomicAdd(&g_deg[ei[NE_ + e]], 1);
}
__global__ void k_scan() {
    __shared__ int ssum[512];
    int tid = threadIdx.x;
    const int CH = (NNODES + 511) / 512;
    int base = tid * CH;
    int s = 0;
    for (int i = 0; i < CH; ++i) {
        int idx = base + i;
        if (idx < NNODES) s += g_deg[idx] - 1;
    }
    ssum[tid] = s;
    __syncthreads();
    for (int off = 1; off < 512; off <<= 1) {
        int v = ssum[tid];
        int u = (tid >= off) ? ssum[tid - off] : 0;
        __syncthreads();
        ssum[tid] = v + u;
        __syncthreads();
    }
    int run = (tid == 0) ? 0 : ssum[tid - 1];
    for (int i = 0; i < CH; ++i) {
        int idx = base + i;
        if (idx < NNODES) {
            g_off[idx] = run;
            g_cur[idx] = run;
            g_dinv[idx] = rsqrtf((float)g_deg[idx]);
            run += g_deg[idx] - 1;
        }
    }
    if (tid == 511) g_off[NNODES] = run;
}
__global__ void k_scatter(const int* __restrict__ ei) {
    int e = blockIdx.x * blockDim.x + threadIdx.x;
    if (e < NE_) {
        int s = ei[e];
        int d = ei[NE_ + e];
        int p = atomicAdd(&g_cur[d], 1);
        g_srcs[p] = s;
        g_wnorm[p] = g_dinv[s] * g_dinv[d];
    }
}

// ---------------- nsum -> bf16 hi/lo ---------------------------------------
__global__ void k_nsum(const float* __restrict__ nodes) {
    long i = (long)blockIdx.x * blockDim.x + threadIdx.x;
    const long total = (long)NNODES * FDIM / 4;
    if (i >= total) return;
    const float4* nd = (const float4*)nodes;
    long n = i / (FDIM / 4);
    long f = i % (FDIM / 4);
    float4 a = nd[n * (2 * FDIM / 4) + f];
    float4 b = nd[n * (2 * FDIM / 4) + FDIM / 4 + f];
    float v[4] = {a.x + b.x, a.y + b.y, a.z + b.z, a.w + b.w};
    __nv_bfloat16 h[4], l[4];
#pragma unroll
    for (int q = 0; q < 4; ++q) bsplit(v[q], h[q], l[q]);
    __nv_bfloat162* ph = (__nv_bfloat162*)g_nsum_hi + i * 2;
    __nv_bfloat162* pl = (__nv_bfloat162*)g_nsum_lo + i * 2;
    ph[0] = __nv_bfloat162{h[0], h[1]}; ph[1] = __nv_bfloat162{h[2], h[3]};
    pl[0] = __nv_bfloat162{l[0], l[1]}; pl[1] = __nv_bfloat162{l[2], l[3]};
}

// ---------------- prep: x cvt, WpT, WT transposes, dvec --------------------
#define PREP_S0 1024
#define PREP_S1 1024
#define PREP_S2 768
__global__ void k_prep(const float* __restrict__ x, const float* __restrict__ Wp,
                       const float* __restrict__ gW, const float* __restrict__ bp) {
    int blk = blockIdx.x;
    if (blk < PREP_S0) {
        int idx = blk * 256 + threadIdx.x;
        bsplit(x[idx], g_x_hi[idx], g_x_lo[idx]);
    } else if (blk < PREP_S0 + PREP_S1) {
        int idx = (blk - PREP_S0) * 256 + threadIdx.x;
        int k = idx >> 9, f2 = idx & 511;
        bsplit(Wp[idx], g_WpT_hi[(long)f2 * FDIM + k], g_WpT_lo[(long)f2 * FDIM + k]);
    } else if (blk < PREP_S0 + PREP_S1 + PREP_S2) {
        int idx = (blk - PREP_S0 - PREP_S1) * 256 + threadIdx.x;
        int l = idx / (SDIM * SDIM), r2 = idx % (SDIM * SDIM);
        int i = r2 >> 8, o = r2 & 255;
        long dst = (long)l * SDIM * SDIM + (long)o * SDIM + i;
        bsplit(gW[idx], g_WT_hi[dst], g_WT_lo[dst]);
    } else {
        __shared__ float sh[256];
        int j = blk - (PREP_S0 + PREP_S1 + PREP_S2);
        float s = 0.f;
        for (int k = threadIdx.x; k < FDIM; k += 256)
            s += bp[k] * x[(long)j * FDIM + k];
        sh[threadIdx.x] = s;
        __syncthreads();
        for (int o = 128; o > 0; o >>= 1) {
            if (threadIdx.x < o) sh[threadIdx.x] += sh[threadIdx.x + o];
            __syncthreads();
        }
        if (threadIdx.x == 0) g_dvec[j] = 2.f * sh[0];
    }
}

// ---------------- bf16-split NT GEMM via mma.sync.m16n8k16 -----------------
// CTA tile 64(M) x 128(N), 8 warps (2x4), warp tile 32x32 -> acc 32 regs.
#define KST   32
#define RSTR  40
#define TILEA (64 * RSTR * 2)                 // 5120 B  (A hi or lo, one stage)
#define TILEBB (128 * RSTR * 2)               // 10240 B (B hi or lo, one stage)
#define STAGEB (2 * TILEA + 2 * TILEBB)       // 30720 B per stage
#define MMA_SMEM (2 * STAGEB)                 // 61440 B

__device__ __forceinline__ void cpa16g(void* dst, const void* src, int nbytes) {
    unsigned d = (unsigned)__cvta_generic_to_shared(dst);
    asm volatile("cp.async.cg.shared.global [%0], [%1], 16, %2;\n"
                 :: "r"(d), "l"(src), "r"(nbytes));
}
__device__ __forceinline__ void mma16(float c[4], const unsigned a[4], const unsigned b[2]) {
    asm volatile(
        "mma.sync.aligned.m16n8k16.row.col.f32.bf16.bf16.f32 "
        "{%0,%1,%2,%3}, {%4,%5,%6,%7}, {%8,%9}, {%0,%1,%2,%3};"
        : "+f"(c[0]), "+f"(c[1]), "+f"(c[2]), "+f"(c[3])
        : "r"(a[0]), "r"(a[1]), "r"(a[2]), "r"(a[3]), "r"(b[0]), "r"(b[1]));
}
__device__ __forceinline__ void store_split(__nv_bfloat16* Ohi, __nv_bfloat16* Olo,
                                            long idx, float v0, float v1) {
    __nv_bfloat16 h0, l0, h1, l1;
    bsplit(v0, h0, l0);
    bsplit(v1, h1, l1);
    *(__nv_bfloat162*)(Ohi + idx) = __nv_bfloat162{h0, h1};
    *(__nv_bfloat162*)(Olo + idx) = __nv_bfloat162{l0, l1};
}
__device__ __forceinline__ void store_hsplit(__half* Hh, __half* Hl,
                                             long idx, float v0, float v1) {
    __half h0, l0, h1, l1;
    hsplit(v0, h0, l0);
    hsplit(v1, h1, l1);
    *(__half2*)(Hh + idx) = __half2{h0, h1};
    *(__half2*)(Hl + idx) = __half2{l0, l1};
}

// modes: 0 = fp16 hi/lo hw store; 1 = H0 (dvec add + bf16 split [b,n,s]); 2 = bf16 split row-major
__global__ __launch_bounds__(256, 3) void mma_bf(
    const __nv_bfloat16* __restrict__ Ahi, const __nv_bfloat16* __restrict__ Alo,
    const __nv_bfloat16* __restrict__ Bhi, const __nv_bfloat16* __restrict__ Blo,
    __half* __restrict__ Chh, __half* __restrict__ Chl,
    __nv_bfloat16* __restrict__ Ohi, __nv_bfloat16* __restrict__ Olo,
    const float* __restrict__ dvec,
    int M, int K, int ldc, long aSlab, long cSlab, int mode)
{
    extern __shared__ char smem[];
    int t = threadIdx.x;
    int brow = blockIdx.x * 64, bcol = blockIdx.y * 128;
    long zA = (long)blockIdx.z * aSlab;
    int lane = t & 31, wid = t >> 5;
    int g = lane >> 2, tig = lane & 3;
    int wm = (wid & 1) * 32, wn = (wid >> 1) * 32;

    float acc[2][4][4] = {};
    int nK = K / KST;

    // per-stage chunk assignment:
    //  A (64 rows x 4 quads = 256 chunks): thread t -> chunk t
    //  B (128 rows x 4 quads = 512 chunks): thread t -> chunks t, t+256
    int arow = t >> 2, aq = (t & 3);
    int brow0 = t >> 2, bq0 = (t & 3);
    int brow1 = (t + 256) >> 2, bq1 = (t & 3);

    auto load_stage = [&](int st, int k0) {
        char* base = smem + st * STAGEB;
        {
            long ao = zA + (long)(brow + arow) * K + k0 + aq * 8;
            int av = ((brow + arow) < M) ? 16 : 0;
            unsigned off = arow * (RSTR * 2) + aq * 16;
            cpa16g(base + off, Ahi + ao, av);
            cpa16g(base + TILEA + off, Alo + ao, av);
        }
        {
            long bo = (long)(bcol + brow0) * K + k0 + bq0 * 8;
            unsigned off = brow0 * (RSTR * 2) + bq0 * 16;
            cpa16g(base + 2 * TILEA + off, Bhi + bo, 16);
            cpa16g(base + 2 * TILEA + TILEBB + off, Blo + bo, 16);
        }
        {
            long bo = (long)(bcol + brow1) * K + k0 + bq1 * 8;
            unsigned off = brow1 * (RSTR * 2) + bq1 * 16;
            cpa16g(base + 2 * TILEA + off, Bhi + bo, 16);
            cpa16g(base + 2 * TILEA + TILEBB + off, Blo + bo, 16);
        }
        asm volatile("cp.async.commit_group;\n");
    };

    load_stage(0, 0);

    for (int it = 0; it < nK; ++it) {
        asm volatile("cp.async.wait_group 0;\n");
        __syncthreads();
        if (it + 1 < nK) load_stage((it + 1) & 1, (it + 1) * KST);
        char* base = smem + (it & 1) * STAGEB;
        const __nv_bfloat16* ah_s = (const __nv_bfloat16*)(base);
        const __nv_bfloat16* al_s = (const __nv_bfloat16*)(base + TILEA);
        const __nv_bfloat16* bh_s = (const __nv_bfloat16*)(base + 2 * TILEA);
        const __nv_bfloat16* bl_s = (const __nv_bfloat16*)(base + 2 * TILEA + TILEBB);

#pragma unroll
        for (int ks = 0; ks < KST; ks += 16) {
            unsigned ah[2][4], al[2][4], bh[4][2], bl[4][2];
#pragma unroll
            for (int mi = 0; mi < 2; ++mi) {
                int m = wm + mi * 16 + g;
                ah[mi][0] = *(const unsigned*)(ah_s + m * RSTR + ks + 2 * tig);
                ah[mi][1] = *(const unsigned*)(ah_s + (m + 8) * RSTR + ks + 2 * tig);
                ah[mi][2] = *(const unsigned*)(ah_s + m * RSTR + ks + 8 + 2 * tig);
                ah[mi][3] = *(const unsigned*)(ah_s + (m + 8) * RSTR + ks + 8 + 2 * tig);
                al[mi][0] = *(const unsigned*)(al_s + m * RSTR + ks + 2 * tig);
                al[mi][1] = *(const unsigned*)(al_s + (m + 8) * RSTR + ks + 2 * tig);
                al[mi][2] = *(const unsigned*)(al_s + m * RSTR + ks + 8 + 2 * tig);
                al[mi][3] = *(const unsigned*)(al_s + (m + 8) * RSTR + ks + 8 + 2 * tig);
            }
#pragma unroll
            for (int ni = 0; ni < 4; ++ni) {
                int n = wn + ni * 8 + g;
                bh[ni][0] = *(const unsigned*)(bh_s + n * RSTR + ks + 2 * tig);
                bh[ni][1] = *(const unsigned*)(bh_s + n * RSTR + ks + 8 + 2 * tig);
                bl[ni][0] = *(const unsigned*)(bl_s + n * RSTR + ks + 2 * tig);
                bl[ni][1] = *(const unsigned*)(bl_s + n * RSTR + ks + 8 + 2 * tig);
            }
#pragma unroll
            for (int mi = 0; mi < 2; ++mi)
#pragma unroll
                for (int ni = 0; ni < 4; ++ni)
                    mma16(acc[mi][ni], ah[mi], bh[ni]);
#pragma unroll
            for (int mi = 0; mi < 2; ++mi)
#pragma unroll
                for (int ni = 0; ni < 4; ++ni)
                    mma16(acc[mi][ni], ah[mi], bl[ni]);
#pragma unroll
            for (int mi = 0; mi < 2; ++mi)
#pragma unroll
                for (int ni = 0; ni < 4; ++ni)
                    mma16(acc[mi][ni], al[mi], bh[ni]);
        }
        __syncthreads();
    }

    // epilogue
#pragma unroll
    for (int mi = 0; mi < 2; ++mi) {
        int r0 = brow + wm + mi * 16 + g;
#pragma unroll
        for (int ni = 0; ni < 4; ++ni) {
            int c0 = bcol + wn + ni * 8 + 2 * tig;
            if (mode == 0) {
                long zc = (long)blockIdx.z * cSlab;
                if (r0 < M)
                    store_hsplit(Chh, Chl, zc + (long)r0 * ldc + c0,
                                 acc[mi][ni][0], acc[mi][ni][1]);
                if (r0 + 8 < M)
                    store_hsplit(Chh, Chl, zc + (long)(r0 + 8) * ldc + c0,
                                 acc[mi][ni][2], acc[mi][ni][3]);
            } else if (mode == 1) {
                int b = c0 >> 8, s0 = c0 & 255;
                float d0 = dvec[c0], d1 = dvec[c0 + 1];
                long baseO = (long)b * NNODES * SDIM;
                if (r0 < M)
                    store_split(Ohi, Olo, baseO + (long)r0 * SDIM + s0,
                                acc[mi][ni][0] + d0, acc[mi][ni][1] + d1);
                if (r0 + 8 < M)
                    store_split(Ohi, Olo, baseO + (long)(r0 + 8) * SDIM + s0,
                                acc[mi][ni][2] + d0, acc[mi][ni][3] + d1);
            } else {
                if (r0 < M)
                    store_split(Ohi, Olo, (long)r0 * ldc + c0,
                                acc[mi][ni][0], acc[mi][ni][1]);
                if (r0 + 8 < M)
                    store_split(Ohi, Olo, (long)(r0 + 8) * ldc + c0,
                                acc[mi][ni][2], acc[mi][ni][3]);
            }
        }
    }
}

// ---------------- CSR aggregation (fp16 gather, simple loop) ----------------
__global__ __launch_bounds__(256) void k_agg(const float* __restrict__ bias,
                                             const float* __restrict__ wbp,
                                             const float* __restrict__ bbp,
                                             float* __restrict__ out, int final_) {
    __shared__ float red[4][2][2];
    int sub = threadIdx.x >> 6;
    int t64 = threadIdx.x & 63;
    int node = blockIdx.x * 4 + sub;
    float dt = g_dinv[node];
    const uint2* Hh = (const uint2*)g_hw_h;
    const uint2* Hl = (const uint2*)g_hw_l;
    const long slab8 = (long)NNODES * 64;
    long n8 = (long)node * 64 + t64;

    float4 s0h = h2f4(Hh[n8]),         s0l = h2f4(Hl[n8]);
    float4 s1h = h2f4(Hh[slab8 + n8]), s1l = h2f4(Hl[slab8 + n8]);
    float sw = dt * dt;
    float4 acc0 = make_float4((s0h.x + s0l.x) * sw, (s0h.y + s0l.y) * sw,
                              (s0h.z + s0l.z) * sw, (s0h.w + s0l.w) * sw);
    float4 acc1 = make_float4((s1h.x + s1l.x) * sw, (s1h.y + s1l.y) * sw,
                              (s1h.z + s1l.z) * sw, (s1h.w + s1l.w) * sw);
    int e0 = g_off[node], e1 = g_off[node + 1];
    for (int e = e0; e < e1; ++e) {
        int src = g_srcs[e];
        float w = g_wnorm[e];
        long s8 = (long)src * 64 + t64;
        float4 u0 = h2f4(Hh[s8]);
        float4 u1 = h2f4(Hh[slab8 + s8]);
        acc0.x = fmaf(u0.x, w, acc0.x); acc0.y = fmaf(u0.y, w, acc0.y);
        acc0.z = fmaf(u0.z, w, acc0.z); acc0.w = fmaf(u0.w, w, acc0.w);
        acc1.x = fmaf(u1.x, w, acc1.x); acc1.y = fmaf(u1.y, w, acc1.y);
        acc1.z = fmaf(u1.z, w, acc1.z); acc1.w = fmaf(u1.w, w, acc1.w);
    }
    float4 bb = ((const float4*)bias)[t64];
    acc0.x += bb.x; acc0.y += bb.y; acc0.z += bb.z; acc0.w += bb.w;
    acc1.x += bb.x; acc1.y += bb.y; acc1.z += bb.z; acc1.w += bb.w;
    acc0.x = acc0.x > 0.f ? acc0.x : 0.01f * acc0.x;
    acc0.y = acc0.y > 0.f ? acc0.y : 0.01f * acc0.y;
    acc0.z = acc0.z > 0.f ? acc0.z : 0.01f * acc0.z;
    acc0.w = acc0.w > 0.f ? acc0.w : 0.01f * acc0.w;
    acc1.x = acc1.x > 0.f ? acc1.x : 0.01f * acc1.x;
    acc1.y = acc1.y > 0.f ? acc1.y : 0.01f * acc1.y;
    acc1.z = acc1.z > 0.f ? acc1.z : 0.01f * acc1.z;
    acc1.w = acc1.w > 0.f ? acc1.w : 0.01f * acc1.w;

    if (!final_) {
        long bE = (long)node * SDIM + t64 * 4;
        __nv_bfloat16 h0, l0, h1, l1, h2, l2, h3, l3;
        bsplit(acc0.x, h0, l0); bsplit(acc0.y, h1, l1);
        bsplit(acc0.z, h2, l2); bsplit(acc0.w, h3, l3);
        ((__nv_bfloat162*)(g_Ahi + bE))[0] = __nv_bfloat162{h0, h1};
        ((__nv_bfloat162*)(g_Ahi + bE))[1] = __nv_bfloat162{h2, h3};
        ((__nv_bfloat162*)(g_Alo + bE))[0] = __nv_bfloat162{l0, l1};
        ((__nv_bfloat162*)(g_Alo + bE))[1] = __nv_bfloat162{l2, l3};
        long bE1 = bE + (long)NNODES * SDIM;
        bsplit(acc1.x, h0, l0); bsplit(acc1.y, h1, l1);
        bsplit(acc1.z, h2, l2); bsplit(acc1.w, h3, l3);
        ((__nv_bfloat162*)(g_Ahi + bE1))[0] = __nv_bfloat162{h0, h1};
        ((__nv_bfloat162*)(g_Ahi + bE1))[1] = __nv_bfloat162{h2, h3};
        ((__nv_bfloat162*)(g_Alo + bE1))[0] = __nv_bfloat162{l0, l1};
        ((__nv_bfloat162*)(g_Alo + bE1))[1] = __nv_bfloat162{l2, l3};
    } else {
        float4 w4 = ((const float4*)wbp)[t64];
        float p0 = acc0.x * w4.x + acc0.y * w4.y + acc0.z * w4.z + acc0.w * w4.w;
        float p1 = acc1.x * w4.x + acc1.y * w4.y + acc1.z * w4.z + acc1.w * w4.w;
#pragma unroll
        for (int o = 16; o; o >>= 1) {
            p0 += __shfl_xor_sync(0xffffffffu, p0, o);
            p1 += __shfl_xor_sync(0xffffffffu, p1, o);
        }
        int w = t64 >> 5;
        if ((t64 & 31) == 0) { red[sub][w][0] = p0; red[sub][w][1] = p1; }
        __syncthreads();
        if (t64 == 0) {
            float b0 = bbp[0];
            out[node] = red[sub][0][0] + red[sub][1][0] + b0;
            out[NNODES + node] = red[sub][0][1] + red[sub][1][1] + b0;
        }
    }
}

// ---------------- launcher -------------------------------------------------
extern "C" void kernel_launch(void* const* d_in, const int* in_sizes, int n_in,
                              void* d_out, int out_size) {
    const float* x     = (const float*)d_in[0];
    const float* nodes = (const float*)d_in[1];
    const int*   ei    = (const int*)  d_in[2];
    const float* Wp    = (const float*)d_in[3];
    const float* bp    = (const float*)d_in[4];
    const float* gW    = (const float*)d_in[5];
    const float* gb    = (const float*)d_in[6];
    const float* wbp   = (const float*)d_in[7];
    const float* bbp   = (const float*)d_in[8];
    float* out = (float*)d_out;

    cudaFuncSetAttribute(mma_bf, cudaFuncAttributeMaxDynamicSharedMemorySize, MMA_SMEM);

    void *pNh, *pNl, *pXh, *pXl, *pWh, *pWl, *pCh, *pCl, *pTh, *pTl, *pAh, *pAl,
         *pHh, *pHl, *pDV;
    cudaGetSymbolAddress(&pNh, g_nsum_hi); cudaGetSymbolAddress(&pNl, g_nsum_lo);
    cudaGetSymbolAddress(&pXh, g_x_hi);    cudaGetSymbolAddress(&pXl, g_x_lo);
    cudaGetSymbolAddress(&pWh, g_WpT_hi);  cudaGetSymbolAddress(&pWl, g_WpT_lo);
    cudaGetSymbolAddress(&pCh, g_CT_hi);   cudaGetSymbolAddress(&pCl, g_CT_lo);
    cudaGetSymbolAddress(&pTh, g_WT_hi);   cudaGetSymbolAddress(&pTl, g_WT_lo);
    cudaGetSymbolAddress(&pAh, g_Ahi);     cudaGetSymbolAddress(&pAl, g_Alo);
    cudaGetSymbolAddress(&pHh, g_hw_h);    cudaGetSymbolAddress(&pHl, g_hw_l);
    cudaGetSymbolAddress(&pDV, g_dvec);

    const int MB64 = (NNODES + 63) / 64;   // 313
    const long slab = (long)NNODES * SDIM;

    // 0: nsum -> hi/lo
    k_nsum<<<(int)(((long)NNODES * FDIM / 4 + 255) / 256), 256>>>(nodes);
    // 1: x cvt + WpT + WT + dvec
    k_prep<<<PREP_S0 + PREP_S1 + PREP_S2 + BSJ, 256>>>(x, Wp, gW, bp);
    // 2: CT = x @ Wp (mode 2)
    mma_bf<<<dim3(BSJ / 64, FDIM / 128, 1), 256, MMA_SMEM>>>(
        (__nv_bfloat16*)pXh, (__nv_bfloat16*)pXl,
        (__nv_bfloat16*)pWh, (__nv_bfloat16*)pWl,
        nullptr, nullptr, (__nv_bfloat16*)pCh, (__nv_bfloat16*)pCl, nullptr,
        BSJ, FDIM, FDIM, 0, 0, 2);
    // 3: H0 = nsum @ CT^T + dvec (mode 1)  <- ncu samples launch index 3
    mma_bf<<<dim3(MB64, BSJ / 128, 1), 256, MMA_SMEM>>>(
        (__nv_bfloat16*)pNh, (__nv_bfloat16*)pNl,
        (__nv_bfloat16*)pCh, (__nv_bfloat16*)pCl,
        nullptr, nullptr, (__nv_bfloat16*)pAh, (__nv_bfloat16*)pAl, (float*)pDV,
        NNODES, FDIM, 0, 0, 0, 1);

    // CSR build
    k_init_deg<<<(NNODES + 255) / 256, 256>>>();
    k_hist<<<(NE_ + 255) / 256, 256>>>(ei);
    k_scan<<<1, 512>>>();
    k_scatter<<<(NE_ + 255) / 256, 256>>>(ei);

    // GCN layers (final layer fuses belief projection)
    for (int l = 0; l < NLAYERS; ++l) {
        mma_bf<<<dim3(MB64, SDIM / 128, NB), 256, MMA_SMEM>>>(
            (__nv_bfloat16*)pAh, (__nv_bfloat16*)pAl,
            (__nv_bfloat16*)pTh + (long)l * SDIM * SDIM,
            (__nv_bfloat16*)pTl + (long)l * SDIM * SDIM,
            (__half*)pHh, (__half*)pHl, nullptr, nullptr, nullptr,
            NNODES, SDIM, SDIM, slab, slab, 0);
        k_agg<<<NNODES / 4, 256>>>(gb + (long)l * SDIM, wbp, bbp, out,
                                   (l == NLAYERS - 1) ? 1 : 0);
    }
}

// round 13
// speedup vs baseline: 1.6652x; 1.0387x over previous
#include <cuda_runtime.h>
#include <cuda_bf16.h>
#include <cuda_fp16.h>
#include <cstdint>

#define NB       2
#define SDIM     256
#define FDIM     512
#define NNODES   20000
#define NE_      320000
#define NLAYERS  3
#define BSJ      512

// ---------------- scratch (device globals) ---------------------------------
__device__ __nv_bfloat16 g_nsum_hi[(size_t)NNODES * FDIM];
__device__ __nv_bfloat16 g_nsum_lo[(size_t)NNODES * FDIM];
__device__ __nv_bfloat16 g_x_hi  [(size_t)BSJ * FDIM];
__device__ __nv_bfloat16 g_x_lo  [(size_t)BSJ * FDIM];
__device__ __nv_bfloat16 g_WpT_hi[(size_t)FDIM * FDIM];
__device__ __nv_bfloat16 g_WpT_lo[(size_t)FDIM * FDIM];
__device__ __nv_bfloat16 g_CT_hi [(size_t)BSJ * FDIM];
__device__ __nv_bfloat16 g_CT_lo [(size_t)BSJ * FDIM];
__device__ __nv_bfloat16 g_WT_hi [(size_t)NLAYERS * SDIM * SDIM];
__device__ __nv_bfloat16 g_WT_lo [(size_t)NLAYERS * SDIM * SDIM];
__device__ __nv_bfloat16 g_Ahi   [(size_t)NB * NNODES * SDIM];
__device__ __nv_bfloat16 g_Alo   [(size_t)NB * NNODES * SDIM];
__device__ __half        g_hw_h  [(size_t)NB * NNODES * SDIM];   // hw fp16 (hi only)
__device__ float g_dvec[BSJ];
__device__ int   g_deg [NNODES];
__device__ int   g_off [NNODES + 1];
__device__ int   g_cur [NNODES];
__device__ int   g_srcs[NE_];
__device__ float g_wnorm[NE_];
__device__ float g_dinv[NNODES];

__device__ __forceinline__ void bsplit(float v, __nv_bfloat16& h, __nv_bfloat16& l) {
    h = __float2bfloat16(v);
    l = __float2bfloat16(v - __bfloat162float(h));
}
__device__ __forceinline__ float4 h2f4(uint2 u) {
    __half2 a = *(__half2*)&u.x, b = *(__half2*)&u.y;
    float2 fa = __half22float2(a), fb = __half22float2(b);
    return make_float4(fa.x, fa.y, fb.x, fb.y);
}

// ---------------- CSR build ------------------------------------------------
__global__ void k_hist(const int* __restrict__ ei) {
    int e = blockIdx.x * blockDim.x + threadIdx.x;
    if (e < NE_) atomicAdd(&g_deg[ei[NE_ + e]], 1);
}
__global__ void k_scan() {
    __shared__ int ssum[512];
    int tid = threadIdx.x;
    const int CH = (NNODES + 511) / 512;
    int base = tid * CH;
    int s = 0;
    for (int i = 0; i < CH; ++i) {
        int idx = base + i;
        if (idx < NNODES) s += g_deg[idx] - 1;
    }
    ssum[tid] = s;
    __syncthreads();
    for (int off = 1; off < 512; off <<= 1) {
        int v = ssum[tid];
        int u = (tid >= off) ? ssum[tid - off] : 0;
        __syncthreads();
        ssum[tid] = v + u;
        __syncthreads();
    }
    int run = (tid == 0) ? 0 : ssum[tid - 1];
    for (int i = 0; i < CH; ++i) {
        int idx = base + i;
        if (idx < NNODES) {
            g_off[idx] = run;
            g_cur[idx] = run;
            g_dinv[idx] = rsqrtf((float)g_deg[idx]);
            run += g_deg[idx] - 1;
        }
    }
    if (tid == 511) g_off[NNODES] = run;
}
__global__ void k_scatter(const int* __restrict__ ei) {
    int e = blockIdx.x * blockDim.x + threadIdx.x;
    if (e < NE_) {
        int s = ei[e];
        int d = ei[NE_ + e];
        int p = atomicAdd(&g_cur[d], 1);
        g_srcs[p] = s;
        g_wnorm[p] = g_dinv[s] * g_dinv[d];
    }
}

// ---------------- nsum -> bf16 hi/lo (+ deg init in tail blocks) -----------
#define NSUM_BLK ((int)(((long)NNODES * FDIM / 4 + 255) / 256))   // 10000
__global__ void k_nsum(const float* __restrict__ nodes) {
    if (blockIdx.x >= NSUM_BLK) {
        int i = (blockIdx.x - NSUM_BLK) * 256 + threadIdx.x;
        if (i < NNODES) g_deg[i] = 1;
        return;
    }
    long i = (long)blockIdx.x * blockDim.x + threadIdx.x;
    const float4* nd = (const float4*)nodes;
    long n = i / (FDIM / 4);
    long f = i % (FDIM / 4);
    float4 a = nd[n * (2 * FDIM / 4) + f];
    float4 b = nd[n * (2 * FDIM / 4) + FDIM / 4 + f];
    float v[4] = {a.x + b.x, a.y + b.y, a.z + b.z, a.w + b.w};
    __nv_bfloat16 h[4], l[4];
#pragma unroll
    for (int q = 0; q < 4; ++q) bsplit(v[q], h[q], l[q]);
    __nv_bfloat162* ph = (__nv_bfloat162*)g_nsum_hi + i * 2;
    __nv_bfloat162* pl = (__nv_bfloat162*)g_nsum_lo + i * 2;
    ph[0] = __nv_bfloat162{h[0], h[1]}; ph[1] = __nv_bfloat162{h[2], h[3]};
    pl[0] = __nv_bfloat162{l[0], l[1]}; pl[1] = __nv_bfloat162{l[2], l[3]};
}

// ---------------- prep: x cvt, WpT, WT transposes, dvec --------------------
#define PREP_S0 1024
#define PREP_S1 1024
#define PREP_S2 768
__global__ void k_prep(const float* __restrict__ x, const float* __restrict__ Wp,
                       const float* __restrict__ gW, const float* __restrict__ bp) {
    int blk = blockIdx.x;
    if (blk < PREP_S0) {
        int idx = blk * 256 + threadIdx.x;
        bsplit(x[idx], g_x_hi[idx], g_x_lo[idx]);
    } else if (blk < PREP_S0 + PREP_S1) {
        int idx = (blk - PREP_S0) * 256 + threadIdx.x;
        int k = idx >> 9, f2 = idx & 511;
        bsplit(Wp[idx], g_WpT_hi[(long)f2 * FDIM + k], g_WpT_lo[(long)f2 * FDIM + k]);
    } else if (blk < PREP_S0 + PREP_S1 + PREP_S2) {
        int idx = (blk - PREP_S0 - PREP_S1) * 256 + threadIdx.x;
        int l = idx / (SDIM * SDIM), r2 = idx % (SDIM * SDIM);
        int i = r2 >> 8, o = r2 & 255;
        long dst = (long)l * SDIM * SDIM + (long)o * SDIM + i;
        bsplit(gW[idx], g_WT_hi[dst], g_WT_lo[dst]);
    } else {
        __shared__ float sh[256];
        int j = blk - (PREP_S0 + PREP_S1 + PREP_S2);
        float s = 0.f;
        for (int k = threadIdx.x; k < FDIM; k += 256)
            s += bp[k] * x[(long)j * FDIM + k];
        sh[threadIdx.x] = s;
        __syncthreads();
        for (int o = 128; o > 0; o >>= 1) {
            if (threadIdx.x < o) sh[threadIdx.x] += sh[threadIdx.x + o];
            __syncthreads();
        }
        if (threadIdx.x == 0) g_dvec[j] = 2.f * sh[0];
    }
}

// ---------------- bf16-split NT GEMM via mma.sync.m16n8k16 -----------------
// CTA tile 64(M) x 128(N), 8 warps (2x4), warp tile 32x32.
#define KST   32
#define RSTR  40
#define TILEA (64 * RSTR * 2)
#define TILEBB (128 * RSTR * 2)
#define STAGEB (2 * TILEA + 2 * TILEBB)
#define MMA_SMEM (2 * STAGEB)

__device__ __forceinline__ void cpa16g(void* dst, const void* src, int nbytes) {
    unsigned d = (unsigned)__cvta_generic_to_shared(dst);
    asm volatile("cp.async.cg.shared.global [%0], [%1], 16, %2;\n"
                 :: "r"(d), "l"(src), "r"(nbytes));
}
__device__ __forceinline__ void mma16(float c[4], const unsigned a[4], const unsigned b[2]) {
    asm volatile(
        "mma.sync.aligned.m16n8k16.row.col.f32.bf16.bf16.f32 "
        "{%0,%1,%2,%3}, {%4,%5,%6,%7}, {%8,%9}, {%0,%1,%2,%3};"
        : "+f"(c[0]), "+f"(c[1]), "+f"(c[2]), "+f"(c[3])
        : "r"(a[0]), "r"(a[1]), "r"(a[2]), "r"(a[3]), "r"(b[0]), "r"(b[1]));
}
__device__ __forceinline__ void store_split(__nv_bfloat16* Ohi, __nv_bfloat16* Olo,
                                            long idx, float v0, float v1) {
    __nv_bfloat16 h0, l0, h1, l1;
    bsplit(v0, h0, l0);
    bsplit(v1, h1, l1);
    *(__nv_bfloat162*)(Ohi + idx) = __nv_bfloat162{h0, h1};
    *(__nv_bfloat162*)(Olo + idx) = __nv_bfloat162{l0, l1};
}

// modes: 0 = fp16 hi-only hw store; 1 = H0 (dvec add + bf16 split [b,n,s]); 2 = bf16 split row-major
__global__ __launch_bounds__(256, 3) void mma_bf(
    const __nv_bfloat16* __restrict__ Ahi, const __nv_bfloat16* __restrict__ Alo,
    const __nv_bfloat16* __restrict__ Bhi, const __nv_bfloat16* __restrict__ Blo,
    __half* __restrict__ Chh,
    __nv_bfloat16* __restrict__ Ohi, __nv_bfloat16* __restrict__ Olo,
    const float* __restrict__ dvec,
    int M, int K, int ldc, long aSlab, long cSlab, int mode)
{
    extern __shared__ char smem[];
    int t = threadIdx.x;
    int brow = blockIdx.x * 64, bcol = blockIdx.y * 128;
    long zA = (long)blockIdx.z * aSlab;
    int lane = t & 31, wid = t >> 5;
    int g = lane >> 2, tig = lane & 3;
    int wm = (wid & 1) * 32, wn = (wid >> 1) * 32;

    float acc[2][4][4] = {};
    int nK = K / KST;

    int arow = t >> 2, aq = (t & 3);
    int brow0 = t >> 2, bq0 = (t & 3);
    int brow1 = (t + 256) >> 2, bq1 = (t & 3);

    auto load_stage = [&](int st, int k0) {
        char* base = smem + st * STAGEB;
        {
            long ao = zA + (long)(brow + arow) * K + k0 + aq * 8;
            int av = ((brow + arow) < M) ? 16 : 0;
            unsigned off = arow * (RSTR * 2) + aq * 16;
            cpa16g(base + off, Ahi + ao, av);
            cpa16g(base + TILEA + off, Alo + ao, av);
        }
        {
            long bo = (long)(bcol + brow0) * K + k0 + bq0 * 8;
            unsigned off = brow0 * (RSTR * 2) + bq0 * 16;
            cpa16g(base + 2 * TILEA + off, Bhi + bo, 16);
            cpa16g(base + 2 * TILEA + TILEBB + off, Blo + bo, 16);
        }
        {
            long bo = (long)(bcol + brow1) * K + k0 + bq1 * 8;
            unsigned off = brow1 * (RSTR * 2) + bq1 * 16;
            cpa16g(base + 2 * TILEA + off, Bhi + bo, 16);
            cpa16g(base + 2 * TILEA + TILEBB + off, Blo + bo, 16);
        }
        asm volatile("cp.async.commit_group;\n");
    };

    load_stage(0, 0);

    for (int it = 0; it < nK; ++it) {
        asm volatile("cp.async.wait_group 0;\n");
        __syncthreads();
        if (it + 1 < nK) load_stage((it + 1) & 1, (it + 1) * KST);
        char* base = smem + (it & 1) * STAGEB;
        const __nv_bfloat16* ah_s = (const __nv_bfloat16*)(base);
        const __nv_bfloat16* al_s = (const __nv_bfloat16*)(base + TILEA);
        const __nv_bfloat16* bh_s = (const __nv_bfloat16*)(base + 2 * TILEA);
        const __nv_bfloat16* bl_s = (const __nv_bfloat16*)(base + 2 * TILEA + TILEBB);

#pragma unroll
        for (int ks = 0; ks < KST; ks += 16) {
            unsigned ah[2][4], al[2][4], bh[4][2], bl[4][2];
#pragma unroll
            for (int mi = 0; mi < 2; ++mi) {
                int m = wm + mi * 16 + g;
                ah[mi][0] = *(const unsigned*)(ah_s + m * RSTR + ks + 2 * tig);
                ah[mi][1] = *(const unsigned*)(ah_s + (m + 8) * RSTR + ks + 2 * tig);
                ah[mi][2] = *(const unsigned*)(ah_s + m * RSTR + ks + 8 + 2 * tig);
                ah[mi][3] = *(const unsigned*)(ah_s + (m + 8) * RSTR + ks + 8 + 2 * tig);
                al[mi][0] = *(const unsigned*)(al_s + m * RSTR + ks + 2 * tig);
                al[mi][1] = *(const unsigned*)(al_s + (m + 8) * RSTR + ks + 2 * tig);
                al[mi][2] = *(const unsigned*)(al_s + m * RSTR + ks + 8 + 2 * tig);
                al[mi][3] = *(const unsigned*)(al_s + (m + 8) * RSTR + ks + 8 + 2 * tig);
            }
#pragma unroll
            for (int ni = 0; ni < 4; ++ni) {
                int n = wn + ni * 8 + g;
                bh[ni][0] = *(const unsigned*)(bh_s + n * RSTR + ks + 2 * tig);
                bh[ni][1] = *(const unsigned*)(bh_s + n * RSTR + ks + 8 + 2 * tig);
                bl[ni][0] = *(const unsigned*)(bl_s + n * RSTR + ks + 2 * tig);
                bl[ni][1] = *(const unsigned*)(bl_s + n * RSTR + ks + 8 + 2 * tig);
            }
#pragma unroll
            for (int mi = 0; mi < 2; ++mi)
#pragma unroll
                for (int ni = 0; ni < 4; ++ni)
                    mma16(acc[mi][ni], ah[mi], bh[ni]);
#pragma unroll
            for (int mi = 0; mi < 2; ++mi)
#pragma unroll
                for (int ni = 0; ni < 4; ++ni)
                    mma16(acc[mi][ni], ah[mi], bl[ni]);
#pragma unroll
            for (int mi = 0; mi < 2; ++mi)
#pragma unroll
                for (int ni = 0; ni < 4; ++ni)
                    mma16(acc[mi][ni], al[mi], bh[ni]);
        }
        __syncthreads();
    }

    // epilogue
#pragma unroll
    for (int mi = 0; mi < 2; ++mi) {
        int r0 = brow + wm + mi * 16 + g;
#pragma unroll
        for (int ni = 0; ni < 4; ++ni) {
            int c0 = bcol + wn + ni * 8 + 2 * tig;
            if (mode == 0) {
                long zc = (long)blockIdx.z * cSlab;
                if (r0 < M)
                    *(__half2*)(Chh + zc + (long)r0 * ldc + c0) =
                        __floats2half2_rn(acc[mi][ni][0], acc[mi][ni][1]);
                if (r0 + 8 < M)
                    *(__half2*)(Chh + zc + (long)(r0 + 8) * ldc + c0) =
                        __floats2half2_rn(acc[mi][ni][2], acc[mi][ni][3]);
            } else if (mode == 1) {
                int b = c0 >> 8, s0 = c0 & 255;
                float d0 = dvec[c0], d1 = dvec[c0 + 1];
                long baseO = (long)b * NNODES * SDIM;
                if (r0 < M)
                    store_split(Ohi, Olo, baseO + (long)r0 * SDIM + s0,
                                acc[mi][ni][0] + d0, acc[mi][ni][1] + d1);
                if (r0 + 8 < M)
                    store_split(Ohi, Olo, baseO + (long)(r0 + 8) * SDIM + s0,
                                acc[mi][ni][2] + d0, acc[mi][ni][3] + d1);
            } else {
                if (r0 < M)
                    store_split(Ohi, Olo, (long)r0 * ldc + c0,
                                acc[mi][ni][0], acc[mi][ni][1]);
                if (r0 + 8 < M)
                    store_split(Ohi, Olo, (long)(r0 + 8) * ldc + c0,
                                acc[mi][ni][2], acc[mi][ni][3]);
            }
        }
    }
}

// ---------------- CSR aggregation (fp16 gather, unrolled loop) --------------
__global__ __launch_bounds__(256) void k_agg(const float* __restrict__ bias,
                                             const float* __restrict__ wbp,
                                             const float* __restrict__ bbp,
                                             float* __restrict__ out, int final_) {
    __shared__ float red[4][2][2];
    int sub = threadIdx.x >> 6;
    int t64 = threadIdx.x & 63;
    int node = blockIdx.x * 4 + sub;
    float dt = g_dinv[node];
    const uint2* Hh = (const uint2*)g_hw_h;
    const long slab8 = (long)NNODES * 64;
    long n8 = (long)node * 64 + t64;

    float4 s0 = h2f4(Hh[n8]);
    float4 s1 = h2f4(Hh[slab8 + n8]);
    float sw = dt * dt;
    float4 acc0 = make_float4(s0.x * sw, s0.y * sw, s0.z * sw, s0.w * sw);
    float4 acc1 = make_float4(s1.x * sw, s1.y * sw, s1.z * sw, s1.w * sw);
    int e0 = g_off[node], e1 = g_off[node + 1];
#pragma unroll 4
    for (int e = e0; e < e1; ++e) {
        int src = g_srcs[e];
        float w = g_wnorm[e];
        long s8 = (long)src * 64 + t64;
        float4 u0 = h2f4(Hh[s8]);
        float4 u1 = h2f4(Hh[slab8 + s8]);
        acc0.x = fmaf(u0.x, w, acc0.x); acc0.y = fmaf(u0.y, w, acc0.y);
        acc0.z = fmaf(u0.z, w, acc0.z); acc0.w = fmaf(u0.w, w, acc0.w);
        acc1.x = fmaf(u1.x, w, acc1.x); acc1.y = fmaf(u1.y, w, acc1.y);
        acc1.z = fmaf(u1.z, w, acc1.z); acc1.w = fmaf(u1.w, w, acc1.w);
    }
    float4 bb = ((const float4*)bias)[t64];
    acc0.x += bb.x; acc0.y += bb.y; acc0.z += bb.z; acc0.w += bb.w;
    acc1.x += bb.x; acc1.y += bb.y; acc1.z += bb.z; acc1.w += bb.w;
    acc0.x = acc0.x > 0.f ? acc0.x : 0.01f * acc0.x;
    acc0.y = acc0.y > 0.f ? acc0.y : 0.01f * acc0.y;
    acc0.z = acc0.z > 0.f ? acc0.z : 0.01f * acc0.z;
    acc0.w = acc0.w > 0.f ? acc0.w : 0.01f * acc0.w;
    acc1.x = acc1.x > 0.f ? acc1.x : 0.01f * acc1.x;
    acc1.y = acc1.y > 0.f ? acc1.y : 0.01f * acc1.y;
    acc1.z = acc1.z > 0.f ? acc1.z : 0.01f * acc1.z;
    acc1.w = acc1.w > 0.f ? acc1.w : 0.01f * acc1.w;

    if (!final_) {
        long bE = (long)node * SDIM + t64 * 4;
        __nv_bfloat16 h0, l0, h1, l1, h2, l2, h3, l3;
        bsplit(acc0.x, h0, l0); bsplit(acc0.y, h1, l1);
        bsplit(acc0.z, h2, l2); bsplit(acc0.w, h3, l3);
        ((__nv_bfloat162*)(g_Ahi + bE))[0] = __nv_bfloat162{h0, h1};
        ((__nv_bfloat162*)(g_Ahi + bE))[1] = __nv_bfloat162{h2, h3};
        ((__nv_bfloat162*)(g_Alo + bE))[0] = __nv_bfloat162{l0, l1};
        ((__nv_bfloat162*)(g_Alo + bE))[1] = __nv_bfloat162{l2, l3};
        long bE1 = bE + (long)NNODES * SDIM;
        bsplit(acc1.x, h0, l0); bsplit(acc1.y, h1, l1);
        bsplit(acc1.z, h2, l2); bsplit(acc1.w, h3, l3);
        ((__nv_bfloat162*)(g_Ahi + bE1))[0] = __nv_bfloat162{h0, h1};
        ((__nv_bfloat162*)(g_Ahi + bE1))[1] = __nv_bfloat162{h2, h3};
        ((__nv_bfloat162*)(g_Alo + bE1))[0] = __nv_bfloat162{l0, l1};
        ((__nv_bfloat162*)(g_Alo + bE1))[1] = __nv_bfloat162{l2, l3};
    } else {
        float4 w4 = ((const float4*)wbp)[t64];
        float p0 = acc0.x * w4.x + acc0.y * w4.y + acc0.z * w4.z + acc0.w * w4.w;
        float p1 = acc1.x * w4.x + acc1.y * w4.y + acc1.z * w4.z + acc1.w * w4.w;
#pragma unroll
        for (int o = 16; o; o >>= 1) {
            p0 += __shfl_xor_sync(0xffffffffu, p0, o);
            p1 += __shfl_xor_sync(0xffffffffu, p1, o);
        }
        int w = t64 >> 5;
        if ((t64 & 31) == 0) { red[sub][w][0] = p0; red[sub][w][1] = p1; }
        __syncthreads();
        if (t64 == 0) {
            float b0 = bbp[0];
            out[node] = red[sub][0][0] + red[sub][1][0] + b0;
            out[NNODES + node] = red[sub][0][1] + red[sub][1][1] + b0;
        }
    }
}

// ---------------- launcher -------------------------------------------------
extern "C" void kernel_launch(void* const* d_in, const int* in_sizes, int n_in,
                              void* d_out, int out_size) {
    const float* x     = (const float*)d_in[0];
    const float* nodes = (const float*)d_in[1];
    const int*   ei    = (const int*)  d_in[2];
    const float* Wp    = (const float*)d_in[3];
    const float* bp    = (const float*)d_in[4];
    const float* gW    = (const float*)d_in[5];
    const float* gb    = (const float*)d_in[6];
    const float* wbp   = (const float*)d_in[7];
    const float* bbp   = (const float*)d_in[8];
    float* out = (float*)d_out;

    cudaFuncSetAttribute(mma_bf, cudaFuncAttributeMaxDynamicSharedMemorySize, MMA_SMEM);

    void *pNh, *pNl, *pXh, *pXl, *pWh, *pWl, *pCh, *pCl, *pTh, *pTl, *pAh, *pAl,
         *pHh, *pDV;
    cudaGetSymbolAddress(&pNh, g_nsum_hi); cudaGetSymbolAddress(&pNl, g_nsum_lo);
    cudaGetSymbolAddress(&pXh, g_x_hi);    cudaGetSymbolAddress(&pXl, g_x_lo);
    cudaGetSymbolAddress(&pWh, g_WpT_hi);  cudaGetSymbolAddress(&pWl, g_WpT_lo);
    cudaGetSymbolAddress(&pCh, g_CT_hi);   cudaGetSymbolAddress(&pCl, g_CT_lo);
    cudaGetSymbolAddress(&pTh, g_WT_hi);   cudaGetSymbolAddress(&pTl, g_WT_lo);
    cudaGetSymbolAddress(&pAh, g_Ahi);     cudaGetSymbolAddress(&pAl, g_Alo);
    cudaGetSymbolAddress(&pHh, g_hw_h);    cudaGetSymbolAddress(&pDV, g_dvec);

    const int MB64 = (NNODES + 63) / 64;   // 313
    const long slab = (long)NNODES * SDIM;

    // 0: nsum -> hi/lo (+ deg init)
    k_nsum<<<NSUM_BLK + (NNODES + 255) / 256, 256>>>(nodes);
    // 1: x cvt + WpT + WT + dvec
    k_prep<<<PREP_S0 + PREP_S1 + PREP_S2 + BSJ, 256>>>(x, Wp, gW, bp);
    // 2: CT = x @ Wp (mode 2)
    mma_bf<<<dim3(BSJ / 64, FDIM / 128, 1), 256, MMA_SMEM>>>(
        (__nv_bfloat16*)pXh, (__nv_bfloat16*)pXl,
        (__nv_bfloat16*)pWh, (__nv_bfloat16*)pWl,
        nullptr, (__nv_bfloat16*)pCh, (__nv_bfloat16*)pCl, nullptr,
        BSJ, FDIM, FDIM, 0, 0, 2);
    // 3: H0 = nsum @ CT^T + dvec (mode 1)  <- ncu samples launch index 3
    mma_bf<<<dim3(MB64, BSJ / 128, 1), 256, MMA_SMEM>>>(
        (__nv_bfloat16*)pNh, (__nv_bfloat16*)pNl,
        (__nv_bfloat16*)pCh, (__nv_bfloat16*)pCl,
        nullptr, (__nv_bfloat16*)pAh, (__nv_bfloat16*)pAl, (float*)pDV,
        NNODES, FDIM, 0, 0, 0, 1);

    // CSR build
    k_hist<<<(NE_ + 255) / 256, 256>>>(ei);
    k_scan<<<1, 512>>>();
    k_scatter<<<(NE_ + 255) / 256, 256>>>(ei);

    // GCN layers (final layer fuses belief projection)
    for (int l = 0; l < NLAYERS; ++l) {
        mma_bf<<<dim3(MB64, SDIM / 128, NB), 256, MMA_SMEM>>>(
            (__nv_bfloat16*)pAh, (__nv_bfloat16*)pAl,
            (__nv_bfloat16*)pTh + (long)l * SDIM * SDIM,
            (__nv_bfloat16*)pTl + (long)l * SDIM * SDIM,
            (__half*)pHh, nullptr, nullptr, nullptr,
            NNODES, SDIM, SDIM, slab, slab, 0);
        k_agg<<<NNODES / 4, 256>>>(gb + (long)l * SDIM, wbp, bbp, out,
                                   (l == NLAYERS - 1) ? 1 : 0);
    }
}

// round 14
// speedup vs baseline: 1.6768x; 1.0070x over previous
#include <cuda_runtime.h>
#include <cuda_bf16.h>
#include <cuda_fp16.h>
#include <cstdint>

#define NB       2
#define SDIM     256
#define FDIM     512
#define NNODES   20000
#define NE_      320000
#define NLAYERS  3
#define BSJ      512

// ---------------- scratch (device globals) ---------------------------------
__device__ __nv_bfloat16 g_nsum_hi[(size_t)NNODES * FDIM];
__device__ __nv_bfloat16 g_nsum_lo[(size_t)NNODES * FDIM];
__device__ __nv_bfloat16 g_x_hi  [(size_t)BSJ * FDIM];
__device__ __nv_bfloat16 g_x_lo  [(size_t)BSJ * FDIM];
__device__ __nv_bfloat16 g_WpT_hi[(size_t)FDIM * FDIM];
__device__ __nv_bfloat16 g_WpT_lo[(size_t)FDIM * FDIM];
__device__ __nv_bfloat16 g_CT_hi [(size_t)BSJ * FDIM];
__device__ __nv_bfloat16 g_CT_lo [(size_t)BSJ * FDIM];
__device__ __nv_bfloat16 g_WT_hi [(size_t)NLAYERS * SDIM * SDIM];
__device__ __nv_bfloat16 g_WT_lo [(size_t)NLAYERS * SDIM * SDIM];
__device__ __nv_bfloat16 g_Ahi   [(size_t)NB * NNODES * SDIM];
__device__ __nv_bfloat16 g_Alo   [(size_t)NB * NNODES * SDIM];
// hw fp16, batch-interleaved: [node][s/4][batch][4 halves] -> 512 halves/node
__device__ __half        g_hw    [(size_t)NNODES * NB * SDIM];
__device__ float g_dvec[BSJ];
__device__ int   g_deg [NNODES];
__device__ int   g_off [NNODES + 1];
__device__ int   g_cur [NNODES];
__device__ int   g_srcs[NE_];
__device__ float g_wnorm[NE_];
__device__ float g_dinv[NNODES];

__device__ __forceinline__ void bsplit(float v, __nv_bfloat16& h, __nv_bfloat16& l) {
    h = __float2bfloat16(v);
    l = __float2bfloat16(v - __bfloat162float(h));
}
__device__ __forceinline__ float4 h2f4u2(unsigned a, unsigned b) {
    __half2 x = *(__half2*)&a, y = *(__half2*)&b;
    float2 fx = __half22float2(x), fy = __half22float2(y);
    return make_float4(fx.x, fx.y, fy.x, fy.y);
}

// ---------------- CSR build ------------------------------------------------
__global__ void k_hist(const int* __restrict__ ei) {
    int e = blockIdx.x * blockDim.x + threadIdx.x;
    if (e < NE_) atomicAdd(&g_deg[ei[NE_ + e]], 1);
}
__global__ void k_scan() {
    __shared__ int ssum[512];
    int tid = threadIdx.x;
    const int CH = (NNODES + 511) / 512;
    int base = tid * CH;
    int s = 0;
    for (int i = 0; i < CH; ++i) {
        int idx = base + i;
        if (idx < NNODES) s += g_deg[idx] - 1;
    }
    ssum[tid] = s;
    __syncthreads();
    for (int off = 1; off < 512; off <<= 1) {
        int v = ssum[tid];
        int u = (tid >= off) ? ssum[tid - off] : 0;
        __syncthreads();
        ssum[tid] = v + u;
        __syncthreads();
    }
    int run = (tid == 0) ? 0 : ssum[tid - 1];
    for (int i = 0; i < CH; ++i) {
        int idx = base + i;
        if (idx < NNODES) {
            g_off[idx] = run;
            g_cur[idx] = run;
            g_dinv[idx] = rsqrtf((float)g_deg[idx]);
            run += g_deg[idx] - 1;
        }
    }
    if (tid == 511) g_off[NNODES] = run;
}
__global__ void k_scatter(const int* __restrict__ ei) {
    int e = blockIdx.x * blockDim.x + threadIdx.x;
    if (e < NE_) {
        int s = ei[e];
        int d = ei[NE_ + e];
        int p = atomicAdd(&g_cur[d], 1);
        g_srcs[p] = s;
        g_wnorm[p] = g_dinv[s] * g_dinv[d];
    }
}

// ---------------- nsum -> bf16 hi/lo (+ deg init in tail blocks) -----------
#define NSUM_BLK ((int)(((long)NNODES * FDIM / 4 + 255) / 256))   // 10000
__global__ void k_nsum(const float* __restrict__ nodes) {
    if (blockIdx.x >= NSUM_BLK) {
        int i = (blockIdx.x - NSUM_BLK) * 256 + threadIdx.x;
        if (i < NNODES) g_deg[i] = 1;
        return;
    }
    long i = (long)blockIdx.x * blockDim.x + threadIdx.x;
    const float4* nd = (const float4*)nodes;
    long n = i / (FDIM / 4);
    long f = i % (FDIM / 4);
    float4 a = nd[n * (2 * FDIM / 4) + f];
    float4 b = nd[n * (2 * FDIM / 4) + FDIM / 4 + f];
    float v[4] = {a.x + b.x, a.y + b.y, a.z + b.z, a.w + b.w};
    __nv_bfloat16 h[4], l[4];
#pragma unroll
    for (int q = 0; q < 4; ++q) bsplit(v[q], h[q], l[q]);
    __nv_bfloat162* ph = (__nv_bfloat162*)g_nsum_hi + i * 2;
    __nv_bfloat162* pl = (__nv_bfloat162*)g_nsum_lo + i * 2;
    ph[0] = __nv_bfloat162{h[0], h[1]}; ph[1] = __nv_bfloat162{h[2], h[3]};
    pl[0] = __nv_bfloat162{l[0], l[1]}; pl[1] = __nv_bfloat162{l[2], l[3]};
}

// ---------------- prep: x cvt, WpT, WT transposes, dvec --------------------
#define PREP_S0 1024
#define PREP_S1 1024
#define PREP_S2 768
__global__ void k_prep(const float* __restrict__ x, const float* __restrict__ Wp,
                       const float* __restrict__ gW, const float* __restrict__ bp) {
    int blk = blockIdx.x;
    if (blk < PREP_S0) {
        int idx = blk * 256 + threadIdx.x;
        bsplit(x[idx], g_x_hi[idx], g_x_lo[idx]);
    } else if (blk < PREP_S0 + PREP_S1) {
        int idx = (blk - PREP_S0) * 256 + threadIdx.x;
        int k = idx >> 9, f2 = idx & 511;
        bsplit(Wp[idx], g_WpT_hi[(long)f2 * FDIM + k], g_WpT_lo[(long)f2 * FDIM + k]);
    } else if (blk < PREP_S0 + PREP_S1 + PREP_S2) {
        int idx = (blk - PREP_S0 - PREP_S1) * 256 + threadIdx.x;
        int l = idx / (SDIM * SDIM), r2 = idx % (SDIM * SDIM);
        int i = r2 >> 8, o = r2 & 255;
        long dst = (long)l * SDIM * SDIM + (long)o * SDIM + i;
        bsplit(gW[idx], g_WT_hi[dst], g_WT_lo[dst]);
    } else {
        __shared__ float sh[256];
        int j = blk - (PREP_S0 + PREP_S1 + PREP_S2);
        float s = 0.f;
        for (int k = threadIdx.x; k < FDIM; k += 256)
            s += bp[k] * x[(long)j * FDIM + k];
        sh[threadIdx.x] = s;
        __syncthreads();
        for (int o = 128; o > 0; o >>= 1) {
            if (threadIdx.x < o) sh[threadIdx.x] += sh[threadIdx.x + o];
            __syncthreads();
        }
        if (threadIdx.x == 0) g_dvec[j] = 2.f * sh[0];
    }
}

// ---------------- bf16-split NT GEMM via mma.sync.m16n8k16 -----------------
// CTA tile 64(M) x 128(N), 8 warps (2x4), warp tile 32x32.
#define KST   32
#define RSTR  40
#define TILEA (64 * RSTR * 2)
#define TILEBB (128 * RSTR * 2)
#define STAGEB (2 * TILEA + 2 * TILEBB)
#define MMA_SMEM (2 * STAGEB)

__device__ __forceinline__ void cpa16g(void* dst, const void* src, int nbytes) {
    unsigned d = (unsigned)__cvta_generic_to_shared(dst);
    asm volatile("cp.async.cg.shared.global [%0], [%1], 16, %2;\n"
                 :: "r"(d), "l"(src), "r"(nbytes));
}
__device__ __forceinline__ void mma16(float c[4], const unsigned a[4], const unsigned b[2]) {
    asm volatile(
        "mma.sync.aligned.m16n8k16.row.col.f32.bf16.bf16.f32 "
        "{%0,%1,%2,%3}, {%4,%5,%6,%7}, {%8,%9}, {%0,%1,%2,%3};"
        : "+f"(c[0]), "+f"(c[1]), "+f"(c[2]), "+f"(c[3])
        : "r"(a[0]), "r"(a[1]), "r"(a[2]), "r"(a[3]), "r"(b[0]), "r"(b[1]));
}
__device__ __forceinline__ void store_split(__nv_bfloat16* Ohi, __nv_bfloat16* Olo,
                                            long idx, float v0, float v1) {
    __nv_bfloat16 h0, l0, h1, l1;
    bsplit(v0, h0, l0);
    bsplit(v1, h1, l1);
    *(__nv_bfloat162*)(Ohi + idx) = __nv_bfloat162{h0, h1};
    *(__nv_bfloat162*)(Olo + idx) = __nv_bfloat162{l0, l1};
}

// modes: 0 = fp16 hw store (batch-interleaved layout, batch = blockIdx.z);
//        1 = H0 (dvec add + bf16 split [b,n,s]); 2 = bf16 split row-major
__global__ __launch_bounds__(256, 3) void mma_bf(
    const __nv_bfloat16* __restrict__ Ahi, const __nv_bfloat16* __restrict__ Alo,
    const __nv_bfloat16* __restrict__ Bhi, const __nv_bfloat16* __restrict__ Blo,
    __half* __restrict__ Chh,
    __nv_bfloat16* __restrict__ Ohi, __nv_bfloat16* __restrict__ Olo,
    const float* __restrict__ dvec,
    int M, int K, int ldc, long aSlab, int mode)
{
    extern __shared__ char smem[];
    int t = threadIdx.x;
    int brow = blockIdx.x * 64, bcol = blockIdx.y * 128;
    long zA = (long)blockIdx.z * aSlab;
    int lane = t & 31, wid = t >> 5;
    int g = lane >> 2, tig = lane & 3;
    int wm = (wid & 1) * 32, wn = (wid >> 1) * 32;

    float acc[2][4][4] = {};
    int nK = K / KST;

    int arow = t >> 2, aq = (t & 3);
    int brow0 = t >> 2, bq0 = (t & 3);
    int brow1 = (t + 256) >> 2, bq1 = (t & 3);

    auto load_stage = [&](int st, int k0) {
        char* base = smem + st * STAGEB;
        {
            long ao = zA + (long)(brow + arow) * K + k0 + aq * 8;
            int av = ((brow + arow) < M) ? 16 : 0;
            unsigned off = arow * (RSTR * 2) + aq * 16;
            cpa16g(base + off, Ahi + ao, av);
            cpa16g(base + TILEA + off, Alo + ao, av);
        }
        {
            long bo = (long)(bcol + brow0) * K + k0 + bq0 * 8;
            unsigned off = brow0 * (RSTR * 2) + bq0 * 16;
            cpa16g(base + 2 * TILEA + off, Bhi + bo, 16);
            cpa16g(base + 2 * TILEA + TILEBB + off, Blo + bo, 16);
        }
        {
            long bo = (long)(bcol + brow1) * K + k0 + bq1 * 8;
            unsigned off = brow1 * (RSTR * 2) + bq1 * 16;
            cpa16g(base + 2 * TILEA + off, Bhi + bo, 16);
            cpa16g(base + 2 * TILEA + TILEBB + off, Blo + bo, 16);
        }
        asm volatile("cp.async.commit_group;\n");
    };

    load_stage(0, 0);

    for (int it = 0; it < nK; ++it) {
        asm volatile("cp.async.wait_group 0;\n");
        __syncthreads();
        if (it + 1 < nK) load_stage((it + 1) & 1, (it + 1) * KST);
        char* base = smem + (it & 1) * STAGEB;
        const __nv_bfloat16* ah_s = (const __nv_bfloat16*)(base);
        const __nv_bfloat16* al_s = (const __nv_bfloat16*)(base + TILEA);
        const __nv_bfloat16* bh_s = (const __nv_bfloat16*)(base + 2 * TILEA);
        const __nv_bfloat16* bl_s = (const __nv_bfloat16*)(base + 2 * TILEA + TILEBB);

#pragma unroll
        for (int ks = 0; ks < KST; ks += 16) {
            unsigned ah[2][4], al[2][4], bh[4][2], bl[4][2];
#pragma unroll
            for (int mi = 0; mi < 2; ++mi) {
                int m = wm + mi * 16 + g;
                ah[mi][0] = *(const unsigned*)(ah_s + m * RSTR + ks + 2 * tig);
                ah[mi][1] = *(const unsigned*)(ah_s + (m + 8) * RSTR + ks + 2 * tig);
                ah[mi][2] = *(const unsigned*)(ah_s + m * RSTR + ks + 8 + 2 * tig);
                ah[mi][3] = *(const unsigned*)(ah_s + (m + 8) * RSTR + ks + 8 + 2 * tig);
                al[mi][0] = *(const unsigned*)(al_s + m * RSTR + ks + 2 * tig);
                al[mi][1] = *(const unsigned*)(al_s + (m + 8) * RSTR + ks + 2 * tig);
                al[mi][2] = *(const unsigned*)(al_s + m * RSTR + ks + 8 + 2 * tig);
                al[mi][3] = *(const unsigned*)(al_s + (m + 8) * RSTR + ks + 8 + 2 * tig);
            }
#pragma unroll
            for (int ni = 0; ni < 4; ++ni) {
                int n = wn + ni * 8 + g;
                bh[ni][0] = *(const unsigned*)(bh_s + n * RSTR + ks + 2 * tig);
                bh[ni][1] = *(const unsigned*)(bh_s + n * RSTR + ks + 8 + 2 * tig);
                bl[ni][0] = *(const unsigned*)(bl_s + n * RSTR + ks + 2 * tig);
                bl[ni][1] = *(const unsigned*)(bl_s + n * RSTR + ks + 8 + 2 * tig);
            }
#pragma unroll
            for (int mi = 0; mi < 2; ++mi)
#pragma unroll
                for (int ni = 0; ni < 4; ++ni)
                    mma16(acc[mi][ni], ah[mi], bh[ni]);
#pragma unroll
            for (int mi = 0; mi < 2; ++mi)
#pragma unroll
                for (int ni = 0; ni < 4; ++ni)
                    mma16(acc[mi][ni], ah[mi], bl[ni]);
#pragma unroll
            for (int mi = 0; mi < 2; ++mi)
#pragma unroll
                for (int ni = 0; ni < 4; ++ni)
                    mma16(acc[mi][ni], al[mi], bh[ni]);
        }
        __syncthreads();
    }

    // epilogue
    int z = blockIdx.z;
#pragma unroll
    for (int mi = 0; mi < 2; ++mi) {
        int r0 = brow + wm + mi * 16 + g;
#pragma unroll
        for (int ni = 0; ni < 4; ++ni) {
            int c0 = bcol + wn + ni * 8 + 2 * tig;
            if (mode == 0) {
                // batch-interleaved: off = r*512 + (s>>2)*8 + z*4 + (s&3)
                if (r0 < M) {
                    long off = (long)r0 * (NB * SDIM) + (c0 >> 2) * (NB * 4) + z * 4 + (c0 & 3);
                    *(__half2*)(Chh + off) = __floats2half2_rn(acc[mi][ni][0], acc[mi][ni][1]);
                }
                if (r0 + 8 < M) {
                    long off = (long)(r0 + 8) * (NB * SDIM) + (c0 >> 2) * (NB * 4) + z * 4 + (c0 & 3);
                    *(__half2*)(Chh + off) = __floats2half2_rn(acc[mi][ni][2], acc[mi][ni][3]);
                }
            } else if (mode == 1) {
                int b = c0 >> 8, s0 = c0 & 255;
                float d0 = dvec[c0], d1 = dvec[c0 + 1];
                long baseO = (long)b * NNODES * SDIM;
                if (r0 < M)
                    store_split(Ohi, Olo, baseO + (long)r0 * SDIM + s0,
                                acc[mi][ni][0] + d0, acc[mi][ni][1] + d1);
                if (r0 + 8 < M)
                    store_split(Ohi, Olo, baseO + (long)(r0 + 8) * SDIM + s0,
                                acc[mi][ni][2] + d0, acc[mi][ni][3] + d1);
            } else {
                if (r0 < M)
                    store_split(Ohi, Olo, (long)r0 * ldc + c0,
                                acc[mi][ni][0], acc[mi][ni][1]);
                if (r0 + 8 < M)
                    store_split(Ohi, Olo, (long)(r0 + 8) * ldc + c0,
                                acc[mi][ni][2], acc[mi][ni][3]);
            }
        }
    }
}

// ---------------- CSR aggregation (interleaved fp16 gather) -----------------
__global__ __launch_bounds__(256) void k_agg(const float* __restrict__ bias,
                                             const float* __restrict__ wbp,
                                             const float* __restrict__ bbp,
                                             float* __restrict__ out, int final_) {
    __shared__ float red[4][2][2];
    int sub = threadIdx.x >> 6;
    int t64 = threadIdx.x & 63;
    int node = blockIdx.x * 4 + sub;
    float dt = g_dinv[node];
    const uint4* H = (const uint4*)g_hw;   // one uint4 = both batches' 4 halves
    long n16 = (long)node * 64 + t64;

    uint4 sv = H[n16];
    float4 s0 = h2f4u2(sv.x, sv.y);
    float4 s1 = h2f4u2(sv.z, sv.w);
    float sw = dt * dt;
    float4 acc0 = make_float4(s0.x * sw, s0.y * sw, s0.z * sw, s0.w * sw);
    float4 acc1 = make_float4(s1.x * sw, s1.y * sw, s1.z * sw, s1.w * sw);
    int e0 = g_off[node], e1 = g_off[node + 1];
#pragma unroll 4
    for (int e = e0; e < e1; ++e) {
        int src = g_srcs[e];
        float w = g_wnorm[e];
        uint4 uv = H[(long)src * 64 + t64];
        float4 u0 = h2f4u2(uv.x, uv.y);
        float4 u1 = h2f4u2(uv.z, uv.w);
        acc0.x = fmaf(u0.x, w, acc0.x); acc0.y = fmaf(u0.y, w, acc0.y);
        acc0.z = fmaf(u0.z, w, acc0.z); acc0.w = fmaf(u0.w, w, acc0.w);
        acc1.x = fmaf(u1.x, w, acc1.x); acc1.y = fmaf(u1.y, w, acc1.y);
        acc1.z = fmaf(u1.z, w, acc1.z); acc1.w = fmaf(u1.w, w, acc1.w);
    }
    float4 bb = ((const float4*)bias)[t64];
    acc0.x += bb.x; acc0.y += bb.y; acc0.z += bb.z; acc0.w += bb.w;
    acc1.x += bb.x; acc1.y += bb.y; acc1.z += bb.z; acc1.w += bb.w;
    acc0.x = acc0.x > 0.f ? acc0.x : 0.01f * acc0.x;
    acc0.y = acc0.y > 0.f ? acc0.y : 0.01f * acc0.y;
    acc0.z = acc0.z > 0.f ? acc0.z : 0.01f * acc0.z;
    acc0.w = acc0.w > 0.f ? acc0.w : 0.01f * acc0.w;
    acc1.x = acc1.x > 0.f ? acc1.x : 0.01f * acc1.x;
    acc1.y = acc1.y > 0.f ? acc1.y : 0.01f * acc1.y;
    acc1.z = acc1.z > 0.f ? acc1.z : 0.01f * acc1.z;
    acc1.w = acc1.w > 0.f ? acc1.w : 0.01f * acc1.w;

    if (!final_) {
        long bE = (long)node * SDIM + t64 * 4;
        __nv_bfloat16 h0, l0, h1, l1, h2, l2, h3, l3;
        bsplit(acc0.x, h0, l0); bsplit(acc0.y, h1, l1);
        bsplit(acc0.z, h2, l2); bsplit(acc0.w, h3, l3);
        ((__nv_bfloat162*)(g_Ahi + bE))[0] = __nv_bfloat162{h0, h1};
        ((__nv_bfloat162*)(g_Ahi + bE))[1] = __nv_bfloat162{h2, h3};
        ((__nv_bfloat162*)(g_Alo + bE))[0] = __nv_bfloat162{l0, l1};
        ((__nv_bfloat162*)(g_Alo + bE))[1] = __nv_bfloat162{l2, l3};
        long bE1 = bE + (long)NNODES * SDIM;
        bsplit(acc1.x, h0, l0); bsplit(acc1.y, h1, l1);
        bsplit(acc1.z, h2, l2); bsplit(acc1.w, h3, l3);
        ((__nv_bfloat162*)(g_Ahi + bE1))[0] = __nv_bfloat162{h0, h1};
        ((__nv_bfloat162*)(g_Ahi + bE1))[1] = __nv_bfloat162{h2, h3};
        ((__nv_bfloat162*)(g_Alo + bE1))[0] = __nv_bfloat162{l0, l1};
        ((__nv_bfloat162*)(g_Alo + bE1))[1] = __nv_bfloat162{l2, l3};
    } else {
        float4 w4 = ((const float4*)wbp)[t64];
        float p0 = acc0.x * w4.x + acc0.y * w4.y + acc0.z * w4.z + acc0.w * w4.w;
        float p1 = acc1.x * w4.x + acc1.y * w4.y + acc1.z * w4.z + acc1.w * w4.w;
#pragma unroll
        for (int o = 16; o; o >>= 1) {
            p0 += __shfl_xor_sync(0xffffffffu, p0, o);
            p1 += __shfl_xor_sync(0xffffffffu, p1, o);
        }
        int w = t64 >> 5;
        if ((t64 & 31) == 0) { red[sub][w][0] = p0; red[sub][w][1] = p1; }
        __syncthreads();
        if (t64 == 0) {
            float b0 = bbp[0];
            out[node] = red[sub][0][0] + red[sub][1][0] + b0;
            out[NNODES + node] = red[sub][0][1] + red[sub][1][1] + b0;
        }
    }
}

// ---------------- launcher -------------------------------------------------
extern "C" void kernel_launch(void* const* d_in, const int* in_sizes, int n_in,
                              void* d_out, int out_size) {
    const float* x     = (const float*)d_in[0];
    const float* nodes = (const float*)d_in[1];
    const int*   ei    = (const int*)  d_in[2];
    const float* Wp    = (const float*)d_in[3];
    const float* bp    = (const float*)d_in[4];
    const float* gW    = (const float*)d_in[5];
    const float* gb    = (const float*)d_in[6];
    const float* wbp   = (const float*)d_in[7];
    const float* bbp   = (const float*)d_in[8];
    float* out = (float*)d_out;

    cudaFuncSetAttribute(mma_bf, cudaFuncAttributeMaxDynamicSharedMemorySize, MMA_SMEM);

    void *pNh, *pNl, *pXh, *pXl, *pWh, *pWl, *pCh, *pCl, *pTh, *pTl, *pAh, *pAl,
         *pHw, *pDV;
    cudaGetSymbolAddress(&pNh, g_nsum_hi); cudaGetSymbolAddress(&pNl, g_nsum_lo);
    cudaGetSymbolAddress(&pXh, g_x_hi);    cudaGetSymbolAddress(&pXl, g_x_lo);
    cudaGetSymbolAddress(&pWh, g_WpT_hi);  cudaGetSymbolAddress(&pWl, g_WpT_lo);
    cudaGetSymbolAddress(&pCh, g_CT_hi);   cudaGetSymbolAddress(&pCl, g_CT_lo);
    cudaGetSymbolAddress(&pTh, g_WT_hi);   cudaGetSymbolAddress(&pTl, g_WT_lo);
    cudaGetSymbolAddress(&pAh, g_Ahi);     cudaGetSymbolAddress(&pAl, g_Alo);
    cudaGetSymbolAddress(&pHw, g_hw);      cudaGetSymbolAddress(&pDV, g_dvec);

    const int MB64 = (NNODES + 63) / 64;   // 313
    const long slab = (long)NNODES * SDIM;

    // 0: nsum -> hi/lo (+ deg init)
    k_nsum<<<NSUM_BLK + (NNODES + 255) / 256, 256>>>(nodes);
    // 1: x cvt + WpT + WT + dvec
    k_prep<<<PREP_S0 + PREP_S1 + PREP_S2 + BSJ, 256>>>(x, Wp, gW, bp);
    // 2: CT = x @ Wp (mode 2)
    mma_bf<<<dim3(BSJ / 64, FDIM / 128, 1), 256, MMA_SMEM>>>(
        (__nv_bfloat16*)pXh, (__nv_bfloat16*)pXl,
        (__nv_bfloat16*)pWh, (__nv_bfloat16*)pWl,
        nullptr, (__nv_bfloat16*)pCh, (__nv_bfloat16*)pCl, nullptr,
        BSJ, FDIM, FDIM, 0, 2);
    // 3: H0 = nsum @ CT^T + dvec (mode 1)  <- ncu samples launch index 3
    mma_bf<<<dim3(MB64, BSJ / 128, 1), 256, MMA_SMEM>>>(
        (__nv_bfloat16*)pNh, (__nv_bfloat16*)pNl,
        (__nv_bfloat16*)pCh, (__nv_bfloat16*)pCl,
        nullptr, (__nv_bfloat16*)pAh, (__nv_bfloat16*)pAl, (float*)pDV,
        NNODES, FDIM, 0, 0, 1);

    // CSR build
    k_hist<<<(NE_ + 255) / 256, 256>>>(ei);
    k_scan<<<1, 512>>>();
    k_scatter<<<(NE_ + 255) / 256, 256>>>(ei);

    // GCN layers (final layer fuses belief projection)
    for (int l = 0; l < NLAYERS; ++l) {
        mma_bf<<<dim3(MB64, SDIM / 128, NB), 256, MMA_SMEM>>>(
            (__nv_bfloat16*)pAh, (__nv_bfloat16*)pAl,
            (__nv_bfloat16*)pTh + (long)l * SDIM * SDIM,
            (__nv_bfloat16*)pTl + (long)l * SDIM * SDIM,
            (__half*)pHw, nullptr, nullptr, nullptr,
            NNODES, SDIM, SDIM, slab, 0);
        k_agg<<<NNODES / 4, 256>>>(gb + (long)l * SDIM, wbp, bbp, out,
                                   (l == NLAYERS - 1) ? 1 : 0);
    }
}

// round 15
// speedup vs baseline: 1.8898x; 1.1270x over previous
#include <cuda_runtime.h>
#include <cuda_bf16.h>
#include <cuda_fp16.h>
#include <cstdint>

#define NB       2
#define SDIM     256
#define FDIM     512
#define NNODES   20000
#define NE_      320000
#define NLAYERS  3
#define BSJ      512

// ---------------- scratch (device globals) ---------------------------------
__device__ __nv_bfloat16 g_nsum_hi[(size_t)NNODES * FDIM];
__device__ __nv_bfloat16 g_nsum_lo[(size_t)NNODES * FDIM];
__device__ __nv_bfloat16 g_x_hi  [(size_t)BSJ * FDIM];
__device__ __nv_bfloat16 g_x_lo  [(size_t)BSJ * FDIM];
__device__ __nv_bfloat16 g_WpT_hi[(size_t)FDIM * FDIM];
__device__ __nv_bfloat16 g_WpT_lo[(size_t)FDIM * FDIM];
__device__ __nv_bfloat16 g_CT_hi [(size_t)BSJ * FDIM];
__device__ __nv_bfloat16 g_CT_lo [(size_t)BSJ * FDIM];
__device__ __nv_bfloat16 g_WT_hi [(size_t)NLAYERS * SDIM * SDIM];
__device__ __nv_bfloat16 g_WT_lo [(size_t)NLAYERS * SDIM * SDIM];
__device__ __nv_bfloat16 g_Ahi   [(size_t)NB * NNODES * SDIM];
__device__ __nv_bfloat16 g_Alo   [(size_t)NB * NNODES * SDIM];
// hw fp16, batch-interleaved: [node][s/4][batch][4 halves]
__device__ __half        g_hw    [(size_t)NNODES * NB * SDIM];
__device__ float g_dvec[BSJ];
__device__ int   g_deg [NNODES];
__device__ int   g_off [NNODES + 1];
__device__ int   g_cur [NNODES];
__device__ int   g_srcs[NE_];
__device__ float g_wnorm[NE_];
__device__ float g_dinv[NNODES];

__device__ __forceinline__ void bsplit(float v, __nv_bfloat16& h, __nv_bfloat16& l) {
    h = __float2bfloat16(v);
    l = __float2bfloat16(v - __bfloat162float(h));
}
__device__ __forceinline__ float4 h2f4u2(unsigned a, unsigned b) {
    __half2 x = *(__half2*)&a, y = *(__half2*)&b;
    float2 fx = __half22float2(x), fy = __half22float2(y);
    return make_float4(fx.x, fx.y, fy.x, fy.y);
}

// ---------------- CSR build ------------------------------------------------
__global__ void k_hist(const int* __restrict__ ei) {
    int e = blockIdx.x * blockDim.x + threadIdx.x;
    if (e < NE_) atomicAdd(&g_deg[ei[NE_ + e]], 1);
}
__global__ void k_scan() {
    __shared__ int ssum[512];
    int tid = threadIdx.x;
    const int CH = (NNODES + 511) / 512;
    int base = tid * CH;
    int s = 0;
    for (int i = 0; i < CH; ++i) {
        int idx = base + i;
        if (idx < NNODES) s += g_deg[idx] - 1;
    }
    ssum[tid] = s;
    __syncthreads();
    for (int off = 1; off < 512; off <<= 1) {
        int v = ssum[tid];
        int u = (tid >= off) ? ssum[tid - off] : 0;
        __syncthreads();
        ssum[tid] = v + u;
        __syncthreads();
    }
    int run = (tid == 0) ? 0 : ssum[tid - 1];
    for (int i = 0; i < CH; ++i) {
        int idx = base + i;
        if (idx < NNODES) {
            g_off[idx] = run;
            g_cur[idx] = run;
            g_dinv[idx] = rsqrtf((float)g_deg[idx]);
            run += g_deg[idx] - 1;
        }
    }
    if (tid == 511) g_off[NNODES] = run;
}
__global__ void k_scatter(const int* __restrict__ ei) {
    int e = blockIdx.x * blockDim.x + threadIdx.x;
    if (e < NE_) {
        int s = ei[e];
        int d = ei[NE_ + e];
        int p = atomicAdd(&g_cur[d], 1);
        g_srcs[p] = s;
        g_wnorm[p] = g_dinv[s] * g_dinv[d];
    }
}

// ---------------- nsum -> bf16 hi/lo (+ deg init in tail blocks) -----------
#define NSUM_BLK ((int)(((long)NNODES * FDIM / 4 + 255) / 256))   // 10000
__global__ void k_nsum(const float* __restrict__ nodes) {
    if (blockIdx.x >= NSUM_BLK) {
        int i = (blockIdx.x - NSUM_BLK) * 256 + threadIdx.x;
        if (i < NNODES) g_deg[i] = 1;
        return;
    }
    long i = (long)blockIdx.x * blockDim.x + threadIdx.x;
    const float4* nd = (const float4*)nodes;
    long n = i / (FDIM / 4);
    long f = i % (FDIM / 4);
    float4 a = nd[n * (2 * FDIM / 4) + f];
    float4 b = nd[n * (2 * FDIM / 4) + FDIM / 4 + f];
    float v[4] = {a.x + b.x, a.y + b.y, a.z + b.z, a.w + b.w};
    __nv_bfloat16 h[4], l[4];
#pragma unroll
    for (int q = 0; q < 4; ++q) bsplit(v[q], h[q], l[q]);
    __nv_bfloat162* ph = (__nv_bfloat162*)g_nsum_hi + i * 2;
    __nv_bfloat162* pl = (__nv_bfloat162*)g_nsum_lo + i * 2;
    ph[0] = __nv_bfloat162{h[0], h[1]}; ph[1] = __nv_bfloat162{h[2], h[3]};
    pl[0] = __nv_bfloat162{l[0], l[1]}; pl[1] = __nv_bfloat162{l[2], l[3]};
}

// ---------------- prep: x cvt, WpT, WT transposes, dvec --------------------
#define PREP_S0 1024
#define PREP_S1 1024
#define PREP_S2 768
__global__ void k_prep(const float* __restrict__ x, const float* __restrict__ Wp,
                       const float* __restrict__ gW, const float* __restrict__ bp) {
    int blk = blockIdx.x;
    if (blk < PREP_S0) {
        int idx = blk * 256 + threadIdx.x;
        bsplit(x[idx], g_x_hi[idx], g_x_lo[idx]);
    } else if (blk < PREP_S0 + PREP_S1) {
        int idx = (blk - PREP_S0) * 256 + threadIdx.x;
        int k = idx >> 9, f2 = idx & 511;
        bsplit(Wp[idx], g_WpT_hi[(long)f2 * FDIM + k], g_WpT_lo[(long)f2 * FDIM + k]);
    } else if (blk < PREP_S0 + PREP_S1 + PREP_S2) {
        int idx = (blk - PREP_S0 - PREP_S1) * 256 + threadIdx.x;
        int l = idx / (SDIM * SDIM), r2 = idx % (SDIM * SDIM);
        int i = r2 >> 8, o = r2 & 255;
        long dst = (long)l * SDIM * SDIM + (long)o * SDIM + i;
        bsplit(gW[idx], g_WT_hi[dst], g_WT_lo[dst]);
    } else {
        __shared__ float sh[256];
        int j = blk - (PREP_S0 + PREP_S1 + PREP_S2);
        float s = 0.f;
        for (int k = threadIdx.x; k < FDIM; k += 256)
            s += bp[k] * x[(long)j * FDIM + k];
        sh[threadIdx.x] = s;
        __syncthreads();
        for (int o = 128; o > 0; o >>= 1) {
            if (threadIdx.x < o) sh[threadIdx.x] += sh[threadIdx.x + o];
            __syncthreads();
        }
        if (threadIdx.x == 0) g_dvec[j] = 2.f * sh[0];
    }
}

// ---------------- bf16-split NT GEMM via mma.sync.m16n8k16 -----------------
#define KST   32
#define RSTR  40
#define TILEA (64 * RSTR * 2)
#define TILEBB (128 * RSTR * 2)
#define STAGEB (2 * TILEA + 2 * TILEBB)
#define MMA_SMEM (2 * STAGEB)

__device__ __forceinline__ void cpa16g(void* dst, const void* src, int nbytes) {
    unsigned d = (unsigned)__cvta_generic_to_shared(dst);
    asm volatile("cp.async.cg.shared.global [%0], [%1], 16, %2;\n"
                 :: "r"(d), "l"(src), "r"(nbytes));
}
__device__ __forceinline__ void mma16(float c[4], const unsigned a[4], const unsigned b[2]) {
    asm volatile(
        "mma.sync.aligned.m16n8k16.row.col.f32.bf16.bf16.f32 "
        "{%0,%1,%2,%3}, {%4,%5,%6,%7}, {%8,%9}, {%0,%1,%2,%3};"
        : "+f"(c[0]), "+f"(c[1]), "+f"(c[2]), "+f"(c[3])
        : "r"(a[0]), "r"(a[1]), "r"(a[2]), "r"(a[3]), "r"(b[0]), "r"(b[1]));
}
__device__ __forceinline__ void store_split(__nv_bfloat16* Ohi, __nv_bfloat16* Olo,
                                            long idx, float v0, float v1) {
    __nv_bfloat16 h0, l0, h1, l1;
    bsplit(v0, h0, l0);
    bsplit(v1, h1, l1);
    *(__nv_bfloat162*)(Ohi + idx) = __nv_bfloat162{h0, h1};
    *(__nv_bfloat162*)(Olo + idx) = __nv_bfloat162{l0, l1};
}

// modes: 0 = fp16 hw store (batch-interleaved, batch = blockIdx.z);
//        1 = H0 (dvec add + bf16 split [b,n,s]); 2 = bf16 split row-major
__global__ __launch_bounds__(256, 3) void mma_bf(
    const __nv_bfloat16* __restrict__ Ahi, const __nv_bfloat16* __restrict__ Alo,
    const __nv_bfloat16* __restrict__ Bhi, const __nv_bfloat16* __restrict__ Blo,
    __half* __restrict__ Chh,
    __nv_bfloat16* __restrict__ Ohi, __nv_bfloat16* __restrict__ Olo,
    const float* __restrict__ dvec,
    int M, int K, int ldc, long aSlab, int mode)
{
    extern __shared__ char smem[];
    int t = threadIdx.x;
    int brow = blockIdx.x * 64, bcol = blockIdx.y * 128;
    long zA = (long)blockIdx.z * aSlab;
    int lane = t & 31, wid = t >> 5;
    int g = lane >> 2, tig = lane & 3;
    int wm = (wid & 1) * 32, wn = (wid >> 1) * 32;

    float acc[2][4][4] = {};
    int nK = K / KST;

    int arow = t >> 2, aq = (t & 3);
    int brow0 = t >> 2, bq0 = (t & 3);
    int brow1 = (t + 256) >> 2, bq1 = (t & 3);

    auto load_stage = [&](int st, int k0) {
        char* base = smem + st * STAGEB;
        {
            long ao = zA + (long)(brow + arow) * K + k0 + aq * 8;
            int av = ((brow + arow) < M) ? 16 : 0;
            unsigned off = arow * (RSTR * 2) + aq * 16;
            cpa16g(base + off, Ahi + ao, av);
            cpa16g(base + TILEA + off, Alo + ao, av);
        }
        {
            long bo = (long)(bcol + brow0) * K + k0 + bq0 * 8;
            unsigned off = brow0 * (RSTR * 2) + bq0 * 16;
            cpa16g(base + 2 * TILEA + off, Bhi + bo, 16);
            cpa16g(base + 2 * TILEA + TILEBB + off, Blo + bo, 16);
        }
        {
            long bo = (long)(bcol + brow1) * K + k0 + bq1 * 8;
            unsigned off = brow1 * (RSTR * 2) + bq1 * 16;
            cpa16g(base + 2 * TILEA + off, Bhi + bo, 16);
            cpa16g(base + 2 * TILEA + TILEBB + off, Blo + bo, 16);
        }
        asm volatile("cp.async.commit_group;\n");
    };

    load_stage(0, 0);

    for (int it = 0; it < nK; ++it) {
        asm volatile("cp.async.wait_group 0;\n");
        __syncthreads();
        if (it + 1 < nK) load_stage((it + 1) & 1, (it + 1) * KST);
        char* base = smem + (it & 1) * STAGEB;
        const __nv_bfloat16* ah_s = (const __nv_bfloat16*)(base);
        const __nv_bfloat16* al_s = (const __nv_bfloat16*)(base + TILEA);
        const __nv_bfloat16* bh_s = (const __nv_bfloat16*)(base + 2 * TILEA);
        const __nv_bfloat16* bl_s = (const __nv_bfloat16*)(base + 2 * TILEA + TILEBB);

#pragma unroll
        for (int ks = 0; ks < KST; ks += 16) {
            unsigned ah[2][4], al[2][4], bh[4][2], bl[4][2];
#pragma unroll
            for (int mi = 0; mi < 2; ++mi) {
                int m = wm + mi * 16 + g;
                ah[mi][0] = *(const unsigned*)(ah_s + m * RSTR + ks + 2 * tig);
                ah[mi][1] = *(const unsigned*)(ah_s + (m + 8) * RSTR + ks + 2 * tig);
                ah[mi][2] = *(const unsigned*)(ah_s + m * RSTR + ks + 8 + 2 * tig);
                ah[mi][3] = *(const unsigned*)(ah_s + (m + 8) * RSTR + ks + 8 + 2 * tig);
                al[mi][0] = *(const unsigned*)(al_s + m * RSTR + ks + 2 * tig);
                al[mi][1] = *(const unsigned*)(al_s + (m + 8) * RSTR + ks + 2 * tig);
                al[mi][2] = *(const unsigned*)(al_s + m * RSTR + ks + 8 + 2 * tig);
                al[mi][3] = *(const unsigned*)(al_s + (m + 8) * RSTR + ks + 8 + 2 * tig);
            }
#pragma unroll
            for (int ni = 0; ni < 4; ++ni) {
                int n = wn + ni * 8 + g;
                bh[ni][0] = *(const unsigned*)(bh_s + n * RSTR + ks + 2 * tig);
                bh[ni][1] = *(const unsigned*)(bh_s + n * RSTR + ks + 8 + 2 * tig);
                bl[ni][0] = *(const unsigned*)(bl_s + n * RSTR + ks + 2 * tig);
                bl[ni][1] = *(const unsigned*)(bl_s + n * RSTR + ks + 8 + 2 * tig);
            }
#pragma unroll
            for (int mi = 0; mi < 2; ++mi)
#pragma unroll
                for (int ni = 0; ni < 4; ++ni)
                    mma16(acc[mi][ni], ah[mi], bh[ni]);
#pragma unroll
            for (int mi = 0; mi < 2; ++mi)
#pragma unroll
                for (int ni = 0; ni < 4; ++ni)
                    mma16(acc[mi][ni], ah[mi], bl[ni]);
#pragma unroll
            for (int mi = 0; mi < 2; ++mi)
#pragma unroll
                for (int ni = 0; ni < 4; ++ni)
                    mma16(acc[mi][ni], al[mi], bh[ni]);
        }
        __syncthreads();
    }

    // epilogue
    int z = blockIdx.z;
#pragma unroll
    for (int mi = 0; mi < 2; ++mi) {
        int r0 = brow + wm + mi * 16 + g;
#pragma unroll
        for (int ni = 0; ni < 4; ++ni) {
            int c0 = bcol + wn + ni * 8 + 2 * tig;
            if (mode == 0) {
                if (r0 < M) {
                    long off = (long)r0 * (NB * SDIM) + (c0 >> 2) * (NB * 4) + z * 4 + (c0 & 3);
                    *(__half2*)(Chh + off) = __floats2half2_rn(acc[mi][ni][0], acc[mi][ni][1]);
                }
                if (r0 + 8 < M) {
                    long off = (long)(r0 + 8) * (NB * SDIM) + (c0 >> 2) * (NB * 4) + z * 4 + (c0 & 3);
                    *(__half2*)(Chh + off) = __floats2half2_rn(acc[mi][ni][2], acc[mi][ni][3]);
                }
            } else if (mode == 1) {
                int b = c0 >> 8, s0 = c0 & 255;
                float d0 = dvec[c0], d1 = dvec[c0 + 1];
                long baseO = (long)b * NNODES * SDIM;
                if (r0 < M)
                    store_split(Ohi, Olo, baseO + (long)r0 * SDIM + s0,
                                acc[mi][ni][0] + d0, acc[mi][ni][1] + d1);
                if (r0 + 8 < M)
                    store_split(Ohi, Olo, baseO + (long)(r0 + 8) * SDIM + s0,
                                acc[mi][ni][2] + d0, acc[mi][ni][3] + d1);
            } else {
                if (r0 < M)
                    store_split(Ohi, Olo, (long)r0 * ldc + c0,
                                acc[mi][ni][0], acc[mi][ni][1]);
                if (r0 + 8 < M)
                    store_split(Ohi, Olo, (long)(r0 + 8) * ldc + c0,
                                acc[mi][ni][2], acc[mi][ni][3]);
            }
        }
    }
}

// ---------------- CSR aggregation (interleaved fp16 gather) -----------------
__global__ __launch_bounds__(256) void k_agg(const float* __restrict__ bias,
                                             const float* __restrict__ wbp,
                                             const float* __restrict__ bbp,
                                             float* __restrict__ out, int final_) {
    __shared__ float red[4][2][2];
    int sub = threadIdx.x >> 6;
    int t64 = threadIdx.x & 63;
    int node = blockIdx.x * 4 + sub;
    float dt = g_dinv[node];
    const uint4* H = (const uint4*)g_hw;
    long n16 = (long)node * 64 + t64;

    uint4 sv = H[n16];
    float4 s0 = h2f4u2(sv.x, sv.y);
    float4 s1 = h2f4u2(sv.z, sv.w);
    float sw = dt * dt;
    float4 acc0 = make_float4(s0.x * sw, s0.y * sw, s0.z * sw, s0.w * sw);
    float4 acc1 = make_float4(s1.x * sw, s1.y * sw, s1.z * sw, s1.w * sw);
    int e0 = g_off[node], e1 = g_off[node + 1];
#pragma unroll 4
    for (int e = e0; e < e1; ++e) {
        int src = g_srcs[e];
        float w = g_wnorm[e];
        uint4 uv = H[(long)src * 64 + t64];
        float4 u0 = h2f4u2(uv.x, uv.y);
        float4 u1 = h2f4u2(uv.z, uv.w);
        acc0.x = fmaf(u0.x, w, acc0.x); acc0.y = fmaf(u0.y, w, acc0.y);
        acc0.z = fmaf(u0.z, w, acc0.z); acc0.w = fmaf(u0.w, w, acc0.w);
        acc1.x = fmaf(u1.x, w, acc1.x); acc1.y = fmaf(u1.y, w, acc1.y);
        acc1.z = fmaf(u1.z, w, acc1.z); acc1.w = fmaf(u1.w, w, acc1.w);
    }
    float4 bb = ((const float4*)bias)[t64];
    acc0.x += bb.x; acc0.y += bb.y; acc0.z += bb.z; acc0.w += bb.w;
    acc1.x += bb.x; acc1.y += bb.y; acc1.z += bb.z; acc1.w += bb.w;
    acc0.x = acc0.x > 0.f ? acc0.x : 0.01f * acc0.x;
    acc0.y = acc0.y > 0.f ? acc0.y : 0.01f * acc0.y;
    acc0.z = acc0.z > 0.f ? acc0.z : 0.01f * acc0.z;
    acc0.w = acc0.w > 0.f ? acc0.w : 0.01f * acc0.w;
    acc1.x = acc1.x > 0.f ? acc1.x : 0.01f * acc1.x;
    acc1.y = acc1.y > 0.f ? acc1.y : 0.01f * acc1.y;
    acc1.z = acc1.z > 0.f ? acc1.z : 0.01f * acc1.z;
    acc1.w = acc1.w > 0.f ? acc1.w : 0.01f * acc1.w;

    if (!final_) {
        long bE = (long)node * SDIM + t64 * 4;
        __nv_bfloat16 h0, l0, h1, l1, h2, l2, h3, l3;
        bsplit(acc0.x, h0, l0); bsplit(acc0.y, h1, l1);
        bsplit(acc0.z, h2, l2); bsplit(acc0.w, h3, l3);
        ((__nv_bfloat162*)(g_Ahi + bE))[0] = __nv_bfloat162{h0, h1};
        ((__nv_bfloat162*)(g_Ahi + bE))[1] = __nv_bfloat162{h2, h3};
        ((__nv_bfloat162*)(g_Alo + bE))[0] = __nv_bfloat162{l0, l1};
        ((__nv_bfloat162*)(g_Alo + bE))[1] = __nv_bfloat162{l2, l3};
        long bE1 = bE + (long)NNODES * SDIM;
        bsplit(acc1.x, h0, l0); bsplit(acc1.y, h1, l1);
        bsplit(acc1.z, h2, l2); bsplit(acc1.w, h3, l3);
        ((__nv_bfloat162*)(g_Ahi + bE1))[0] = __nv_bfloat162{h0, h1};
        ((__nv_bfloat162*)(g_Ahi + bE1))[1] = __nv_bfloat162{h2, h3};
        ((__nv_bfloat162*)(g_Alo + bE1))[0] = __nv_bfloat162{l0, l1};
        ((__nv_bfloat162*)(g_Alo + bE1))[1] = __nv_bfloat162{l2, l3};
    } else {
        float4 w4 = ((const float4*)wbp)[t64];
        float p0 = acc0.x * w4.x + acc0.y * w4.y + acc0.z * w4.z + acc0.w * w4.w;
        float p1 = acc1.x * w4.x + acc1.y * w4.y + acc1.z * w4.z + acc1.w * w4.w;
#pragma unroll
        for (int o = 16; o; o >>= 1) {
            p0 += __shfl_xor_sync(0xffffffffu, p0, o);
            p1 += __shfl_xor_sync(0xffffffffu, p1, o);
        }
        int w = t64 >> 5;
        if ((t64 & 31) == 0) { red[sub][w][0] = p0; red[sub][w][1] = p1; }
        __syncthreads();
        if (t64 == 0) {
            float b0 = bbp[0];
            out[node] = red[sub][0][0] + red[sub][1][0] + b0;
            out[NNODES + node] = red[sub][0][1] + red[sub][1][1] + b0;
        }
    }
}

// ---------------- launcher (dual-stream overlap) ----------------------------
extern "C" void kernel_launch(void* const* d_in, const int* in_sizes, int n_in,
                              void* d_out, int out_size) {
    const float* x     = (const float*)d_in[0];
    const float* nodes = (const float*)d_in[1];
    const int*   ei    = (const int*)  d_in[2];
    const float* Wp    = (const float*)d_in[3];
    const float* bp    = (const float*)d_in[4];
    const float* gW    = (const float*)d_in[5];
    const float* gb    = (const float*)d_in[6];
    const float* wbp   = (const float*)d_in[7];
    const float* bbp   = (const float*)d_in[8];
    float* out = (float*)d_out;

    static cudaStream_t sB = nullptr;
    static cudaEvent_t eStart = nullptr, eNsum = nullptr, eCSR = nullptr;
    if (!sB) {
        cudaStreamCreateWithFlags(&sB, cudaStreamNonBlocking);
        cudaEventCreateWithFlags(&eStart, cudaEventDisableTiming);
        cudaEventCreateWithFlags(&eNsum, cudaEventDisableTiming);
        cudaEventCreateWithFlags(&eCSR, cudaEventDisableTiming);
    }

    cudaFuncSetAttribute(mma_bf, cudaFuncAttributeMaxDynamicSharedMemorySize, MMA_SMEM);

    void *pNh, *pNl, *pXh, *pXl, *pWh, *pWl, *pCh, *pCl, *pTh, *pTl, *pAh, *pAl,
         *pHw, *pDV;
    cudaGetSymbolAddress(&pNh, g_nsum_hi); cudaGetSymbolAddress(&pNl, g_nsum_lo);
    cudaGetSymbolAddress(&pXh, g_x_hi);    cudaGetSymbolAddress(&pXl, g_x_lo);
    cudaGetSymbolAddress(&pWh, g_WpT_hi);  cudaGetSymbolAddress(&pWl, g_WpT_lo);
    cudaGetSymbolAddress(&pCh, g_CT_hi);   cudaGetSymbolAddress(&pCl, g_CT_lo);
    cudaGetSymbolAddress(&pTh, g_WT_hi);   cudaGetSymbolAddress(&pTl, g_WT_lo);
    cudaGetSymbolAddress(&pAh, g_Ahi);     cudaGetSymbolAddress(&pAl, g_Alo);
    cudaGetSymbolAddress(&pHw, g_hw);      cudaGetSymbolAddress(&pDV, g_dvec);

    const int MB64 = (NNODES + 63) / 64;   // 313
    const long slab = (long)NNODES * SDIM;

    // Fork stream B off the capture (legacy) stream.
    cudaEventRecord(eStart, 0);
    cudaStreamWaitEvent(sB, eStart, 0);

    // stream B: nsum(+deg init) -> CSR build
    k_nsum<<<NSUM_BLK + (NNODES + 255) / 256, 256, 0, sB>>>(nodes);
    cudaEventRecord(eNsum, sB);
    k_hist<<<(NE_ + 255) / 256, 256, 0, sB>>>(ei);
    k_scan<<<1, 512, 0, sB>>>();
    k_scatter<<<(NE_ + 255) / 256, 256, 0, sB>>>(ei);
    cudaEventRecord(eCSR, sB);

    // stream 0: prep -> CT -> (nsum ready) H0 -> layers
    k_prep<<<PREP_S0 + PREP_S1 + PREP_S2 + BSJ, 256>>>(x, Wp, gW, bp);
    mma_bf<<<dim3(BSJ / 64, FDIM / 128, 1), 256, MMA_SMEM>>>(
        (__nv_bfloat16*)pXh, (__nv_bfloat16*)pXl,
        (__nv_bfloat16*)pWh, (__nv_bfloat16*)pWl,
        nullptr, (__nv_bfloat16*)pCh, (__nv_bfloat16*)pCl, nullptr,
        BSJ, FDIM, FDIM, 0, 2);
    cudaStreamWaitEvent(0, eNsum, 0);
    mma_bf<<<dim3(MB64, BSJ / 128, 1), 256, MMA_SMEM>>>(
        (__nv_bfloat16*)pNh, (__nv_bfloat16*)pNl,
        (__nv_bfloat16*)pCh, (__nv_bfloat16*)pCl,
        nullptr, (__nv_bfloat16*)pAh, (__nv_bfloat16*)pAl, (float*)pDV,
        NNODES, FDIM, 0, 0, 1);

    // join CSR before first k_agg
    cudaStreamWaitEvent(0, eCSR, 0);

    for (int l = 0; l < NLAYERS; ++l) {
        mma_bf<<<dim3(MB64, SDIM / 128, NB), 256, MMA_SMEM>>>(
            (__nv_bfloat16*)pAh, (__nv_bfloat16*)pAl,
            (__nv_bfloat16*)pTh + (long)l * SDIM * SDIM,
            (__nv_bfloat16*)pTl + (long)l * SDIM * SDIM,
            (__half*)pHw, nullptr, nullptr, nullptr,
            NNODES, SDIM, SDIM, slab, 0);
        k_agg<<<NNODES / 4, 256>>>(gb + (long)l * SDIM, wbp, bbp, out,
                                   (l == NLAYERS - 1) ? 1 : 0);
    }
}

// round 16
// speedup vs baseline: 2.0701x; 1.0954x over previous
#include <cuda_runtime.h>
#include <cuda_bf16.h>
#include <cuda_fp16.h>
#include <cstdint>

#define NB       2
#define SDIM     256
#define FDIM     512
#define NNODES   20000
#define NE_      320000
#define NLAYERS  3
#define BSJ      512

// ---------------- scratch (device globals) ---------------------------------
__device__ __nv_bfloat16 g_nsum_hi[(size_t)NNODES * FDIM];
__device__ __nv_bfloat16 g_nsum_lo[(size_t)NNODES * FDIM];
__device__ __nv_bfloat16 g_x_hi  [(size_t)BSJ * FDIM];
__device__ __nv_bfloat16 g_x_lo  [(size_t)BSJ * FDIM];
__device__ __nv_bfloat16 g_WpT_hi[(size_t)FDIM * FDIM];
__device__ __nv_bfloat16 g_WpT_lo[(size_t)FDIM * FDIM];
__device__ __nv_bfloat16 g_CT_hi [(size_t)BSJ * FDIM];
__device__ __nv_bfloat16 g_CT_lo [(size_t)BSJ * FDIM];
__device__ __half        g_WT16h [(size_t)NLAYERS * SDIM * SDIM];  // layer W fp16 hi
__device__ __half        g_WT16l [(size_t)NLAYERS * SDIM * SDIM];  // layer W fp16 lo
__device__ __half        g_h16   [(size_t)NB * NNODES * SDIM];     // h fp16 single
// hw fp16, batch-interleaved: [node][s/4][batch][4 halves]
__device__ __half        g_hw    [(size_t)NNODES * NB * SDIM];
__device__ float g_dvec[BSJ];
__device__ int   g_deg [NNODES];
__device__ int   g_off [NNODES + 1];
__device__ int   g_cur [NNODES];
__device__ int   g_srcs[NE_];
__device__ float g_wnorm[NE_];
__device__ float g_dinv[NNODES];

__device__ __forceinline__ void bsplit(float v, __nv_bfloat16& h, __nv_bfloat16& l) {
    h = __float2bfloat16(v);
    l = __float2bfloat16(v - __bfloat162float(h));
}
__device__ __forceinline__ void hsplit(float v, __half& h, __half& l) {
    h = __float2half(v);
    l = __float2half(v - __half2float(h));
}
__device__ __forceinline__ float4 h2f4u2(unsigned a, unsigned b) {
    __half2 x = *(__half2*)&a, y = *(__half2*)&b;
    float2 fx = __half22float2(x), fy = __half22float2(y);
    return make_float4(fx.x, fx.y, fy.x, fy.y);
}

// ---------------- CSR build ------------------------------------------------
__global__ void k_hist(const int* __restrict__ ei) {
    int e = blockIdx.x * blockDim.x + threadIdx.x;
    if (e < NE_) atomicAdd(&g_deg[ei[NE_ + e]], 1);
}
__global__ void k_scan() {
    __shared__ int ssum[512];
    int tid = threadIdx.x;
    const int CH = (NNODES + 511) / 512;
    int base = tid * CH;
    int s = 0;
    for (int i = 0; i < CH; ++i) {
        int idx = base + i;
        if (idx < NNODES) s += g_deg[idx] - 1;
    }
    ssum[tid] = s;
    __syncthreads();
    for (int off = 1; off < 512; off <<= 1) {
        int v = ssum[tid];
        int u = (tid >= off) ? ssum[tid - off] : 0;
        __syncthreads();
        ssum[tid] = v + u;
        __syncthreads();
    }
    int run = (tid == 0) ? 0 : ssum[tid - 1];
    for (int i = 0; i < CH; ++i) {
        int idx = base + i;
        if (idx < NNODES) {
            g_off[idx] = run;
            g_cur[idx] = run;
            g_dinv[idx] = rsqrtf((float)g_deg[idx]);
            run += g_deg[idx] - 1;
        }
    }
    if (tid == 511) g_off[NNODES] = run;
}
__global__ void k_scatter(const int* __restrict__ ei) {
    int e = blockIdx.x * blockDim.x + threadIdx.x;
    if (e < NE_) {
        int s = ei[e];
        int d = ei[NE_ + e];
        int p = atomicAdd(&g_cur[d], 1);
        g_srcs[p] = s;
        g_wnorm[p] = g_dinv[s] * g_dinv[d];
    }
}

// ---------------- nsum -> bf16 hi/lo (+ deg init in tail blocks) -----------
#define NSUM_BLK ((int)(((long)NNODES * FDIM / 4 + 255) / 256))   // 10000
__global__ void k_nsum(const float* __restrict__ nodes) {
    if (blockIdx.x >= NSUM_BLK) {
        int i = (blockIdx.x - NSUM_BLK) * 256 + threadIdx.x;
        if (i < NNODES) g_deg[i] = 1;
        return;
    }
    long i = (long)blockIdx.x * blockDim.x + threadIdx.x;
    const float4* nd = (const float4*)nodes;
    long n = i / (FDIM / 4);
    long f = i % (FDIM / 4);
    float4 a = nd[n * (2 * FDIM / 4) + f];
    float4 b = nd[n * (2 * FDIM / 4) + FDIM / 4 + f];
    float v[4] = {a.x + b.x, a.y + b.y, a.z + b.z, a.w + b.w};
    __nv_bfloat16 h[4], l[4];
#pragma unroll
    for (int q = 0; q < 4; ++q) bsplit(v[q], h[q], l[q]);
    __nv_bfloat162* ph = (__nv_bfloat162*)g_nsum_hi + i * 2;
    __nv_bfloat162* pl = (__nv_bfloat162*)g_nsum_lo + i * 2;
    ph[0] = __nv_bfloat162{h[0], h[1]}; ph[1] = __nv_bfloat162{h[2], h[3]};
    pl[0] = __nv_bfloat162{l[0], l[1]}; pl[1] = __nv_bfloat162{l[2], l[3]};
}

// ---------------- prep: x cvt, WpT, WT(fp16 split), dvec -------------------
#define PREP_S0 1024
#define PREP_S1 1024
#define PREP_S2 768
__global__ void k_prep(const float* __restrict__ x, const float* __restrict__ Wp,
                       const float* __restrict__ gW, const float* __restrict__ bp) {
    int blk = blockIdx.x;
    if (blk < PREP_S0) {
        int idx = blk * 256 + threadIdx.x;
        bsplit(x[idx], g_x_hi[idx], g_x_lo[idx]);
    } else if (blk < PREP_S0 + PREP_S1) {
        int idx = (blk - PREP_S0) * 256 + threadIdx.x;
        int k = idx >> 9, f2 = idx & 511;
        bsplit(Wp[idx], g_WpT_hi[(long)f2 * FDIM + k], g_WpT_lo[(long)f2 * FDIM + k]);
    } else if (blk < PREP_S0 + PREP_S1 + PREP_S2) {
        int idx = (blk - PREP_S0 - PREP_S1) * 256 + threadIdx.x;
        int l = idx / (SDIM * SDIM), r2 = idx % (SDIM * SDIM);
        int i = r2 >> 8, o = r2 & 255;
        long dst = (long)l * SDIM * SDIM + (long)o * SDIM + i;
        hsplit(gW[idx], g_WT16h[dst], g_WT16l[dst]);
    } else {
        __shared__ float sh[256];
        int j = blk - (PREP_S0 + PREP_S1 + PREP_S2);
        float s = 0.f;
        for (int k = threadIdx.x; k < FDIM; k += 256)
            s += bp[k] * x[(long)j * FDIM + k];
        sh[threadIdx.x] = s;
        __syncthreads();
        for (int o = 128; o > 0; o >>= 1) {
            if (threadIdx.x < o) sh[threadIdx.x] += sh[threadIdx.x + o];
            __syncthreads();
        }
        if (threadIdx.x == 0) g_dvec[j] = 2.f * sh[0];
    }
}

// ---------------- common GEMM defs ------------------------------------------
#define KST   32
#define RSTR  40
#define TILEA (64 * RSTR * 2)
#define TILEBB (128 * RSTR * 2)
#define STAGEB (2 * TILEA + 2 * TILEBB)
#define MMA_SMEM (2 * STAGEB)
#define STAGE_L (TILEA + 2 * TILEBB)
#define MMA_SMEM_L (2 * STAGE_L)

__device__ __forceinline__ void cpa16g(void* dst, const void* src, int nbytes) {
    unsigned d = (unsigned)__cvta_generic_to_shared(dst);
    asm volatile("cp.async.cg.shared.global [%0], [%1], 16, %2;\n"
                 :: "r"(d), "l"(src), "r"(nbytes));
}
__device__ __forceinline__ void mma16(float c[4], const unsigned a[4], const unsigned b[2]) {
    asm volatile(
        "mma.sync.aligned.m16n8k16.row.col.f32.bf16.bf16.f32 "
        "{%0,%1,%2,%3}, {%4,%5,%6,%7}, {%8,%9}, {%0,%1,%2,%3};"
        : "+f"(c[0]), "+f"(c[1]), "+f"(c[2]), "+f"(c[3])
        : "r"(a[0]), "r"(a[1]), "r"(a[2]), "r"(a[3]), "r"(b[0]), "r"(b[1]));
}
__device__ __forceinline__ void mma16h(float c[4], const unsigned a[4], const unsigned b[2]) {
    asm volatile(
        "mma.sync.aligned.m16n8k16.row.col.f32.f16.f16.f32 "
        "{%0,%1,%2,%3}, {%4,%5,%6,%7}, {%8,%9}, {%0,%1,%2,%3};"
        : "+f"(c[0]), "+f"(c[1]), "+f"(c[2]), "+f"(c[3])
        : "r"(a[0]), "r"(a[1]), "r"(a[2]), "r"(a[3]), "r"(b[0]), "r"(b[1]));
}
__device__ __forceinline__ void store_split(__nv_bfloat16* Ohi, __nv_bfloat16* Olo,
                                            long idx, float v0, float v1) {
    __nv_bfloat16 h0, l0, h1, l1;
    bsplit(v0, h0, l0);
    bsplit(v1, h1, l1);
    *(__nv_bfloat162*)(Ohi + idx) = __nv_bfloat162{h0, h1};
    *(__nv_bfloat162*)(Olo + idx) = __nv_bfloat162{l0, l1};
}

// ---------------- head GEMM (3-term bf16): CT (mode 2) / H0 (mode 1) -------
__global__ __launch_bounds__(256, 3) void mma_bf(
    const __nv_bfloat16* __restrict__ Ahi, const __nv_bfloat16* __restrict__ Alo,
    const __nv_bfloat16* __restrict__ Bhi, const __nv_bfloat16* __restrict__ Blo,
    __half* __restrict__ H16,
    __nv_bfloat16* __restrict__ Ohi, __nv_bfloat16* __restrict__ Olo,
    const float* __restrict__ dvec,
    int M, int K, int ldc, int mode)
{
    extern __shared__ char smem[];
    int t = threadIdx.x;
    int brow = blockIdx.x * 64, bcol = blockIdx.y * 128;
    int lane = t & 31, wid = t >> 5;
    int g = lane >> 2, tig = lane & 3;
    int wm = (wid & 1) * 32, wn = (wid >> 1) * 32;

    float acc[2][4][4] = {};
    int nK = K / KST;

    int arow = t >> 2, aq = (t & 3);
    int brow1 = (t + 256) >> 2;

    auto load_stage = [&](int st, int k0) {
        char* base = smem + st * STAGEB;
        {
            long ao = (long)(brow + arow) * K + k0 + aq * 8;
            int av = ((brow + arow) < M) ? 16 : 0;
            unsigned off = arow * (RSTR * 2) + aq * 16;
            cpa16g(base + off, Ahi + ao, av);
            cpa16g(base + TILEA + off, Alo + ao, av);
        }
        {
            long bo = (long)(bcol + arow) * K + k0 + aq * 8;
            unsigned off = arow * (RSTR * 2) + aq * 16;
            cpa16g(base + 2 * TILEA + off, Bhi + bo, 16);
            cpa16g(base + 2 * TILEA + TILEBB + off, Blo + bo, 16);
        }
        {
            long bo = (long)(bcol + brow1) * K + k0 + aq * 8;
            unsigned off = brow1 * (RSTR * 2) + aq * 16;
            cpa16g(base + 2 * TILEA + off, Bhi + bo, 16);
            cpa16g(base + 2 * TILEA + TILEBB + off, Blo + bo, 16);
        }
        asm volatile("cp.async.commit_group;\n");
    };

    load_stage(0, 0);

    for (int it = 0; it < nK; ++it) {
        asm volatile("cp.async.wait_group 0;\n");
        __syncthreads();
        if (it + 1 < nK) load_stage((it + 1) & 1, (it + 1) * KST);
        char* base = smem + (it & 1) * STAGEB;
        const __nv_bfloat16* ah_s = (const __nv_bfloat16*)(base);
        const __nv_bfloat16* al_s = (const __nv_bfloat16*)(base + TILEA);
        const __nv_bfloat16* bh_s = (const __nv_bfloat16*)(base + 2 * TILEA);
        const __nv_bfloat16* bl_s = (const __nv_bfloat16*)(base + 2 * TILEA + TILEBB);

#pragma unroll
        for (int ks = 0; ks < KST; ks += 16) {
            unsigned ah[2][4], al[2][4], bh[4][2], bl[4][2];
#pragma unroll
            for (int mi = 0; mi < 2; ++mi) {
                int m = wm + mi * 16 + g;
                ah[mi][0] = *(const unsigned*)(ah_s + m * RSTR + ks + 2 * tig);
                ah[mi][1] = *(const unsigned*)(ah_s + (m + 8) * RSTR + ks + 2 * tig);
                ah[mi][2] = *(const unsigned*)(ah_s + m * RSTR + ks + 8 + 2 * tig);
                ah[mi][3] = *(const unsigned*)(ah_s + (m + 8) * RSTR + ks + 8 + 2 * tig);
                al[mi][0] = *(const unsigned*)(al_s + m * RSTR + ks + 2 * tig);
                al[mi][1] = *(const unsigned*)(al_s + (m + 8) * RSTR + ks + 2 * tig);
                al[mi][2] = *(const unsigned*)(al_s + m * RSTR + ks + 8 + 2 * tig);
                al[mi][3] = *(const unsigned*)(al_s + (m + 8) * RSTR + ks + 8 + 2 * tig);
            }
#pragma unroll
            for (int ni = 0; ni < 4; ++ni) {
                int n = wn + ni * 8 + g;
                bh[ni][0] = *(const unsigned*)(bh_s + n * RSTR + ks + 2 * tig);
                bh[ni][1] = *(const unsigned*)(bh_s + n * RSTR + ks + 8 + 2 * tig);
                bl[ni][0] = *(const unsigned*)(bl_s + n * RSTR + ks + 2 * tig);
                bl[ni][1] = *(const unsigned*)(bl_s + n * RSTR + ks + 8 + 2 * tig);
            }
#pragma unroll
            for (int mi = 0; mi < 2; ++mi)
#pragma unroll
                for (int ni = 0; ni < 4; ++ni)
                    mma16(acc[mi][ni], ah[mi], bh[ni]);
#pragma unroll
            for (int mi = 0; mi < 2; ++mi)
#pragma unroll
                for (int ni = 0; ni < 4; ++ni)
                    mma16(acc[mi][ni], ah[mi], bl[ni]);
#pragma unroll
            for (int mi = 0; mi < 2; ++mi)
#pragma unroll
                for (int ni = 0; ni < 4; ++ni)
                    mma16(acc[mi][ni], al[mi], bh[ni]);
        }
        __syncthreads();
    }

#pragma unroll
    for (int mi = 0; mi < 2; ++mi) {
        int r0 = brow + wm + mi * 16 + g;
#pragma unroll
        for (int ni = 0; ni < 4; ++ni) {
            int c0 = bcol + wn + ni * 8 + 2 * tig;
            if (mode == 1) {
                int b = c0 >> 8, s0 = c0 & 255;
                float d0 = dvec[c0], d1 = dvec[c0 + 1];
                long baseO = (long)b * NNODES * SDIM;
                if (r0 < M)
                    *(__half2*)(H16 + baseO + (long)r0 * SDIM + s0) =
                        __floats2half2_rn(acc[mi][ni][0] + d0, acc[mi][ni][1] + d1);
                if (r0 + 8 < M)
                    *(__half2*)(H16 + baseO + (long)(r0 + 8) * SDIM + s0) =
                        __floats2half2_rn(acc[mi][ni][2] + d0, acc[mi][ni][3] + d1);
            } else {
                if (r0 < M)
                    store_split(Ohi, Olo, (long)r0 * ldc + c0,
                                acc[mi][ni][0], acc[mi][ni][1]);
                if (r0 + 8 < M)
                    store_split(Ohi, Olo, (long)(r0 + 8) * ldc + c0,
                                acc[mi][ni][2], acc[mi][ni][3]);
            }
        }
    }
}

// ---------------- layer GEMM (2-term fp16): hw = h @ W^T --------------------
// A fp16 single [z][M][K]; B fp16 hi/lo [N][K]; out batch-interleaved fp16.
__global__ __launch_bounds__(256, 3) void mma_l(
    const __half* __restrict__ A,
    const __half* __restrict__ Bh, const __half* __restrict__ Bl,
    __half* __restrict__ C, int M, int K)
{
    extern __shared__ char smem[];
    int t = threadIdx.x;
    int brow = blockIdx.x * 64, bcol = blockIdx.y * 128;
    long zA = (long)blockIdx.z * ((long)NNODES * SDIM);
    int lane = t & 31, wid = t >> 5;
    int g = lane >> 2, tig = lane & 3;
    int wm = (wid & 1) * 32, wn = (wid >> 1) * 32;

    float acc[2][4][4] = {};
    int nK = K / KST;

    int arow = t >> 2, aq = (t & 3);
    int brow1 = (t + 256) >> 2;

    auto load_stage = [&](int st, int k0) {
        char* base = smem + st * STAGE_L;
        {
            long ao = zA + (long)(brow + arow) * K + k0 + aq * 8;
            int av = ((brow + arow) < M) ? 16 : 0;
            unsigned off = arow * (RSTR * 2) + aq * 16;
            cpa16g(base + off, A + ao, av);
        }
        {
            long bo = (long)(bcol + arow) * K + k0 + aq * 8;
            unsigned off = arow * (RSTR * 2) + aq * 16;
            cpa16g(base + TILEA + off, Bh + bo, 16);
            cpa16g(base + TILEA + TILEBB + off, Bl + bo, 16);
        }
        {
            long bo = (long)(bcol + brow1) * K + k0 + aq * 8;
            unsigned off = brow1 * (RSTR * 2) + aq * 16;
            cpa16g(base + TILEA + off, Bh + bo, 16);
            cpa16g(base + TILEA + TILEBB + off, Bl + bo, 16);
        }
        asm volatile("cp.async.commit_group;\n");
    };

    load_stage(0, 0);

    for (int it = 0; it < nK; ++it) {
        asm volatile("cp.async.wait_group 0;\n");
        __syncthreads();
        if (it + 1 < nK) load_stage((it + 1) & 1, (it + 1) * KST);
        char* base = smem + (it & 1) * STAGE_L;
        const __half* a_s  = (const __half*)(base);
        const __half* bh_s = (const __half*)(base + TILEA);
        const __half* bl_s = (const __half*)(base + TILEA + TILEBB);

#pragma unroll
        for (int ks = 0; ks < KST; ks += 16) {
            unsigned ah[2][4], bh[4][2], bl[4][2];
#pragma unroll
            for (int mi = 0; mi < 2; ++mi) {
                int m = wm + mi * 16 + g;
                ah[mi][0] = *(const unsigned*)(a_s + m * RSTR + ks + 2 * tig);
                ah[mi][1] = *(const unsigned*)(a_s + (m + 8) * RSTR + ks + 2 * tig);
                ah[mi][2] = *(const unsigned*)(a_s + m * RSTR + ks + 8 + 2 * tig);
                ah[mi][3] = *(const unsigned*)(a_s + (m + 8) * RSTR + ks + 8 + 2 * tig);
            }
#pragma unroll
            for (int ni = 0; ni < 4; ++ni) {
                int n = wn + ni * 8 + g;
                bh[ni][0] = *(const unsigned*)(bh_s + n * RSTR + ks + 2 * tig);
                bh[ni][1] = *(const unsigned*)(bh_s + n * RSTR + ks + 8 + 2 * tig);
                bl[ni][0] = *(const unsigned*)(bl_s + n * RSTR + ks + 2 * tig);
                bl[ni][1] = *(const unsigned*)(bl_s + n * RSTR + ks + 8 + 2 * tig);
            }
#pragma unroll
            for (int mi = 0; mi < 2; ++mi)
#pragma unroll
                for (int ni = 0; ni < 4; ++ni)
                    mma16h(acc[mi][ni], ah[mi], bh[ni]);
#pragma unroll
            for (int mi = 0; mi < 2; ++mi)
#pragma unroll
                for (int ni = 0; ni < 4; ++ni)
                    mma16h(acc[mi][ni], ah[mi], bl[ni]);
        }
        __syncthreads();
    }

    int z = blockIdx.z;
#pragma unroll
    for (int mi = 0; mi < 2; ++mi) {
        int r0 = brow + wm + mi * 16 + g;
#pragma unroll
        for (int ni = 0; ni < 4; ++ni) {
            int c0 = bcol + wn + ni * 8 + 2 * tig;
            if (r0 < M) {
                long off = (long)r0 * (NB * SDIM) + (c0 >> 2) * (NB * 4) + z * 4 + (c0 & 3);
                *(__half2*)(C + off) = __floats2half2_rn(acc[mi][ni][0], acc[mi][ni][1]);
            }
            if (r0 + 8 < M) {
                long off = (long)(r0 + 8) * (NB * SDIM) + (c0 >> 2) * (NB * 4) + z * 4 + (c0 & 3);
                *(__half2*)(C + off) = __floats2half2_rn(acc[mi][ni][2], acc[mi][ni][3]);
            }
        }
    }
}

// ---------------- CSR aggregation (interleaved fp16 gather) -----------------
__global__ __launch_bounds__(256) void k_agg(const float* __restrict__ bias,
                                             const float* __restrict__ wbp,
                                             const float* __restrict__ bbp,
                                             float* __restrict__ out, int final_) {
    __shared__ float red[4][2][2];
    int sub = threadIdx.x >> 6;
    int t64 = threadIdx.x & 63;
    int node = blockIdx.x * 4 + sub;
    float dt = g_dinv[node];
    const uint4* H = (const uint4*)g_hw;
    long n16 = (long)node * 64 + t64;

    uint4 sv = H[n16];
    float4 s0 = h2f4u2(sv.x, sv.y);
    float4 s1 = h2f4u2(sv.z, sv.w);
    float sw = dt * dt;
    float4 acc0 = make_float4(s0.x * sw, s0.y * sw, s0.z * sw, s0.w * sw);
    float4 acc1 = make_float4(s1.x * sw, s1.y * sw, s1.z * sw, s1.w * sw);
    int e0 = g_off[node], e1 = g_off[node + 1];
#pragma unroll 4
    for (int e = e0; e < e1; ++e) {
        int src = g_srcs[e];
        float w = g_wnorm[e];
        uint4 uv = H[(long)src * 64 + t64];
        float4 u0 = h2f4u2(uv.x, uv.y);
        float4 u1 = h2f4u2(uv.z, uv.w);
        acc0.x = fmaf(u0.x, w, acc0.x); acc0.y = fmaf(u0.y, w, acc0.y);
        acc0.z = fmaf(u0.z, w, acc0.z); acc0.w = fmaf(u0.w, w, acc0.w);
        acc1.x = fmaf(u1.x, w, acc1.x); acc1.y = fmaf(u1.y, w, acc1.y);
        acc1.z = fmaf(u1.z, w, acc1.z); acc1.w = fmaf(u1.w, w, acc1.w);
    }
    float4 bb = ((const float4*)bias)[t64];
    acc0.x += bb.x; acc0.y += bb.y; acc0.z += bb.z; acc0.w += bb.w;
    acc1.x += bb.x; acc1.y += bb.y; acc1.z += bb.z; acc1.w += bb.w;
    acc0.x = acc0.x > 0.f ? acc0.x : 0.01f * acc0.x;
    acc0.y = acc0.y > 0.f ? acc0.y : 0.01f * acc0.y;
    acc0.z = acc0.z > 0.f ? acc0.z : 0.01f * acc0.z;
    acc0.w = acc0.w > 0.f ? acc0.w : 0.01f * acc0.w;
    acc1.x = acc1.x > 0.f ? acc1.x : 0.01f * acc1.x;
    acc1.y = acc1.y > 0.f ? acc1.y : 0.01f * acc1.y;
    acc1.z = acc1.z > 0.f ? acc1.z : 0.01f * acc1.z;
    acc1.w = acc1.w > 0.f ? acc1.w : 0.01f * acc1.w;

    if (!final_) {
        long bE = (long)node * SDIM + t64 * 4;
        __half2* p0 = (__half2*)(g_h16 + bE);
        p0[0] = __floats2half2_rn(acc0.x, acc0.y);
        p0[1] = __floats2half2_rn(acc0.z, acc0.w);
        __half2* p1 = (__half2*)(g_h16 + bE + (long)NNODES * SDIM);
        p1[0] = __floats2half2_rn(acc1.x, acc1.y);
        p1[1] = __floats2half2_rn(acc1.z, acc1.w);
    } else {
        float4 w4 = ((const float4*)wbp)[t64];
        float p0 = acc0.x * w4.x + acc0.y * w4.y + acc0.z * w4.z + acc0.w * w4.w;
        float p1 = acc1.x * w4.x + acc1.y * w4.y + acc1.z * w4.z + acc1.w * w4.w;
#pragma unroll
        for (int o = 16; o; o >>= 1) {
            p0 += __shfl_xor_sync(0xffffffffu, p0, o);
            p1 += __shfl_xor_sync(0xffffffffu, p1, o);
        }
        int w = t64 >> 5;
        if ((t64 & 31) == 0) { red[sub][w][0] = p0; red[sub][w][1] = p1; }
        __syncthreads();
        if (t64 == 0) {
            float b0 = bbp[0];
            out[node] = red[sub][0][0] + red[sub][1][0] + b0;
            out[NNODES + node] = red[sub][0][1] + red[sub][1][1] + b0;
        }
    }
}

// ---------------- launcher (dual-stream overlap) ----------------------------
extern "C" void kernel_launch(void* const* d_in, const int* in_sizes, int n_in,
                              void* d_out, int out_size) {
    const float* x     = (const float*)d_in[0];
    const float* nodes = (const float*)d_in[1];
    const int*   ei    = (const int*)  d_in[2];
    const float* Wp    = (const float*)d_in[3];
    const float* bp    = (const float*)d_in[4];
    const float* gW    = (const float*)d_in[5];
    const float* gb    = (const float*)d_in[6];
    const float* wbp   = (const float*)d_in[7];
    const float* bbp   = (const float*)d_in[8];
    float* out = (float*)d_out;

    static cudaStream_t sB = nullptr;
    static cudaEvent_t eStart = nullptr, eNsum = nullptr, eCSR = nullptr;
    if (!sB) {
        cudaStreamCreateWithFlags(&sB, cudaStreamNonBlocking);
        cudaEventCreateWithFlags(&eStart, cudaEventDisableTiming);
        cudaEventCreateWithFlags(&eNsum, cudaEventDisableTiming);
        cudaEventCreateWithFlags(&eCSR, cudaEventDisableTiming);
    }

    cudaFuncSetAttribute(mma_bf, cudaFuncAttributeMaxDynamicSharedMemorySize, MMA_SMEM);
    cudaFuncSetAttribute(mma_l, cudaFuncAttributeMaxDynamicSharedMemorySize, MMA_SMEM_L);

    void *pNh, *pNl, *pXh, *pXl, *pWh, *pWl, *pCh, *pCl, *pTh, *pTl, *pH16, *pHw, *pDV;
    cudaGetSymbolAddress(&pNh, g_nsum_hi); cudaGetSymbolAddress(&pNl, g_nsum_lo);
    cudaGetSymbolAddress(&pXh, g_x_hi);    cudaGetSymbolAddress(&pXl, g_x_lo);
    cudaGetSymbolAddress(&pWh, g_WpT_hi);  cudaGetSymbolAddress(&pWl, g_WpT_lo);
    cudaGetSymbolAddress(&pCh, g_CT_hi);   cudaGetSymbolAddress(&pCl, g_CT_lo);
    cudaGetSymbolAddress(&pTh, g_WT16h);   cudaGetSymbolAddress(&pTl, g_WT16l);
    cudaGetSymbolAddress(&pH16, g_h16);    cudaGetSymbolAddress(&pHw, g_hw);
    cudaGetSymbolAddress(&pDV, g_dvec);

    const int MB64 = (NNODES + 63) / 64;   // 313

    // Fork stream B off the capture (legacy) stream.
    cudaEventRecord(eStart, 0);
    cudaStreamWaitEvent(sB, eStart, 0);

    // stream B: nsum(+deg init) -> CSR build
    k_nsum<<<NSUM_BLK + (NNODES + 255) / 256, 256, 0, sB>>>(nodes);
    cudaEventRecord(eNsum, sB);
    k_hist<<<(NE_ + 255) / 256, 256, 0, sB>>>(ei);
    k_scan<<<1, 512, 0, sB>>>();
    k_scatter<<<(NE_ + 255) / 256, 256, 0, sB>>>(ei);
    cudaEventRecord(eCSR, sB);

    // stream 0: prep -> CT -> (nsum ready) H0 -> layers
    k_prep<<<PREP_S0 + PREP_S1 + PREP_S2 + BSJ, 256>>>(x, Wp, gW, bp);
    mma_bf<<<dim3(BSJ / 64, FDIM / 128, 1), 256, MMA_SMEM>>>(
        (__nv_bfloat16*)pXh, (__nv_bfloat16*)pXl,
        (__nv_bfloat16*)pWh, (__nv_bfloat16*)pWl,
        nullptr, (__nv_bfloat16*)pCh, (__nv_bfloat16*)pCl, nullptr,
        BSJ, FDIM, FDIM, 2);
    cudaStreamWaitEvent(0, eNsum, 0);
    mma_bf<<<dim3(MB64, BSJ / 128, 1), 256, MMA_SMEM>>>(
        (__nv_bfloat16*)pNh, (__nv_bfloat16*)pNl,
        (__nv_bfloat16*)pCh, (__nv_bfloat16*)pCl,
        (__half*)pH16, nullptr, nullptr, (float*)pDV,
        NNODES, FDIM, 0, 1);

    // join CSR before first k_agg
    cudaStreamWaitEvent(0, eCSR, 0);

    for (int l = 0; l < NLAYERS; ++l) {
        mma_l<<<dim3(MB64, SDIM / 128, NB), 256, MMA_SMEM_L>>>(
            (__half*)pH16,
            (__half*)pTh + (long)l * SDIM * SDIM,
            (__half*)pTl + (long)l * SDIM * SDIM,
            (__half*)pHw, NNODES, SDIM);
        k_agg<<<NNODES / 4, 256>>>(gb + (long)l * SDIM, wbp, bbp, out,
                                   (l == NLAYERS - 1) ? 1 : 0);
    }
}

// round 17
// speedup vs baseline: 2.5753x; 1.2441x over previous
#include <cuda_runtime.h>
#include <cuda_bf16.h>
#include <cuda_fp16.h>
#include <cstdint>

#define NB       2
#define SDIM     256
#define FDIM     512
#define NNODES   20000
#define NE_      320000
#define NLAYERS  3
#define BSJ      512

// ---------------- scratch (device globals) ---------------------------------
__device__ __half        g_nsum16[(size_t)NNODES * FDIM];          // nsum fp16
__device__ __nv_bfloat16 g_x_hi  [(size_t)BSJ * FDIM];
__device__ __nv_bfloat16 g_x_lo  [(size_t)BSJ * FDIM];
__device__ __nv_bfloat16 g_WpT_hi[(size_t)FDIM * FDIM];
__device__ __nv_bfloat16 g_WpT_lo[(size_t)FDIM * FDIM];
__device__ __half        g_CT16h [(size_t)BSJ * FDIM];             // CT fp16 hi
__device__ __half        g_CT16l [(size_t)BSJ * FDIM];             // CT fp16 lo
__device__ __half        g_WT16  [(size_t)NLAYERS * SDIM * SDIM];  // layer W fp16
__device__ __half        g_h16   [(size_t)NB * NNODES * SDIM];     // h fp16
// hw fp16, batch-interleaved: [node][s/4][batch][4 halves]
__device__ __half        g_hw    [(size_t)NNODES * NB * SDIM];
__device__ float g_dvec[BSJ];
__device__ int   g_deg [NNODES];
__device__ int   g_off [NNODES + 1];
__device__ int   g_cur [NNODES];
__device__ int   g_srcs[NE_];
__device__ float g_wnorm[NE_];
__device__ float g_dinv[NNODES];

__device__ __forceinline__ void bsplit(float v, __nv_bfloat16& h, __nv_bfloat16& l) {
    h = __float2bfloat16(v);
    l = __float2bfloat16(v - __bfloat162float(h));
}
__device__ __forceinline__ void hsplit(float v, __half& h, __half& l) {
    h = __float2half(v);
    l = __float2half(v - __half2float(h));
}
__device__ __forceinline__ float4 h2f4u2(unsigned a, unsigned b) {
    __half2 x = *(__half2*)&a, y = *(__half2*)&b;
    float2 fx = __half22float2(x), fy = __half22float2(y);
    return make_float4(fx.x, fx.y, fy.x, fy.y);
}

// ---------------- CSR build ------------------------------------------------
__global__ void k_hist(const int* __restrict__ ei) {
    int e = blockIdx.x * blockDim.x + threadIdx.x;
    if (e < NE_) atomicAdd(&g_deg[ei[NE_ + e]], 1);
}
__global__ void k_scan() {
    __shared__ int ssum[512];
    int tid = threadIdx.x;
    const int CH = (NNODES + 511) / 512;
    int base = tid * CH;
    int s = 0;
    for (int i = 0; i < CH; ++i) {
        int idx = base + i;
        if (idx < NNODES) s += g_deg[idx] - 1;
    }
    ssum[tid] = s;
    __syncthreads();
    for (int off = 1; off < 512; off <<= 1) {
        int v = ssum[tid];
        int u = (tid >= off) ? ssum[tid - off] : 0;
        __syncthreads();
        ssum[tid] = v + u;
        __syncthreads();
    }
    int run = (tid == 0) ? 0 : ssum[tid - 1];
    for (int i = 0; i < CH; ++i) {
        int idx = base + i;
        if (idx < NNODES) {
            g_off[idx] = run;
            g_cur[idx] = run;
            g_dinv[idx] = rsqrtf((float)g_deg[idx]);
            run += g_deg[idx] - 1;
        }
    }
    if (tid == 511) g_off[NNODES] = run;
}
__global__ void k_scatter(const int* __restrict__ ei) {
    int e = blockIdx.x * blockDim.x + threadIdx.x;
    if (e < NE_) {
        int s = ei[e];
        int d = ei[NE_ + e];
        int p = atomicAdd(&g_cur[d], 1);
        g_srcs[p] = s;
        g_wnorm[p] = g_dinv[s] * g_dinv[d];
    }
}

// ---------------- nsum -> fp16 (+ deg init in tail blocks) ------------------
#define NSUM_BLK ((int)(((long)NNODES * FDIM / 4 + 255) / 256))   // 10000
__global__ void k_nsum(const float* __restrict__ nodes) {
    if (blockIdx.x >= NSUM_BLK) {
        int i = (blockIdx.x - NSUM_BLK) * 256 + threadIdx.x;
        if (i < NNODES) g_deg[i] = 1;
        return;
    }
    long i = (long)blockIdx.x * blockDim.x + threadIdx.x;
    const float4* nd = (const float4*)nodes;
    long n = i / (FDIM / 4);
    long f = i % (FDIM / 4);
    float4 a = nd[n * (2 * FDIM / 4) + f];
    float4 b = nd[n * (2 * FDIM / 4) + FDIM / 4 + f];
    __half2* p = (__half2*)g_nsum16 + i * 2;
    p[0] = __floats2half2_rn(a.x + b.x, a.y + b.y);
    p[1] = __floats2half2_rn(a.z + b.z, a.w + b.w);
}

// ---------------- prep: x cvt, WpT, WT fp16, dvec ---------------------------
#define PREP_S0 1024
#define PREP_S1 1024
#define PREP_S2 768
__global__ void k_prep(const float* __restrict__ x, const float* __restrict__ Wp,
                       const float* __restrict__ gW, const float* __restrict__ bp) {
    int blk = blockIdx.x;
    if (blk < PREP_S0) {
        int idx = blk * 256 + threadIdx.x;
        bsplit(x[idx], g_x_hi[idx], g_x_lo[idx]);
    } else if (blk < PREP_S0 + PREP_S1) {
        int idx = (blk - PREP_S0) * 256 + threadIdx.x;
        int k = idx >> 9, f2 = idx & 511;
        bsplit(Wp[idx], g_WpT_hi[(long)f2 * FDIM + k], g_WpT_lo[(long)f2 * FDIM + k]);
    } else if (blk < PREP_S0 + PREP_S1 + PREP_S2) {
        int idx = (blk - PREP_S0 - PREP_S1) * 256 + threadIdx.x;
        int l = idx / (SDIM * SDIM), r2 = idx % (SDIM * SDIM);
        int i = r2 >> 8, o = r2 & 255;
        long dst = (long)l * SDIM * SDIM + (long)o * SDIM + i;
        g_WT16[dst] = __float2half(gW[idx]);
    } else {
        __shared__ float sh[256];
        int j = blk - (PREP_S0 + PREP_S1 + PREP_S2);
        float s = 0.f;
        for (int k = threadIdx.x; k < FDIM; k += 256)
            s += bp[k] * x[(long)j * FDIM + k];
        sh[threadIdx.x] = s;
        __syncthreads();
        for (int o = 128; o > 0; o >>= 1) {
            if (threadIdx.x < o) sh[threadIdx.x] += sh[threadIdx.x + o];
            __syncthreads();
        }
        if (threadIdx.x == 0) g_dvec[j] = 2.f * sh[0];
    }
}

// ---------------- common GEMM defs ------------------------------------------
#define KST   32
#define RSTR  40
#define TILEA (64 * RSTR * 2)
#define TILEBB (128 * RSTR * 2)
#define STAGEB (2 * TILEA + 2 * TILEBB)
#define MMA_SMEM (2 * STAGEB)
#define STAGE_H (TILEA + 2 * TILEBB)
#define MMA_SMEM_H (2 * STAGE_H)

__device__ __forceinline__ void cpa16g(void* dst, const void* src, int nbytes) {
    unsigned d = (unsigned)__cvta_generic_to_shared(dst);
    asm volatile("cp.async.cg.shared.global [%0], [%1], 16, %2;\n"
                 :: "r"(d), "l"(src), "r"(nbytes));
}
__device__ __forceinline__ void mma16(float c[4], const unsigned a[4], const unsigned b[2]) {
    asm volatile(
        "mma.sync.aligned.m16n8k16.row.col.f32.bf16.bf16.f32 "
        "{%0,%1,%2,%3}, {%4,%5,%6,%7}, {%8,%9}, {%0,%1,%2,%3};"
        : "+f"(c[0]), "+f"(c[1]), "+f"(c[2]), "+f"(c[3])
        : "r"(a[0]), "r"(a[1]), "r"(a[2]), "r"(a[3]), "r"(b[0]), "r"(b[1]));
}
__device__ __forceinline__ void mma16h(float c[4], const unsigned a[4], const unsigned b[2]) {
    asm volatile(
        "mma.sync.aligned.m16n8k16.row.col.f32.f16.f16.f32 "
        "{%0,%1,%2,%3}, {%4,%5,%6,%7}, {%8,%9}, {%0,%1,%2,%3};"
        : "+f"(c[0]), "+f"(c[1]), "+f"(c[2]), "+f"(c[3])
        : "r"(a[0]), "r"(a[1]), "r"(a[2]), "r"(a[3]), "r"(b[0]), "r"(b[1]));
}

// ---------------- CT GEMM (3-term bf16, fp16-split output) ------------------
__global__ __launch_bounds__(256, 3) void mma_bf(
    const __nv_bfloat16* __restrict__ Ahi, const __nv_bfloat16* __restrict__ Alo,
    const __nv_bfloat16* __restrict__ Bhi, const __nv_bfloat16* __restrict__ Blo,
    __half* __restrict__ Ohi, __half* __restrict__ Olo,
    int M, int K, int ldc)
{
    extern __shared__ char smem[];
    int t = threadIdx.x;
    int brow = blockIdx.x * 64, bcol = blockIdx.y * 128;
    int lane = t & 31, wid = t >> 5;
    int g = lane >> 2, tig = lane & 3;
    int wm = (wid & 1) * 32, wn = (wid >> 1) * 32;

    float acc[2][4][4] = {};
    int nK = K / KST;

    int arow = t >> 2, aq = (t & 3);
    int brow1 = (t + 256) >> 2;

    auto load_stage = [&](int st, int k0) {
        char* base = smem + st * STAGEB;
        {
            long ao = (long)(brow + arow) * K + k0 + aq * 8;
            int av = ((brow + arow) < M) ? 16 : 0;
            unsigned off = arow * (RSTR * 2) + aq * 16;
            cpa16g(base + off, Ahi + ao, av);
            cpa16g(base + TILEA + off, Alo + ao, av);
        }
        {
            long bo = (long)(bcol + arow) * K + k0 + aq * 8;
            unsigned off = arow * (RSTR * 2) + aq * 16;
            cpa16g(base + 2 * TILEA + off, Bhi + bo, 16);
            cpa16g(base + 2 * TILEA + TILEBB + off, Blo + bo, 16);
        }
        {
            long bo = (long)(bcol + brow1) * K + k0 + aq * 8;
            unsigned off = brow1 * (RSTR * 2) + aq * 16;
            cpa16g(base + 2 * TILEA + off, Bhi + bo, 16);
            cpa16g(base + 2 * TILEA + TILEBB + off, Blo + bo, 16);
        }
        asm volatile("cp.async.commit_group;\n");
    };

    load_stage(0, 0);

    for (int it = 0; it < nK; ++it) {
        asm volatile("cp.async.wait_group 0;\n");
        __syncthreads();
        if (it + 1 < nK) load_stage((it + 1) & 1, (it + 1) * KST);
        char* base = smem + (it & 1) * STAGEB;
        const __nv_bfloat16* ah_s = (const __nv_bfloat16*)(base);
        const __nv_bfloat16* al_s = (const __nv_bfloat16*)(base + TILEA);
        const __nv_bfloat16* bh_s = (const __nv_bfloat16*)(base + 2 * TILEA);
        const __nv_bfloat16* bl_s = (const __nv_bfloat16*)(base + 2 * TILEA + TILEBB);

#pragma unroll
        for (int ks = 0; ks < KST; ks += 16) {
            unsigned ah[2][4], al[2][4], bh[4][2], bl[4][2];
#pragma unroll
            for (int mi = 0; mi < 2; ++mi) {
                int m = wm + mi * 16 + g;
                ah[mi][0] = *(const unsigned*)(ah_s + m * RSTR + ks + 2 * tig);
                ah[mi][1] = *(const unsigned*)(ah_s + (m + 8) * RSTR + ks + 2 * tig);
                ah[mi][2] = *(const unsigned*)(ah_s + m * RSTR + ks + 8 + 2 * tig);
                ah[mi][3] = *(const unsigned*)(ah_s + (m + 8) * RSTR + ks + 8 + 2 * tig);
                al[mi][0] = *(const unsigned*)(al_s + m * RSTR + ks + 2 * tig);
                al[mi][1] = *(const unsigned*)(al_s + (m + 8) * RSTR + ks + 2 * tig);
                al[mi][2] = *(const unsigned*)(al_s + m * RSTR + ks + 8 + 2 * tig);
                al[mi][3] = *(const unsigned*)(al_s + (m + 8) * RSTR + ks + 8 + 2 * tig);
            }
#pragma unroll
            for (int ni = 0; ni < 4; ++ni) {
                int n = wn + ni * 8 + g;
                bh[ni][0] = *(const unsigned*)(bh_s + n * RSTR + ks + 2 * tig);
                bh[ni][1] = *(const unsigned*)(bh_s + n * RSTR + ks + 8 + 2 * tig);
                bl[ni][0] = *(const unsigned*)(bl_s + n * RSTR + ks + 2 * tig);
                bl[ni][1] = *(const unsigned*)(bl_s + n * RSTR + ks + 8 + 2 * tig);
            }
#pragma unroll
            for (int mi = 0; mi < 2; ++mi)
#pragma unroll
                for (int ni = 0; ni < 4; ++ni)
                    mma16(acc[mi][ni], ah[mi], bh[ni]);
#pragma unroll
            for (int mi = 0; mi < 2; ++mi)
#pragma unroll
                for (int ni = 0; ni < 4; ++ni)
                    mma16(acc[mi][ni], ah[mi], bl[ni]);
#pragma unroll
            for (int mi = 0; mi < 2; ++mi)
#pragma unroll
                for (int ni = 0; ni < 4; ++ni)
                    mma16(acc[mi][ni], al[mi], bh[ni]);
        }
        __syncthreads();
    }

#pragma unroll
    for (int mi = 0; mi < 2; ++mi) {
        int r0 = brow + wm + mi * 16 + g;
#pragma unroll
        for (int ni = 0; ni < 4; ++ni) {
            int c0 = bcol + wn + ni * 8 + 2 * tig;
#pragma unroll
            for (int rr = 0; rr < 2; ++rr) {
                int r = r0 + rr * 8;
                if (r < M) {
                    __half h0, l0, h1, l1;
                    hsplit(acc[mi][ni][rr * 2 + 0], h0, l0);
                    hsplit(acc[mi][ni][rr * 2 + 1], h1, l1);
                    *(__half2*)(Ohi + (long)r * ldc + c0) = __half2{h0, h1};
                    *(__half2*)(Olo + (long)r * ldc + c0) = __half2{l0, l1};
                }
            }
        }
    }
}

// ---------------- fp16 GEMM: H0 (two=1, mode=1) / layers (two=0, mode=0) ----
__global__ __launch_bounds__(256, 3) void mma_h(
    const __half* __restrict__ A,
    const __half* __restrict__ Bh, const __half* __restrict__ Bl,
    __half* __restrict__ C, const float* __restrict__ dvec,
    int M, int K, long aSlab, int two, int mode)
{
    extern __shared__ char smem[];
    int t = threadIdx.x;
    int brow = blockIdx.x * 64, bcol = blockIdx.y * 128;
    long zA = (long)blockIdx.z * aSlab;
    int lane = t & 31, wid = t >> 5;
    int g = lane >> 2, tig = lane & 3;
    int wm = (wid & 1) * 32, wn = (wid >> 1) * 32;

    float acc[2][4][4] = {};
    int nK = K / KST;

    int arow = t >> 2, aq = (t & 3);
    int brow1 = (t + 256) >> 2;

    auto load_stage = [&](int st, int k0) {
        char* base = smem + st * STAGE_H;
        {
            long ao = zA + (long)(brow + arow) * K + k0 + aq * 8;
            int av = ((brow + arow) < M) ? 16 : 0;
            unsigned off = arow * (RSTR * 2) + aq * 16;
            cpa16g(base + off, A + ao, av);
        }
        {
            long bo = (long)(bcol + arow) * K + k0 + aq * 8;
            unsigned off = arow * (RSTR * 2) + aq * 16;
            cpa16g(base + TILEA + off, Bh + bo, 16);
            if (two) cpa16g(base + TILEA + TILEBB + off, Bl + bo, 16);
        }
        {
            long bo = (long)(bcol + brow1) * K + k0 + aq * 8;
            unsigned off = brow1 * (RSTR * 2) + aq * 16;
            cpa16g(base + TILEA + off, Bh + bo, 16);
            if (two) cpa16g(base + TILEA + TILEBB + off, Bl + bo, 16);
        }
        asm volatile("cp.async.commit_group;\n");
    };

    load_stage(0, 0);

    for (int it = 0; it < nK; ++it) {
        asm volatile("cp.async.wait_group 0;\n");
        __syncthreads();
        if (it + 1 < nK) load_stage((it + 1) & 1, (it + 1) * KST);
        char* base = smem + (it & 1) * STAGE_H;
        const __half* a_s  = (const __half*)(base);
        const __half* bh_s = (const __half*)(base + TILEA);
        const __half* bl_s = (const __half*)(base + TILEA + TILEBB);

#pragma unroll
        for (int ks = 0; ks < KST; ks += 16) {
            unsigned ah[2][4], bh[4][2], bl[4][2];
#pragma unroll
            for (int mi = 0; mi < 2; ++mi) {
                int m = wm + mi * 16 + g;
                ah[mi][0] = *(const unsigned*)(a_s + m * RSTR + ks + 2 * tig);
                ah[mi][1] = *(const unsigned*)(a_s + (m + 8) * RSTR + ks + 2 * tig);
                ah[mi][2] = *(const unsigned*)(a_s + m * RSTR + ks + 8 + 2 * tig);
                ah[mi][3] = *(const unsigned*)(a_s + (m + 8) * RSTR + ks + 8 + 2 * tig);
            }
#pragma unroll
            for (int ni = 0; ni < 4; ++ni) {
                int n = wn + ni * 8 + g;
                bh[ni][0] = *(const unsigned*)(bh_s + n * RSTR + ks + 2 * tig);
                bh[ni][1] = *(const unsigned*)(bh_s + n * RSTR + ks + 8 + 2 * tig);
                if (two) {
                    bl[ni][0] = *(const unsigned*)(bl_s + n * RSTR + ks + 2 * tig);
                    bl[ni][1] = *(const unsigned*)(bl_s + n * RSTR + ks + 8 + 2 * tig);
                }
            }
#pragma unroll
            for (int mi = 0; mi < 2; ++mi)
#pragma unroll
                for (int ni = 0; ni < 4; ++ni)
                    mma16h(acc[mi][ni], ah[mi], bh[ni]);
            if (two) {
#pragma unroll
                for (int mi = 0; mi < 2; ++mi)
#pragma unroll
                    for (int ni = 0; ni < 4; ++ni)
                        mma16h(acc[mi][ni], ah[mi], bl[ni]);
            }
        }
        __syncthreads();
    }

    int z = blockIdx.z;
#pragma unroll
    for (int mi = 0; mi < 2; ++mi) {
        int r0 = brow + wm + mi * 16 + g;
#pragma unroll
        for (int ni = 0; ni < 4; ++ni) {
            int c0 = bcol + wn + ni * 8 + 2 * tig;
            if (mode == 0) {
#pragma unroll
                for (int rr = 0; rr < 2; ++rr) {
                    int r = r0 + rr * 8;
                    if (r < M) {
                        long off = (long)r * (NB * SDIM) + (c0 >> 2) * (NB * 4) + z * 4 + (c0 & 3);
                        *(__half2*)(C + off) =
                            __floats2half2_rn(acc[mi][ni][rr * 2], acc[mi][ni][rr * 2 + 1]);
                    }
                }
            } else {
                int b = c0 >> 8, s0 = c0 & 255;
                float d0 = dvec[c0], d1 = dvec[c0 + 1];
                long baseO = (long)b * NNODES * SDIM;
#pragma unroll
                for (int rr = 0; rr < 2; ++rr) {
                    int r = r0 + rr * 8;
                    if (r < M)
                        *(__half2*)(C + baseO + (long)r * SDIM + s0) =
                            __floats2half2_rn(acc[mi][ni][rr * 2] + d0,
                                              acc[mi][ni][rr * 2 + 1] + d1);
                }
            }
        }
    }
}

// ---------------- CSR aggregation (interleaved fp16 gather) -----------------
__global__ __launch_bounds__(256) void k_agg(const float* __restrict__ bias,
                                             const float* __restrict__ wbp,
                                             const float* __restrict__ bbp,
                                             float* __restrict__ out, int final_) {
    __shared__ float red[4][2][2];
    int sub = threadIdx.x >> 6;
    int t64 = threadIdx.x & 63;
    int node = blockIdx.x * 4 + sub;
    float dt = g_dinv[node];
    const uint4* H = (const uint4*)g_hw;
    long n16 = (long)node * 64 + t64;

    uint4 sv = H[n16];
    float4 s0 = h2f4u2(sv.x, sv.y);
    float4 s1 = h2f4u2(sv.z, sv.w);
    float sw = dt * dt;
    float4 acc0 = make_float4(s0.x * sw, s0.y * sw, s0.z * sw, s0.w * sw);
    float4 acc1 = make_float4(s1.x * sw, s1.y * sw, s1.z * sw, s1.w * sw);
    int e0 = g_off[node], e1 = g_off[node + 1];
#pragma unroll 4
    for (int e = e0; e < e1; ++e) {
        int src = g_srcs[e];
        float w = g_wnorm[e];
        uint4 uv = H[(long)src * 64 + t64];
        float4 u0 = h2f4u2(uv.x, uv.y);
        float4 u1 = h2f4u2(uv.z, uv.w);
        acc0.x = fmaf(u0.x, w, acc0.x); acc0.y = fmaf(u0.y, w, acc0.y);
        acc0.z = fmaf(u0.z, w, acc0.z); acc0.w = fmaf(u0.w, w, acc0.w);
        acc1.x = fmaf(u1.x, w, acc1.x); acc1.y = fmaf(u1.y, w, acc1.y);
        acc1.z = fmaf(u1.z, w, acc1.z); acc1.w = fmaf(u1.w, w, acc1.w);
    }
    float4 bb = ((const float4*)bias)[t64];
    acc0.x += bb.x; acc0.y += bb.y; acc0.z += bb.z; acc0.w += bb.w;
    acc1.x += bb.x; acc1.y += bb.y; acc1.z += bb.z; acc1.w += bb.w;
    acc0.x = acc0.x > 0.f ? acc0.x : 0.01f * acc0.x;
    acc0.y = acc0.y > 0.f ? acc0.y : 0.01f * acc0.y;
    acc0.z = acc0.z > 0.f ? acc0.z : 0.01f * acc0.z;
    acc0.w = acc0.w > 0.f ? acc0.w : 0.01f * acc0.w;
    acc1.x = acc1.x > 0.f ? acc1.x : 0.01f * acc1.x;
    acc1.y = acc1.y > 0.f ? acc1.y : 0.01f * acc1.y;
    acc1.z = acc1.z > 0.f ? acc1.z : 0.01f * acc1.z;
    acc1.w = acc1.w > 0.f ? acc1.w : 0.01f * acc1.w;

    if (!final_) {
        long bE = (long)node * SDIM + t64 * 4;
        __half2* p0 = (__half2*)(g_h16 + bE);
        p0[0] = __floats2half2_rn(acc0.x, acc0.y);
        p0[1] = __floats2half2_rn(acc0.z, acc0.w);
        __half2* p1 = (__half2*)(g_h16 + bE + (long)NNODES * SDIM);
        p1[0] = __floats2half2_rn(acc1.x, acc1.y);
        p1[1] = __floats2half2_rn(acc1.z, acc1.w);
    } else {
        float4 w4 = ((const float4*)wbp)[t64];
        float p0 = acc0.x * w4.x + acc0.y * w4.y + acc0.z * w4.z + acc0.w * w4.w;
        float p1 = acc1.x * w4.x + acc1.y * w4.y + acc1.z * w4.z + acc1.w * w4.w;
#pragma unroll
        for (int o = 16; o; o >>= 1) {
            p0 += __shfl_xor_sync(0xffffffffu, p0, o);
            p1 += __shfl_xor_sync(0xffffffffu, p1, o);
        }
        int w = t64 >> 5;
        if ((t64 & 31) == 0) { red[sub][w][0] = p0; red[sub][w][1] = p1; }
        __syncthreads();
        if (t64 == 0) {
            float b0 = bbp[0];
            out[node] = red[sub][0][0] + red[sub][1][0] + b0;
            out[NNODES + node] = red[sub][0][1] + red[sub][1][1] + b0;
        }
    }
}

// ---------------- launcher (dual-stream overlap) ----------------------------
extern "C" void kernel_launch(void* const* d_in, const int* in_sizes, int n_in,
                              void* d_out, int out_size) {
    const float* x     = (const float*)d_in[0];
    const float* nodes = (const float*)d_in[1];
    const int*   ei    = (const int*)  d_in[2];
    const float* Wp    = (const float*)d_in[3];
    const float* bp    = (const float*)d_in[4];
    const float* gW    = (const float*)d_in[5];
    const float* gb    = (const float*)d_in[6];
    const float* wbp   = (const float*)d_in[7];
    const float* bbp   = (const float*)d_in[8];
    float* out = (float*)d_out;

    static cudaStream_t sB = nullptr;
    static cudaEvent_t eStart = nullptr, eNsum = nullptr, eCSR = nullptr;
    if (!sB) {
        cudaStreamCreateWithFlags(&sB, cudaStreamNonBlocking);
        cudaEventCreateWithFlags(&eStart, cudaEventDisableTiming);
        cudaEventCreateWithFlags(&eNsum, cudaEventDisableTiming);
        cudaEventCreateWithFlags(&eCSR, cudaEventDisableTiming);
    }

    cudaFuncSetAttribute(mma_bf, cudaFuncAttributeMaxDynamicSharedMemorySize, MMA_SMEM);
    cudaFuncSetAttribute(mma_h, cudaFuncAttributeMaxDynamicSharedMemorySize, MMA_SMEM_H);

    void *pNs, *pXh, *pXl, *pWh, *pWl, *pCh, *pCl, *pWT, *pH16, *pHw, *pDV;
    cudaGetSymbolAddress(&pNs, g_nsum16);
    cudaGetSymbolAddress(&pXh, g_x_hi);    cudaGetSymbolAddress(&pXl, g_x_lo);
    cudaGetSymbolAddress(&pWh, g_WpT_hi);  cudaGetSymbolAddress(&pWl, g_WpT_lo);
    cudaGetSymbolAddress(&pCh, g_CT16h);   cudaGetSymbolAddress(&pCl, g_CT16l);
    cudaGetSymbolAddress(&pWT, g_WT16);
    cudaGetSymbolAddress(&pH16, g_h16);    cudaGetSymbolAddress(&pHw, g_hw);
    cudaGetSymbolAddress(&pDV, g_dvec);

    const int MB64 = (NNODES + 63) / 64;   // 313

    // Fork stream B off the capture (legacy) stream.
    cudaEventRecord(eStart, 0);
    cudaStreamWaitEvent(sB, eStart, 0);

    // stream B: nsum(+deg init) -> CSR build
    k_nsum<<<NSUM_BLK + (NNODES + 255) / 256, 256, 0, sB>>>(nodes);
    cudaEventRecord(eNsum, sB);
    k_hist<<<(NE_ + 255) / 256, 256, 0, sB>>>(ei);
    k_scan<<<1, 512, 0, sB>>>();
    k_scatter<<<(NE_ + 255) / 256, 256, 0, sB>>>(ei);
    cudaEventRecord(eCSR, sB);

    // stream 0: prep -> CT -> (nsum ready) H0 -> layers
    k_prep<<<PREP_S0 + PREP_S1 + PREP_S2 + BSJ, 256>>>(x, Wp, gW, bp);
    mma_bf<<<dim3(BSJ / 64, FDIM / 128, 1), 256, MMA_SMEM>>>(
        (__nv_bfloat16*)pXh, (__nv_bfloat16*)pXl,
        (__nv_bfloat16*)pWh, (__nv_bfloat16*)pWl,
        (__half*)pCh, (__half*)pCl, BSJ, FDIM, FDIM);
    cudaStreamWaitEvent(0, eNsum, 0);
    // H0: A = nsum16, B = CT16 hi/lo (2-term), out h16 [b][n][s] + dvec
    mma_h<<<dim3(MB64, BSJ / 128, 1), 256, MMA_SMEM_H>>>(
        (__half*)pNs, (__half*)pCh, (__half*)pCl,
        (__half*)pH16, (float*)pDV, NNODES, FDIM, 0, 1, 1);

    // join CSR before first k_agg
    cudaStreamWaitEvent(0, eCSR, 0);

    for (int l = 0; l < NLAYERS; ++l) {
        // layer: A = h16 (z slab), B = WT16 single (1-term), out hw interleaved
        mma_h<<<dim3(MB64, SDIM / 128, NB), 256, MMA_SMEM_H>>>(
            (__half*)pH16,
            (__half*)pWT + (long)l * SDIM * SDIM, nullptr,
            (__half*)pHw, nullptr, NNODES, SDIM,
            (long)NNODES * SDIM, 0, 0);
        k_agg<<<NNODES / 4, 256>>>(gb + (long)l * SDIM, wbp, bbp, out,
                                   (l == NLAYERS - 1) ? 1 : 0);
    }
}